// round 12
// baseline (speedup 1.0000x reference)
#include <cuda_runtime.h>
#include <math.h>
#include <stdint.h>

#define EPSBN 1e-5f

__device__ float g_buf128[33554432];
__device__ float g_b64a[8388608];
__device__ float g_b64b[8388608];
__device__ float g_b64c[8388608];
__device__ float g_mean[256];
__device__ float g_istd[256];
__device__ float g_cnorm[512];
__device__ float g_fnorm[32768];
__device__ float g_cbT[131072];
__device__ float g_wp[12288];
__device__ int   g_idx[32768];

// ---------------- tf32 helpers (decoder tolerance path only) ----------------
__device__ __forceinline__ uint32_t f2tf32(float x) {
    uint32_t r;
    asm("cvt.rna.tf32.f32 %0, %1;" : "=r"(r) : "f"(x));
    return r;
}
__device__ __forceinline__ void split_tf32(float x, uint32_t& h, uint32_t& l) {
    h = f2tf32(x);
    l = f2tf32(x - __uint_as_float(h));
}
__device__ __forceinline__ void mma_tf32(float* c, const uint32_t* a, uint32_t b0, uint32_t b1) {
    asm volatile(
        "mma.sync.aligned.m16n8k8.row.col.f32.tf32.tf32.f32 "
        "{%0,%1,%2,%3}, {%4,%5,%6,%7}, {%8,%9}, {%0,%1,%2,%3};\n"
        : "+f"(c[0]), "+f"(c[1]), "+f"(c[2]), "+f"(c[3])
        : "r"(a[0]), "r"(a[1]), "r"(a[2]), "r"(a[3]), "r"(b0), "r"(b1));
}

// ---------------- cp.async helpers ----------------
__device__ __forceinline__ void cp_async4(uint32_t dst, const float* src, int szbytes) {
    asm volatile("cp.async.ca.shared.global [%0], [%1], 4, %2;"
                 :: "r"(dst), "l"(src), "r"(szbytes));
}
__device__ __forceinline__ void cp_commit() { asm volatile("cp.async.commit_group;"); }
__device__ __forceinline__ void cp_wait0()  { asm volatile("cp.async.wait_group 0;"); }

// ---------------- ENCODER conv: 128x128x8 fp32 SIMT + cp.async db ------------
// NUMERICS FROZEN: smem contents are pure copies of the same values (OOB ->
// src-size 0 zfill == 0.0f), FMA block and fold-every-64k identical to rounds
// 4-11. z_e bits feed the frozen VQ argmin. Only the copy schedule changed.
template<int KHW, int KW, int STRIDE, int PAD>
__global__ void __launch_bounds__(256, 2) conv_gemm_ca(
    const float* __restrict__ W, const float* __restrict__ X, float* __restrict__ Y,
    int CO, int CI, int IH, int IW, int OH, int OW)
{
    const int Ktot = CI * KHW;
    const int NT = Ktot >> 3;
    __shared__ __align__(16) float As[2][8][128];
    __shared__ __align__(16) float Bs[2][8][128];
    const int t = threadIdx.x;
    const int pix0 = blockIdx.x * 128, co0 = blockIdx.y * 128;
    const int ohw = OH * OW;

    const int acol = t >> 1;
    const int akq  = (t & 1) << 2;
    const float* Wrow = W + (size_t)(co0 + acol) * Ktot + akq;

    const int bpv = t & 127;
    const int bkq = (t >> 7) << 2;
    const int pixb = pix0 + bpv;
    const int nb = pixb / ohw, remb = pixb - nb * ohw;
    const int oyb = remb / OW, oxb = remb - oyb * OW;
    const int iy0 = oyb * STRIDE - PAD, ix0 = oxb * STRIDE - PAD;
    const float* Xn = X + (size_t)nb * CI * IH * IW;

    const int tx = t & 15, ty = t >> 4;

    const uint32_t sA = (uint32_t)__cvta_generic_to_shared(&As[0][0][0]);
    const uint32_t sB = (uint32_t)__cvta_generic_to_shared(&Bs[0][0][0]);

    #define CA_ISSUE(k0v, bufv)                                                  \
        {   _Pragma("unroll")                                                    \
            for (int i = 0; i < 4; i++)                                          \
                cp_async4(sA + ((((bufv) << 10) + ((akq + i) << 7) + acol) << 2),\
                          Wrow + (k0v) + i, 4);                                  \
            _Pragma("unroll")                                                    \
            for (int i = 0; i < 4; i++) {                                        \
                int k = (k0v) + bkq + i;                                         \
                int ci = k / KHW;                                                \
                int kr = k - ci * KHW;                                           \
                int ky = kr / KW;                                                \
                int kx = kr - ky * KW;                                           \
                int iy = iy0 + ky, ix = ix0 + kx;                                \
                bool ok = ((unsigned)iy < (unsigned)IH) &&                       \
                          ((unsigned)ix < (unsigned)IW);                         \
                const float* src = ok ? (Xn + (ci * IH + iy) * IW + ix) : Xn;    \
                cp_async4(sB + ((((bufv) << 10) + ((bkq + i) << 7) + bpv) << 2), \
                          src, ok ? 4 : 0);                                      \
            }                                                                    \
            cp_commit();                                                         \
        }

    CA_ISSUE(0, 0)

    float acc[8][8] = {};
    float tot[8][8] = {};
    int nch = 0;

    for (int tile = 0; tile < NT; tile++) {
        const int cur = tile & 1;
        cp_wait0();
        __syncthreads();
        if (tile + 1 < NT) CA_ISSUE((tile + 1) << 3, cur ^ 1)

        #pragma unroll
        for (int kk = 0; kk < 8; kk++) {
            float4 a0 = *(const float4*)&As[cur][kk][ty << 2];
            float4 a1 = *(const float4*)&As[cur][kk][64 + (ty << 2)];
            float4 b0 = *(const float4*)&Bs[cur][kk][tx << 2];
            float4 b1 = *(const float4*)&Bs[cur][kk][64 + (tx << 2)];
            float av[8] = {a0.x, a0.y, a0.z, a0.w, a1.x, a1.y, a1.z, a1.w};
            float bv[8] = {b0.x, b0.y, b0.z, b0.w, b1.x, b1.y, b1.z, b1.w};
            #pragma unroll
            for (int i = 0; i < 8; i++)
                #pragma unroll
                for (int j = 0; j < 8; j++)
                    acc[i][j] = fmaf(av[i], bv[j], acc[i][j]);
        }
        if (++nch == 8) {
            nch = 0;
            #pragma unroll
            for (int i = 0; i < 8; i++)
                #pragma unroll
                for (int j = 0; j < 8; j++) {
                    tot[i][j] = __fadd_rn(tot[i][j], acc[i][j]);
                    acc[i][j] = 0.f;
                }
        }
    }
    #pragma unroll
    for (int i = 0; i < 8; i++)
        #pragma unroll
        for (int j = 0; j < 8; j++) tot[i][j] = __fadd_rn(tot[i][j], acc[i][j]);

    #pragma unroll
    for (int j = 0; j < 8; j++) {
        int pj = (j < 4) ? (tx << 2) + j : 64 + (tx << 2) + (j - 4);
        int p = pix0 + pj;
        int n2 = p / ohw, r2 = p - n2 * ohw;
        int oy2 = r2 / OW, ox2 = r2 - oy2 * OW;
        size_t base = (size_t)n2 * CO * ohw + (size_t)oy2 * OW + ox2;
        #pragma unroll
        for (int i = 0; i < 8; i++) {
            int co = co0 + ((i < 4) ? (ty << 2) + i : 64 + (ty << 2) + (i - 4));
            Y[base + (size_t)co * ohw] = tot[i][j];
        }
    }
    #undef CA_ISSUE
}

// ---------------- DECODER conv: 128x128x8 3xTF32 MMA, db + uint2-paired smem --
template<int KHW, int KW, int PAD>
__global__ void __launch_bounds__(256, 2) conv_mma_t(
    const float* __restrict__ W, const float* __restrict__ X, float* __restrict__ Y,
    int CO, int CI, int IH, int IW, int OH, int OW)
{
    const int Ktot = CI * KHW;
    const int NT = Ktot >> 3;
    __shared__ uint2 Aph[2][4][140], Apl[2][4][140], Bph[2][4][140], Bpl[2][4][140];
    const int t = threadIdx.x;
    const int pix0 = blockIdx.x * 128, co0 = blockIdx.y * 128;
    const int ohw = OH * OW;

    const int acol = t >> 1, ahh = t & 1;
    const float* Wrow = W + (size_t)(co0 + acol) * Ktot;

    const int bpv = t & 127, bhh = t >> 7;
    const int pixb = pix0 + bpv;
    const int nb = pixb / ohw, remb = pixb - nb * ohw;
    const int oyb = remb / OW, oxb = remb - oyb * OW;
    const int iy0 = oyb - PAD, ix0 = oxb - PAD;
    const float* Xn = X + (size_t)nb * CI * IH * IW;

    const int warp = t >> 5, lane = t & 31;
    const int wm = warp >> 1, wn = warp & 1;
    const int kq = lane & 3, lr = lane >> 2;

    float acc[2][8][4];
    #pragma unroll
    for (int a = 0; a < 2; a++)
        #pragma unroll
        for (int b = 0; b < 8; b++)
            #pragma unroll
            for (int c = 0; c < 4; c++) acc[a][b][c] = 0.f;

    float wA[4], vB[4];

    #define GATHER_CONV(k0v)                                                     \
        {   float2 w01 = *(const float2*)(Wrow + (k0v) + 2 * ahh);               \
            float2 w45 = *(const float2*)(Wrow + (k0v) + 2 * ahh + 4);           \
            wA[0] = w01.x; wA[1] = w01.y; wA[2] = w45.x; wA[3] = w45.y;          \
            _Pragma("unroll")                                                    \
            for (int i = 0; i < 4; i++) {                                        \
                int klocal = 2 * bhh + (i & 1) + ((i >> 1) << 2);                \
                int k = (k0v) + klocal;                                          \
                int ci = k / KHW;                                                \
                int kr = k - ci * KHW;                                           \
                int ky = kr / KW;                                                \
                int kx = kr - ky * KW;                                           \
                int iy = iy0 + ky, ix = ix0 + kx;                                \
                float v = 0.f;                                                   \
                if ((unsigned)iy < (unsigned)IH && (unsigned)ix < (unsigned)IW)  \
                    v = Xn[(ci * IH + iy) * IW + ix];                            \
                vB[i] = v;                                                       \
            }                                                                    \
        }

    #define STASH(bufv)                                                          \
        {   uint32_t h0,l0,h1,l1,h2,l2,h3,l3;                                    \
            split_tf32(wA[0],h0,l0); split_tf32(wA[1],h1,l1);                    \
            split_tf32(wA[2],h2,l2); split_tf32(wA[3],h3,l3);                    \
            Aph[bufv][2*ahh+0][acol] = make_uint2(h0, h2);                       \
            Aph[bufv][2*ahh+1][acol] = make_uint2(h1, h3);                       \
            Apl[bufv][2*ahh+0][acol] = make_uint2(l0, l2);                       \
            Apl[bufv][2*ahh+1][acol] = make_uint2(l1, l3);                       \
            split_tf32(vB[0],h0,l0); split_tf32(vB[1],h1,l1);                    \
            split_tf32(vB[2],h2,l2); split_tf32(vB[3],h3,l3);                    \
            Bph[bufv][2*bhh+0][bpv] = make_uint2(h0, h2);                        \
            Bph[bufv][2*bhh+1][bpv] = make_uint2(h1, h3);                        \
            Bpl[bufv][2*bhh+0][bpv] = make_uint2(l0, l2);                        \
            Bpl[bufv][2*bhh+1][bpv] = make_uint2(l1, l3);                        \
        }

    GATHER_CONV(0)
    STASH(0)
    __syncthreads();

    for (int tile = 0; tile < NT; tile++) {
        const int cur = tile & 1;
        const bool more = (tile + 1 < NT);
        if (more) GATHER_CONV((tile + 1) << 3)

        uint32_t ah[2][4], al[2][4];
        #pragma unroll
        for (int mt = 0; mt < 2; mt++) {
            int ca = wm * 32 + mt * 16 + lr;
            uint2 u0 = Aph[cur][kq][ca];
            uint2 u1 = Aph[cur][kq][ca + 8];
            ah[mt][0] = u0.x; ah[mt][1] = u1.x; ah[mt][2] = u0.y; ah[mt][3] = u1.y;
            uint2 v0 = Apl[cur][kq][ca];
            uint2 v1 = Apl[cur][kq][ca + 8];
            al[mt][0] = v0.x; al[mt][1] = v1.x; al[mt][2] = v0.y; al[mt][3] = v1.y;
        }
        #pragma unroll
        for (int nt = 0; nt < 8; nt++) {
            int pa = wn * 64 + nt * 8 + lr;
            uint2 bh = Bph[cur][kq][pa];
            uint2 bl = Bpl[cur][kq][pa];
            #pragma unroll
            for (int mt = 0; mt < 2; mt++) {
                mma_tf32(acc[mt][nt], ah[mt], bh.x, bh.y);
                mma_tf32(acc[mt][nt], ah[mt], bl.x, bl.y);
                mma_tf32(acc[mt][nt], al[mt], bh.x, bh.y);
            }
        }
        if (more) STASH(cur ^ 1)
        __syncthreads();
    }

    #pragma unroll
    for (int nt = 0; nt < 8; nt++) {
        int p = pix0 + wn * 64 + nt * 8 + (kq << 1);
        int n2 = p / ohw, r2 = p - n2 * ohw;
        int oy2 = r2 / OW, ox2 = r2 - oy2 * OW;
        size_t rowbase = (size_t)n2 * CO * ohw + (size_t)oy2 * OW + ox2;
        #pragma unroll
        for (int mt = 0; mt < 2; mt++) {
            int c0r = co0 + wm * 32 + mt * 16 + lr;
            float2 v0 = make_float2(acc[mt][nt][0], acc[mt][nt][1]);
            float2 v1 = make_float2(acc[mt][nt][2], acc[mt][nt][3]);
            *(float2*)&Y[rowbase + (size_t)c0r * ohw] = v0;
            *(float2*)&Y[rowbase + (size_t)(c0r + 8) * ohw] = v1;
        }
    }
    #undef GATHER_CONV
    #undef STASH
}

// ---------------- DECODER convT(k=4,s=2,p=1): parity-split 3xTF32 MMA, db -----
__global__ void __launch_bounds__(256, 2) convt_mma(
    const float* __restrict__ W, const float* __restrict__ X, float* __restrict__ Y,
    int CO, int CI, int IH, int IW, int OH, int OW)
{
    const int py = (blockIdx.z >> 1) & 1, px = blockIdx.z & 1;
    const int ky0 = 1 - py, ky1 = 3 - py, dy0 = py, dy1 = py - 1;
    const int kx0 = 1 - px, kx1 = 3 - px, dx0 = px, dx1 = px - 1;
    const int Ktot = CI * 4;
    const int NT = Ktot >> 3;
    __shared__ uint2 Aph[2][4][140], Apl[2][4][140], Bph[2][4][140], Bpl[2][4][140];
    const int t = threadIdx.x;
    const int pix0 = blockIdx.x * 128, co0 = blockIdx.y * 128;
    const int yhw = IH * IW;

    const int acol = t >> 1, ahh = t & 1;
    const int bpv = t & 127, bhh = t >> 7;
    const int pixb = pix0 + bpv;
    const int nb = pixb / yhw, remb = pixb - nb * yhw;
    const int yb = remb / IW, xb = remb - yb * IW;
    const float* Xn = X + (size_t)nb * CI * yhw;

    const int warp = t >> 5, lane = t & 31;
    const int wm = warp >> 1, wn = warp & 1;
    const int kq = lane & 3, lr = lane >> 2;

    float acc[2][8][4];
    #pragma unroll
    for (int a = 0; a < 2; a++)
        #pragma unroll
        for (int b = 0; b < 8; b++)
            #pragma unroll
            for (int c = 0; c < 4; c++) acc[a][b][c] = 0.f;

    float wA[4], vB[4];

    #define GATHER_CT(k0v)                                                       \
        {   _Pragma("unroll")                                                    \
            for (int i = 0; i < 4; i++) {                                        \
                int klocal = 2 * ahh + (i & 1) + ((i >> 1) << 2);                \
                int k = (k0v) + klocal;                                          \
                int ci = k >> 2, tt = k & 3;                                     \
                int ky = (tt & 2) ? ky1 : ky0;                                   \
                int kx = (tt & 1) ? kx1 : kx0;                                   \
                wA[i] = W[(((size_t)ci * CO + co0 + acol) << 4) + (ky << 2) + kx]; \
            }                                                                    \
            _Pragma("unroll")                                                    \
            for (int i = 0; i < 4; i++) {                                        \
                int klocal = 2 * bhh + (i & 1) + ((i >> 1) << 2);                \
                int k = (k0v) + klocal;                                          \
                int ci = k >> 2, tt = k & 3;                                     \
                int iy = yb + ((tt & 2) ? dy1 : dy0);                            \
                int ix = xb + ((tt & 1) ? dx1 : dx0);                            \
                vB[i] = ((unsigned)iy < (unsigned)IH && (unsigned)ix < (unsigned)IW) \
                        ? Xn[(ci * IH + iy) * IW + ix] : 0.f;                    \
            }                                                                    \
        }

    #define STASH2(bufv)                                                         \
        {   uint32_t h0,l0,h1,l1,h2,l2,h3,l3;                                    \
            split_tf32(wA[0],h0,l0); split_tf32(wA[1],h1,l1);                    \
            split_tf32(wA[2],h2,l2); split_tf32(wA[3],h3,l3);                    \
            Aph[bufv][2*ahh+0][acol] = make_uint2(h0, h2);                       \
            Aph[bufv][2*ahh+1][acol] = make_uint2(h1, h3);                       \
            Apl[bufv][2*ahh+0][acol] = make_uint2(l0, l2);                       \
            Apl[bufv][2*ahh+1][acol] = make_uint2(l1, l3);                       \
            split_tf32(vB[0],h0,l0); split_tf32(vB[1],h1,l1);                    \
            split_tf32(vB[2],h2,l2); split_tf32(vB[3],h3,l3);                    \
            Bph[bufv][2*bhh+0][bpv] = make_uint2(h0, h2);                        \
            Bph[bufv][2*bhh+1][bpv] = make_uint2(h1, h3);                        \
            Bpl[bufv][2*bhh+0][bpv] = make_uint2(l0, l2);                        \
            Bpl[bufv][2*bhh+1][bpv] = make_uint2(l1, l3);                        \
        }

    GATHER_CT(0)
    STASH2(0)
    __syncthreads();

    for (int tile = 0; tile < NT; tile++) {
        const int cur = tile & 1;
        const bool more = (tile + 1 < NT);
        if (more) GATHER_CT((tile + 1) << 3)

        uint32_t ah[2][4], al[2][4];
        #pragma unroll
        for (int mt = 0; mt < 2; mt++) {
            int ca = wm * 32 + mt * 16 + lr;
            uint2 u0 = Aph[cur][kq][ca];
            uint2 u1 = Aph[cur][kq][ca + 8];
            ah[mt][0] = u0.x; ah[mt][1] = u1.x; ah[mt][2] = u0.y; ah[mt][3] = u1.y;
            uint2 v0 = Apl[cur][kq][ca];
            uint2 v1 = Apl[cur][kq][ca + 8];
            al[mt][0] = v0.x; al[mt][1] = v1.x; al[mt][2] = v0.y; al[mt][3] = v1.y;
        }
        #pragma unroll
        for (int nt = 0; nt < 8; nt++) {
            int pa = wn * 64 + nt * 8 + lr;
            uint2 bh = Bph[cur][kq][pa];
            uint2 bl = Bpl[cur][kq][pa];
            #pragma unroll
            for (int mt = 0; mt < 2; mt++) {
                mma_tf32(acc[mt][nt], ah[mt], bh.x, bh.y);
                mma_tf32(acc[mt][nt], ah[mt], bl.x, bl.y);
                mma_tf32(acc[mt][nt], al[mt], bh.x, bh.y);
            }
        }
        if (more) STASH2(cur ^ 1)
        __syncthreads();
    }

    const size_t ostride = (size_t)OH * OW;
    #pragma unroll
    for (int nt = 0; nt < 8; nt++) {
        #pragma unroll
        for (int e = 0; e < 2; e++) {
            int pp = pix0 + wn * 64 + nt * 8 + (kq << 1) + e;
            int n2 = pp / yhw, r2 = pp - n2 * yhw;
            int y2 = r2 / IW, x2 = r2 - y2 * IW;
            int oy = (y2 << 1) + py, ox = (x2 << 1) + px;
            #pragma unroll
            for (int mt = 0; mt < 2; mt++) {
                int c0r = co0 + wm * 32 + mt * 16 + lr;
                size_t idx = (((size_t)n2 * CO + c0r) * OH + oy) * OW + ox;
                Y[idx] = acc[mt][nt][e];
                Y[idx + 8 * ostride] = acc[mt][nt][2 + e];
            }
        }
    }
    #undef GATHER_CT
    #undef STASH2
}

// ---------------- d_t2 weight repack: Wp[py*2+px][ci][co][tap] ----------------
__global__ void pack_wt2(const float* __restrict__ W, float* __restrict__ Wp)
{
    int i = blockIdx.x * blockDim.x + threadIdx.x;
    if (i >= 12288) return;
    int tap = i & 3;
    int r = i >> 2;
    int co = r % 3;
    int r2 = r / 3;
    int ci = r2 & 255;
    int pp = r2 >> 8;
    int py = pp >> 1, px = pp & 1;
    int ky = ((tap >> 1) == 0) ? (1 - py) : (3 - py);
    int kx = ((tap & 1) == 0) ? (1 - px) : (3 - px);
    Wp[i] = W[((size_t)ci * 3 + co) * 16 + ky * 4 + kx];
}

// ---------------- direct ConvTranspose CO=3, packed weights, zero-fill taps ---
// Bit-identical to round-9 convt_direct: same tap order (ky asc, kx asc), OOB
// taps contribute fmaf(0,w,acc)=acc exactly.
__global__ void __launch_bounds__(256) convt_direct2(
    const float* __restrict__ Wp, const float* __restrict__ X, float* __restrict__ Y,
    int CI, int IH, int IW, int OH, int OW)
{
    int ox = threadIdx.x, oy = blockIdx.x, n = blockIdx.z;
    int py = oy & 1, px = ox & 1;
    int iyA = (oy + py) >> 1, iyB = iyA - 1;
    int ixA = (ox + px) >> 1, ixB = ixA - 1;
    bool vyA = (unsigned)iyA < (unsigned)IH, vyB = (unsigned)iyB < (unsigned)IH;
    bool vxA = (unsigned)ixA < (unsigned)IW, vxB = (unsigned)ixB < (unsigned)IW;
    const float* Xn = X + (size_t)n * CI * IH * IW;
    const float4* wp = (const float4*)(Wp + (size_t)(py * 2 + px) * 256 * 12);

    float a0 = 0.f, a1 = 0.f, a2 = 0.f;
    for (int ci = 0; ci < CI; ci++) {
        const float* xc = Xn + (size_t)ci * IH * IW;
        float x00 = (vyA && vxA) ? xc[iyA * IW + ixA] : 0.f;
        float x01 = (vyA && vxB) ? xc[iyA * IW + ixB] : 0.f;
        float x10 = (vyB && vxA) ? xc[iyB * IW + ixA] : 0.f;
        float x11 = (vyB && vxB) ? xc[iyB * IW + ixB] : 0.f;
        float4 w0 = wp[ci * 3 + 0];
        float4 w1 = wp[ci * 3 + 1];
        float4 w2 = wp[ci * 3 + 2];
        a0 = fmaf(x00, w0.x, a0); a0 = fmaf(x01, w0.y, a0);
        a0 = fmaf(x10, w0.z, a0); a0 = fmaf(x11, w0.w, a0);
        a1 = fmaf(x00, w1.x, a1); a1 = fmaf(x01, w1.y, a1);
        a1 = fmaf(x10, w1.z, a1); a1 = fmaf(x11, w1.w, a1);
        a2 = fmaf(x00, w2.x, a2); a2 = fmaf(x01, w2.y, a2);
        a2 = fmaf(x10, w2.z, a2); a2 = fmaf(x11, w2.w, a2);
    }
    size_t ohw = (size_t)OH * OW;
    size_t base = (size_t)n * 3 * ohw + (size_t)oy * OW + ox;
    Y[base] = a0;
    Y[base + ohw] = a1;
    Y[base + 2 * ohw] = a2;
}

// ---------------- BatchNorm stats: fp32 Kahan (FROZEN) ----------------
__global__ void bn_stats(const float* __restrict__ x, const float* __restrict__ r,
                         float* __restrict__ mean, float* __restrict__ istd,
                         int C, int HW, int Bn)
{
    int c = blockIdx.x;
    float s = 0.f, cs = 0.f, ss = 0.f, css = 0.f;
    for (int n = 0; n < Bn; n++) {
        const float* p = x + (size_t)(n * C + c) * HW;
        const float* q = r ? r + (size_t)(n * C + c) * HW : (const float*)0;
        for (int i = threadIdx.x; i < HW; i += blockDim.x) {
            float v = p[i];
            if (q) v = __fadd_rn(v, q[i]);
            float y1 = __fsub_rn(v, cs);
            float t1 = __fadd_rn(s, y1);
            cs = __fsub_rn(__fsub_rn(t1, s), y1); s = t1;
            float w = __fmul_rn(v, v);
            float y2 = __fsub_rn(w, css);
            float t2 = __fadd_rn(ss, y2);
            css = __fsub_rn(__fsub_rn(t2, ss), y2); ss = t2;
        }
    }
    s = __fsub_rn(s, cs); ss = __fsub_rn(ss, css);
    __shared__ float shs[32], shss[32];
    int lane = threadIdx.x & 31, wid = threadIdx.x >> 5;
    #pragma unroll
    for (int o = 16; o > 0; o >>= 1) {
        s  += __shfl_down_sync(0xffffffffu, s,  o);
        ss += __shfl_down_sync(0xffffffffu, ss, o);
    }
    if (lane == 0) { shs[wid] = s; shss[wid] = ss; }
    __syncthreads();
    if (threadIdx.x == 0) {
        int nw = blockDim.x >> 5;
        float ts = 0.f, tss = 0.f;
        for (int i = 0; i < nw; i++) { ts += shs[i]; tss += shss[i]; }
        float inv = 1.f / ((float)Bn * (float)HW);
        float m = ts * inv;
        float var = fmaxf(tss * inv - m * m, 0.f);
        mean[c] = m;
        istd[c] = rsqrtf(var + EPSBN);
    }
}

__global__ void bn_apply4(const float4* __restrict__ x, const float4* __restrict__ r,
                          float4* __restrict__ y,
                          const float* __restrict__ g, const float* __restrict__ b,
                          const float* __restrict__ mean, const float* __restrict__ istd,
                          int C, int hwshift4, int total4, int mode)
{
    int stride = gridDim.x * blockDim.x;
    for (int i = blockIdx.x * blockDim.x + threadIdx.x; i < total4; i += stride) {
        int c = (i >> hwshift4) % C;
        float4 v = x[i];
        if (r) {
            float4 rv = r[i];
            v.x = __fadd_rn(v.x, rv.x); v.y = __fadd_rn(v.y, rv.y);
            v.z = __fadd_rn(v.z, rv.z); v.w = __fadd_rn(v.w, rv.w);
        }
        float gc = g[c], bc = b[c], mc = mean[c], ic = istd[c];
        v.x = __fadd_rn(__fmul_rn(__fmul_rn(gc, __fsub_rn(v.x, mc)), ic), bc);
        v.y = __fadd_rn(__fmul_rn(__fmul_rn(gc, __fsub_rn(v.y, mc)), ic), bc);
        v.z = __fadd_rn(__fmul_rn(__fmul_rn(gc, __fsub_rn(v.z, mc)), ic), bc);
        v.w = __fadd_rn(__fmul_rn(__fmul_rn(gc, __fsub_rn(v.w, mc)), ic), bc);
        if (mode == 1) {
            v.x = fmaxf(v.x, 0.f); v.y = fmaxf(v.y, 0.f);
            v.z = fmaxf(v.z, 0.f); v.w = fmaxf(v.w, 0.f);
        } else if (mode == 2) {
            v.x = tanhf(v.x); v.y = tanhf(v.y);
            v.z = tanhf(v.z); v.w = tanhf(v.w);
        }
        y[i] = v;
    }
}

// ---------------- VQ (FROZEN: bit-exact path validated in round 4) ----------
__global__ void transpose_cb(const float* __restrict__ cb, float* __restrict__ cbT)
{
    int i = blockIdx.x * blockDim.x + threadIdx.x;
    int j = i >> 8, k = i & 255;
    cbT[k * 512 + j] = cb[i];
}

__global__ void cnorm_k(const float* __restrict__ cb, float* __restrict__ cn)
{
    int j = blockIdx.x * blockDim.x + threadIdx.x;
    if (j < 512) {
        float s = 0.f;
        const float* p = cb + j * 256;
        for (int c = 0; c < 256; c++) s = __fadd_rn(s, __fmul_rn(p[c], p[c]));
        cn[j] = s;
    }
}

__global__ void fnorm_k(const float* __restrict__ ze, float* __restrict__ fn, int HW)
{
    int w = (blockIdx.x * blockDim.x + threadIdx.x) >> 5;
    int lane = threadIdx.x & 31;
    int n = w / HW, hw = w - n * HW;
    const float* base = ze + (size_t)n * 256 * HW + hw;
    float s = 0.f;
    for (int k = lane; k < 256; k += 32) {
        float v = base[(size_t)k * HW];
        s = __fadd_rn(s, __fmul_rn(v, v));
    }
    #pragma unroll
    for (int o = 16; o > 0; o >>= 1) s += __shfl_down_sync(0xffffffffu, s, o);
    if (lane == 0) fn[w] = s;
}

#define VQ_KC 16
__global__ void __launch_bounds__(512) vq_dist_argmin(
    const float* __restrict__ ze, const float* __restrict__ cbT,
    const float* __restrict__ cn, const float* __restrict__ fnorm,
    int* __restrict__ idx, int HW)
{
    __shared__ float fs[64 * 17];
    __shared__ __align__(16) float cbs[VQ_KC * 512];
    __shared__ float cns[512];
    __shared__ float rd[64 * 8];
    __shared__ int   rj[64 * 8];

    const int t = threadIdx.x, px = t & 63, jg = t >> 6;
    const int p = blockIdx.x * 64 + px;
    cns[t] = cn[t];

    float acc[64];
    #pragma unroll
    for (int j = 0; j < 64; j++) acc[j] = 0.f;

    for (int k0 = 0; k0 < 256; k0 += VQ_KC) {
        __syncthreads();
        for (int i = t; i < 64 * VQ_KC; i += 512) {
            int kk = i >> 6, pp = i & 63;
            int gp = blockIdx.x * 64 + pp;
            int gn = gp / HW, ghw = gp - gn * HW;
            fs[pp * 17 + kk] = ze[((size_t)gn * 256 + (k0 + kk)) * HW + ghw];
        }
        for (int i = t; i < VQ_KC * 512; i += 512)
            cbs[i] = cbT[(size_t)(k0 + (i >> 9)) * 512 + (i & 511)];
        __syncthreads();

        float fv[VQ_KC];
        #pragma unroll
        for (int kk = 0; kk < VQ_KC; kk++) fv[kk] = fs[px * 17 + kk];

        #pragma unroll
        for (int j4 = 0; j4 < 16; j4++) {
            float a0, a1, a2, a3;
            {
                float4 c = *(const float4*)&cbs[jg * 64 + j4 * 4];
                a0 = __fmul_rn(fv[0], c.x); a1 = __fmul_rn(fv[0], c.y);
                a2 = __fmul_rn(fv[0], c.z); a3 = __fmul_rn(fv[0], c.w);
                #pragma unroll
                for (int kk = 1; kk < 8; kk++) {
                    float4 d = *(const float4*)&cbs[kk * 512 + jg * 64 + j4 * 4];
                    a0 = fmaf(fv[kk], d.x, a0); a1 = fmaf(fv[kk], d.y, a1);
                    a2 = fmaf(fv[kk], d.z, a2); a3 = fmaf(fv[kk], d.w, a3);
                }
                acc[j4*4+0] = __fadd_rn(acc[j4*4+0], a0);
                acc[j4*4+1] = __fadd_rn(acc[j4*4+1], a1);
                acc[j4*4+2] = __fadd_rn(acc[j4*4+2], a2);
                acc[j4*4+3] = __fadd_rn(acc[j4*4+3], a3);
            }
            {
                float4 c = *(const float4*)&cbs[8 * 512 + jg * 64 + j4 * 4];
                a0 = __fmul_rn(fv[8], c.x); a1 = __fmul_rn(fv[8], c.y);
                a2 = __fmul_rn(fv[8], c.z); a3 = __fmul_rn(fv[8], c.w);
                #pragma unroll
                for (int kk = 9; kk < 16; kk++) {
                    float4 d = *(const float4*)&cbs[kk * 512 + jg * 64 + j4 * 4];
                    a0 = fmaf(fv[kk], d.x, a0); a1 = fmaf(fv[kk], d.y, a1);
                    a2 = fmaf(fv[kk], d.z, a2); a3 = fmaf(fv[kk], d.w, a3);
                }
                acc[j4*4+0] = __fadd_rn(acc[j4*4+0], a0);
                acc[j4*4+1] = __fadd_rn(acc[j4*4+1], a1);
                acc[j4*4+2] = __fadd_rn(acc[j4*4+2], a2);
                acc[j4*4+3] = __fadd_rn(acc[j4*4+3], a3);
            }
        }
    }

    float S = fnorm[p];
    float best = 3.4028235e38f;
    int bj = 0;
    #pragma unroll
    for (int j = 0; j < 64; j++) {
        float q = __fsub_rn(S, __fmul_rn(2.0f, acc[j]));
        float dj = __fadd_rn(q, cns[jg * 64 + j]);
        if (dj < best) { best = dj; bj = jg * 64 + j; }
    }
    rd[px * 8 + jg] = best;
    rj[px * 8 + jg] = bj;
    __syncthreads();
    if (t < 64) {
        float bb = rd[t * 8]; int jj = rj[t * 8];
        #pragma unroll
        for (int gsel = 1; gsel < 8; gsel++) {
            float d2 = rd[t * 8 + gsel];
            if (d2 < bb) { bb = d2; jj = rj[t * 8 + gsel]; }
        }
        idx[blockIdx.x * 64 + t] = jj;
    }
}

__global__ void vq_gather(const int* __restrict__ idx, const float* __restrict__ cb,
                          float* __restrict__ zq, int HW, int total)
{
    int stride = gridDim.x * blockDim.x;
    for (int i = blockIdx.x * blockDim.x + threadIdx.x; i < total; i += stride) {
        int hw = i % HW, nc = i / HW, c = nc & 255, n = nc >> 8;
        zq[i] = cb[idx[n * HW + hw] * 256 + c];
    }
}

// ---------------- pipeline ----------------
extern "C" void kernel_launch(void* const* d_in, const int* in_sizes, int n_in,
                              void* d_out, int out_size)
{
    const float* img  = (const float*)d_in[0];
    const float* e_w1 = (const float*)d_in[1];
    const float* e_g1 = (const float*)d_in[2];
    const float* e_b1 = (const float*)d_in[3];
    const float* e_w2 = (const float*)d_in[4];
    const float* e_g2 = (const float*)d_in[5];
    const float* e_b2 = (const float*)d_in[6];
    const float* e_w3 = (const float*)d_in[7];
    const float* e_g3 = (const float*)d_in[8];
    const float* e_b3 = (const float*)d_in[9];
    const float* e_w4 = (const float*)d_in[10];
    const float* e_g4 = (const float*)d_in[12];
    const float* e_b4 = (const float*)d_in[13];
    const float* e_g5 = (const float*)d_in[14];
    const float* e_b5 = (const float*)d_in[15];
    const float* cb   = (const float*)d_in[16];
    const float* dw1  = (const float*)d_in[17];
    const float* dg1  = (const float*)d_in[18];
    const float* db1  = (const float*)d_in[19];
    const float* dw2  = (const float*)d_in[20];
    const float* dg2  = (const float*)d_in[21];
    const float* db2  = (const float*)d_in[22];
    const float* dg3  = (const float*)d_in[23];
    const float* db3  = (const float*)d_in[24];
    const float* dt1  = (const float*)d_in[25];
    const float* dg4  = (const float*)d_in[26];
    const float* db4  = (const float*)d_in[27];
    const float* dt2  = (const float*)d_in[28];
    const float* dg5  = (const float*)d_in[30];
    const float* db5  = (const float*)d_in[31];
    float* out = (float*)d_out;

    float *buf128, *b64a, *b64b, *b64c, *mean, *istd, *cnorm, *fnorm, *cbT, *wp;
    int* idx;
    cudaGetSymbolAddress((void**)&buf128, g_buf128);
    cudaGetSymbolAddress((void**)&b64a,   g_b64a);
    cudaGetSymbolAddress((void**)&b64b,   g_b64b);
    cudaGetSymbolAddress((void**)&b64c,   g_b64c);
    cudaGetSymbolAddress((void**)&mean,   g_mean);
    cudaGetSymbolAddress((void**)&istd,   g_istd);
    cudaGetSymbolAddress((void**)&cnorm,  g_cnorm);
    cudaGetSymbolAddress((void**)&fnorm,  g_fnorm);
    cudaGetSymbolAddress((void**)&cbT,    g_cbT);
    cudaGetSymbolAddress((void**)&wp,     g_wp);
    cudaGetSymbolAddress((void**)&idx,    g_idx);

    const int T128 = 33554432, T64 = 8388608;
    const int Q128 = T128 / 4, Q64 = T64 / 4;
    #define F4(p) ((float4*)(p))
    #define CF4(p) ((const float4*)(p))

    // independent prep
    pack_wt2<<<48, 256>>>(dt2, wp);
    transpose_cb<<<512, 256>>>(cb, cbT);
    cnorm_k<<<2, 256>>>(cb, cnorm);

    // ---- encoder (fp32 SIMT + cp.async db; values & FMA order FROZEN) ----
    conv_gemm_ca<16,4,2,1><<<dim3(1024, 2), 256>>>(e_w1, img, buf128, 256, 3, 256, 256, 128, 128);
    bn_stats<<<256, 256>>>(buf128, (const float*)0, mean, istd, 256, 16384, 8);
    bn_apply4<<<8192, 256>>>(CF4(buf128), (const float4*)0, F4(buf128), e_g1, e_b1, mean, istd, 256, 12, Q128, 1);

    conv_gemm_ca<16,4,2,1><<<dim3(256, 2), 256>>>(e_w2, buf128, b64a, 256, 256, 128, 128, 64, 64);
    bn_stats<<<256, 256>>>(b64a, (const float*)0, mean, istd, 256, 4096, 8);
    bn_apply4<<<4096, 256>>>(CF4(b64a), (const float4*)0, F4(b64a), e_g2, e_b2, mean, istd, 256, 10, Q64, 1);

    conv_gemm_ca<9,3,1,1><<<dim3(256, 2), 256>>>(e_w3, b64a, b64b, 256, 256, 64, 64, 64, 64);
    bn_stats<<<256, 256>>>(b64b, (const float*)0, mean, istd, 256, 4096, 8);
    bn_apply4<<<4096, 256>>>(CF4(b64b), (const float4*)0, F4(b64b), e_g3, e_b3, mean, istd, 256, 10, Q64, 1);

    conv_gemm_ca<1,1,1,0><<<dim3(256, 2), 256>>>(e_w4, b64b, b64c, 256, 256, 64, 64, 64, 64);
    bn_stats<<<256, 256>>>(b64c, (const float*)0, mean, istd, 256, 4096, 8);
    bn_apply4<<<4096, 256>>>(CF4(b64c), (const float4*)0, F4(b64c), e_g4, e_b4, mean, istd, 256, 10, Q64, 1);

    bn_stats<<<256, 256>>>(b64a, b64c, mean, istd, 256, 4096, 8);
    bn_apply4<<<4096, 256>>>(CF4(b64a), CF4(b64c), F4(b64b), e_g5, e_b5, mean, istd, 256, 10, Q64, 0);

    // ---- VQ (frozen) ----
    fnorm_k<<<4096, 256>>>(b64b, fnorm, 4096);
    vq_dist_argmin<<<512, 512>>>(b64b, cbT, cnorm, fnorm, idx, 4096);
    vq_gather<<<8192, 256>>>(idx, cb, b64c, 4096, T64);

    // ---- decoder (3-pass split-TF32 tensor cores, tolerance path) ----
    conv_mma_t<9,3,1><<<dim3(256, 2), 256>>>(dw1, b64c, b64a, 256, 256, 64, 64, 64, 64);
    bn_stats<<<256, 256>>>(b64a, (const float*)0, mean, istd, 256, 4096, 8);
    bn_apply4<<<4096, 256>>>(CF4(b64a), (const float4*)0, F4(b64a), dg1, db1, mean, istd, 256, 10, Q64, 1);

    conv_mma_t<1,1,0><<<dim3(256, 2), 256>>>(dw2, b64a, b64b, 256, 256, 64, 64, 64, 64);
    bn_stats<<<256, 256>>>(b64b, (const float*)0, mean, istd, 256, 4096, 8);
    bn_apply4<<<4096, 256>>>(CF4(b64b), (const float4*)0, F4(b64b), dg2, db2, mean, istd, 256, 10, Q64, 1);

    bn_stats<<<256, 256>>>(b64c, b64b, mean, istd, 256, 4096, 8);
    bn_apply4<<<4096, 256>>>(CF4(b64c), CF4(b64b), F4(b64a), dg3, db3, mean, istd, 256, 10, Q64, 1);

    convt_mma<<<dim3(256, 2, 4), 256>>>(dt1, b64a, buf128, 256, 256, 64, 64, 128, 128);
    bn_stats<<<256, 256>>>(buf128, (const float*)0, mean, istd, 256, 16384, 8);
    bn_apply4<<<8192, 256>>>(CF4(buf128), (const float4*)0, F4(buf128), dg4, db4, mean, istd, 256, 12, Q128, 1);

    convt_direct2<<<dim3(256, 1, 8), 256>>>(wp, buf128, out, 256, 128, 128, 256, 256);
    bn_stats<<<3, 256>>>(out, (const float*)0, mean, istd, 3, 65536, 8);
    bn_apply4<<<384, 256>>>(CF4(out), (const float4*)0, F4(out), dg5, db5, mean, istd, 3, 14, 393216, 2);
}

// round 13
// speedup vs baseline: 1.0446x; 1.0446x over previous
#include <cuda_runtime.h>
#include <math.h>
#include <stdint.h>

#define EPSBN 1e-5f

__device__ float g_buf128[33554432];
__device__ float g_b64a[8388608];
__device__ float g_b64b[8388608];
__device__ float g_b64c[8388608];
__device__ float g_mean[256];
__device__ float g_istd[256];
__device__ float g_cnorm[512];
__device__ float g_fnorm[32768];
__device__ float g_cbT[131072];
__device__ float g_wp[12288];
__device__ int   g_idx[32768];

// ---------------- tf32 helpers (decoder tolerance path only) ----------------
__device__ __forceinline__ uint32_t f2tf32(float x) {
    uint32_t r;
    asm("cvt.rna.tf32.f32 %0, %1;" : "=r"(r) : "f"(x));
    return r;
}
__device__ __forceinline__ void split_tf32(float x, uint32_t& h, uint32_t& l) {
    h = f2tf32(x);
    l = f2tf32(x - __uint_as_float(h));
}
__device__ __forceinline__ void mma_tf32(float* c, const uint32_t* a, uint32_t b0, uint32_t b1) {
    asm volatile(
        "mma.sync.aligned.m16n8k8.row.col.f32.tf32.tf32.f32 "
        "{%0,%1,%2,%3}, {%4,%5,%6,%7}, {%8,%9}, {%0,%1,%2,%3};\n"
        : "+f"(c[0]), "+f"(c[1]), "+f"(c[2]), "+f"(c[3])
        : "r"(a[0]), "r"(a[1]), "r"(a[2]), "r"(a[3]), "r"(b0), "r"(b1));
}

// ---------------- ENCODER conv: 128x128x8 fp32 SIMT (numerics FROZEN) --------
// Per-(co,pixel) ascending-k FMA chain, acc->tot folds every 64 k — bit-
// identical to rounds 4-11 (the proven 9373us configuration). z_e bits feed
// the VQ argmin; round-10 proved zero tolerance for perturbation. Round-12
// proved cp.async-per-4B is a 2.3x regression on this layout. DO NOT ALTER.
template<int KHW, int KW, int STRIDE, int PAD>
__global__ void __launch_bounds__(256, 2) conv_gemm_t(
    const float* __restrict__ W, const float* __restrict__ X, float* __restrict__ Y,
    int CO, int CI, int IH, int IW, int OH, int OW)
{
    const int Ktot = CI * KHW;
    __shared__ __align__(16) float As[8][128];
    __shared__ __align__(16) float Bs[8][128];
    const int t = threadIdx.x;
    const int pix0 = blockIdx.x * 128, co0 = blockIdx.y * 128;
    const int ohw = OH * OW;

    const int acol = t >> 1;
    const int akq  = (t & 1) << 2;
    const float* Wrow = W + (size_t)(co0 + acol) * Ktot + akq;

    const int bpv = t & 127;
    const int bkq = (t >> 7) << 2;
    const int pixb = pix0 + bpv;
    const int nb = pixb / ohw, remb = pixb - nb * ohw;
    const int oyb = remb / OW, oxb = remb - oyb * OW;
    const int iy0 = oyb * STRIDE - PAD, ix0 = oxb * STRIDE - PAD;
    const float* Xn = X + (size_t)nb * CI * IH * IW;

    const int tx = t & 15, ty = t >> 4;
    float acc[8][8] = {};
    float tot[8][8] = {};
    int nch = 0;

    for (int k0 = 0; k0 < Ktot; k0 += 8) {
        float4 wv = *(const float4*)(Wrow + k0);
        float bval[4];
        #pragma unroll
        for (int i = 0; i < 4; i++) {
            int k = k0 + bkq + i;
            int ci = k / KHW;
            int kr = k - ci * KHW;
            int ky = kr / KW;
            int kx = kr - ky * KW;
            int iy = iy0 + ky, ix = ix0 + kx;
            float v = 0.f;
            if ((unsigned)iy < (unsigned)IH && (unsigned)ix < (unsigned)IW)
                v = Xn[(ci * IH + iy) * IW + ix];
            bval[i] = v;
        }
        As[akq + 0][acol] = wv.x;
        As[akq + 1][acol] = wv.y;
        As[akq + 2][acol] = wv.z;
        As[akq + 3][acol] = wv.w;
        #pragma unroll
        for (int i = 0; i < 4; i++) Bs[bkq + i][bpv] = bval[i];
        __syncthreads();
        #pragma unroll
        for (int kk = 0; kk < 8; kk++) {
            float4 a0 = *(const float4*)&As[kk][ty << 2];
            float4 a1 = *(const float4*)&As[kk][64 + (ty << 2)];
            float4 b0 = *(const float4*)&Bs[kk][tx << 2];
            float4 b1 = *(const float4*)&Bs[kk][64 + (tx << 2)];
            float av[8] = {a0.x, a0.y, a0.z, a0.w, a1.x, a1.y, a1.z, a1.w};
            float bv[8] = {b0.x, b0.y, b0.z, b0.w, b1.x, b1.y, b1.z, b1.w};
            #pragma unroll
            for (int i = 0; i < 8; i++)
                #pragma unroll
                for (int j = 0; j < 8; j++)
                    acc[i][j] = fmaf(av[i], bv[j], acc[i][j]);
        }
        __syncthreads();
        if (++nch == 8) {
            nch = 0;
            #pragma unroll
            for (int i = 0; i < 8; i++)
                #pragma unroll
                for (int j = 0; j < 8; j++) {
                    tot[i][j] = __fadd_rn(tot[i][j], acc[i][j]);
                    acc[i][j] = 0.f;
                }
        }
    }
    #pragma unroll
    for (int i = 0; i < 8; i++)
        #pragma unroll
        for (int j = 0; j < 8; j++) tot[i][j] = __fadd_rn(tot[i][j], acc[i][j]);

    #pragma unroll
    for (int j = 0; j < 8; j++) {
        int pj = (j < 4) ? (tx << 2) + j : 64 + (tx << 2) + (j - 4);
        int p = pix0 + pj;
        int n2 = p / ohw, r2 = p - n2 * ohw;
        int oy2 = r2 / OW, ox2 = r2 - oy2 * OW;
        size_t base = (size_t)n2 * CO * ohw + (size_t)oy2 * OW + ox2;
        #pragma unroll
        for (int i = 0; i < 8; i++) {
            int co = co0 + ((i < 4) ? (ty << 2) + i : 64 + (ty << 2) + (i - 4));
            Y[base + (size_t)co * ohw] = tot[i][j];
        }
    }
}

// ---------------- DECODER conv: 128x128x8 3xTF32 MMA, db + uint2-paired smem --
template<int KHW, int KW, int PAD>
__global__ void __launch_bounds__(256, 2) conv_mma_t(
    const float* __restrict__ W, const float* __restrict__ X, float* __restrict__ Y,
    int CO, int CI, int IH, int IW, int OH, int OW)
{
    const int Ktot = CI * KHW;
    const int NT = Ktot >> 3;
    __shared__ uint2 Aph[2][4][140], Apl[2][4][140], Bph[2][4][140], Bpl[2][4][140];
    const int t = threadIdx.x;
    const int pix0 = blockIdx.x * 128, co0 = blockIdx.y * 128;
    const int ohw = OH * OW;

    const int acol = t >> 1, ahh = t & 1;
    const float* Wrow = W + (size_t)(co0 + acol) * Ktot;

    const int bpv = t & 127, bhh = t >> 7;
    const int pixb = pix0 + bpv;
    const int nb = pixb / ohw, remb = pixb - nb * ohw;
    const int oyb = remb / OW, oxb = remb - oyb * OW;
    const int iy0 = oyb - PAD, ix0 = oxb - PAD;
    const float* Xn = X + (size_t)nb * CI * IH * IW;

    const int warp = t >> 5, lane = t & 31;
    const int wm = warp >> 1, wn = warp & 1;
    const int kq = lane & 3, lr = lane >> 2;

    float acc[2][8][4];
    #pragma unroll
    for (int a = 0; a < 2; a++)
        #pragma unroll
        for (int b = 0; b < 8; b++)
            #pragma unroll
            for (int c = 0; c < 4; c++) acc[a][b][c] = 0.f;

    float wA[4], vB[4];

    #define GATHER_CONV(k0v)                                                     \
        {   float2 w01 = *(const float2*)(Wrow + (k0v) + 2 * ahh);               \
            float2 w45 = *(const float2*)(Wrow + (k0v) + 2 * ahh + 4);           \
            wA[0] = w01.x; wA[1] = w01.y; wA[2] = w45.x; wA[3] = w45.y;          \
            _Pragma("unroll")                                                    \
            for (int i = 0; i < 4; i++) {                                        \
                int klocal = 2 * bhh + (i & 1) + ((i >> 1) << 2);                \
                int k = (k0v) + klocal;                                          \
                int ci = k / KHW;                                                \
                int kr = k - ci * KHW;                                           \
                int ky = kr / KW;                                                \
                int kx = kr - ky * KW;                                           \
                int iy = iy0 + ky, ix = ix0 + kx;                                \
                float v = 0.f;                                                   \
                if ((unsigned)iy < (unsigned)IH && (unsigned)ix < (unsigned)IW)  \
                    v = Xn[(ci * IH + iy) * IW + ix];                            \
                vB[i] = v;                                                       \
            }                                                                    \
        }

    #define STASH(bufv)                                                          \
        {   uint32_t h0,l0,h1,l1,h2,l2,h3,l3;                                    \
            split_tf32(wA[0],h0,l0); split_tf32(wA[1],h1,l1);                    \
            split_tf32(wA[2],h2,l2); split_tf32(wA[3],h3,l3);                    \
            Aph[bufv][2*ahh+0][acol] = make_uint2(h0, h2);                       \
            Aph[bufv][2*ahh+1][acol] = make_uint2(h1, h3);                       \
            Apl[bufv][2*ahh+0][acol] = make_uint2(l0, l2);                       \
            Apl[bufv][2*ahh+1][acol] = make_uint2(l1, l3);                       \
            split_tf32(vB[0],h0,l0); split_tf32(vB[1],h1,l1);                    \
            split_tf32(vB[2],h2,l2); split_tf32(vB[3],h3,l3);                    \
            Bph[bufv][2*bhh+0][bpv] = make_uint2(h0, h2);                        \
            Bph[bufv][2*bhh+1][bpv] = make_uint2(h1, h3);                        \
            Bpl[bufv][2*bhh+0][bpv] = make_uint2(l0, l2);                        \
            Bpl[bufv][2*bhh+1][bpv] = make_uint2(l1, l3);                        \
        }

    GATHER_CONV(0)
    STASH(0)
    __syncthreads();

    for (int tile = 0; tile < NT; tile++) {
        const int cur = tile & 1;
        const bool more = (tile + 1 < NT);
        if (more) GATHER_CONV((tile + 1) << 3)

        uint32_t ah[2][4], al[2][4];
        #pragma unroll
        for (int mt = 0; mt < 2; mt++) {
            int ca = wm * 32 + mt * 16 + lr;
            uint2 u0 = Aph[cur][kq][ca];
            uint2 u1 = Aph[cur][kq][ca + 8];
            ah[mt][0] = u0.x; ah[mt][1] = u1.x; ah[mt][2] = u0.y; ah[mt][3] = u1.y;
            uint2 v0 = Apl[cur][kq][ca];
            uint2 v1 = Apl[cur][kq][ca + 8];
            al[mt][0] = v0.x; al[mt][1] = v1.x; al[mt][2] = v0.y; al[mt][3] = v1.y;
        }
        #pragma unroll
        for (int nt = 0; nt < 8; nt++) {
            int pa = wn * 64 + nt * 8 + lr;
            uint2 bh = Bph[cur][kq][pa];
            uint2 bl = Bpl[cur][kq][pa];
            #pragma unroll
            for (int mt = 0; mt < 2; mt++) {
                mma_tf32(acc[mt][nt], ah[mt], bh.x, bh.y);
                mma_tf32(acc[mt][nt], ah[mt], bl.x, bl.y);
                mma_tf32(acc[mt][nt], al[mt], bh.x, bh.y);
            }
        }
        if (more) STASH(cur ^ 1)
        __syncthreads();
    }

    #pragma unroll
    for (int nt = 0; nt < 8; nt++) {
        int p = pix0 + wn * 64 + nt * 8 + (kq << 1);
        int n2 = p / ohw, r2 = p - n2 * ohw;
        int oy2 = r2 / OW, ox2 = r2 - oy2 * OW;
        size_t rowbase = (size_t)n2 * CO * ohw + (size_t)oy2 * OW + ox2;
        #pragma unroll
        for (int mt = 0; mt < 2; mt++) {
            int c0r = co0 + wm * 32 + mt * 16 + lr;
            float2 v0 = make_float2(acc[mt][nt][0], acc[mt][nt][1]);
            float2 v1 = make_float2(acc[mt][nt][2], acc[mt][nt][3]);
            *(float2*)&Y[rowbase + (size_t)c0r * ohw] = v0;
            *(float2*)&Y[rowbase + (size_t)(c0r + 8) * ohw] = v1;
        }
    }
    #undef GATHER_CONV
    #undef STASH
}

// ---------------- DECODER convT(k=4,s=2,p=1): parity-split 3xTF32 MMA, db -----
__global__ void __launch_bounds__(256, 2) convt_mma(
    const float* __restrict__ W, const float* __restrict__ X, float* __restrict__ Y,
    int CO, int CI, int IH, int IW, int OH, int OW)
{
    const int py = (blockIdx.z >> 1) & 1, px = blockIdx.z & 1;
    const int ky0 = 1 - py, ky1 = 3 - py, dy0 = py, dy1 = py - 1;
    const int kx0 = 1 - px, kx1 = 3 - px, dx0 = px, dx1 = px - 1;
    const int Ktot = CI * 4;
    const int NT = Ktot >> 3;
    __shared__ uint2 Aph[2][4][140], Apl[2][4][140], Bph[2][4][140], Bpl[2][4][140];
    const int t = threadIdx.x;
    const int pix0 = blockIdx.x * 128, co0 = blockIdx.y * 128;
    const int yhw = IH * IW;

    const int acol = t >> 1, ahh = t & 1;
    const int bpv = t & 127, bhh = t >> 7;
    const int pixb = pix0 + bpv;
    const int nb = pixb / yhw, remb = pixb - nb * yhw;
    const int yb = remb / IW, xb = remb - yb * IW;
    const float* Xn = X + (size_t)nb * CI * yhw;

    const int warp = t >> 5, lane = t & 31;
    const int wm = warp >> 1, wn = warp & 1;
    const int kq = lane & 3, lr = lane >> 2;

    float acc[2][8][4];
    #pragma unroll
    for (int a = 0; a < 2; a++)
        #pragma unroll
        for (int b = 0; b < 8; b++)
            #pragma unroll
            for (int c = 0; c < 4; c++) acc[a][b][c] = 0.f;

    float wA[4], vB[4];

    #define GATHER_CT(k0v)                                                       \
        {   _Pragma("unroll")                                                    \
            for (int i = 0; i < 4; i++) {                                        \
                int klocal = 2 * ahh + (i & 1) + ((i >> 1) << 2);                \
                int k = (k0v) + klocal;                                          \
                int ci = k >> 2, tt = k & 3;                                     \
                int ky = (tt & 2) ? ky1 : ky0;                                   \
                int kx = (tt & 1) ? kx1 : kx0;                                   \
                wA[i] = W[(((size_t)ci * CO + co0 + acol) << 4) + (ky << 2) + kx]; \
            }                                                                    \
            _Pragma("unroll")                                                    \
            for (int i = 0; i < 4; i++) {                                        \
                int klocal = 2 * bhh + (i & 1) + ((i >> 1) << 2);                \
                int k = (k0v) + klocal;                                          \
                int ci = k >> 2, tt = k & 3;                                     \
                int iy = yb + ((tt & 2) ? dy1 : dy0);                            \
                int ix = xb + ((tt & 1) ? dx1 : dx0);                            \
                vB[i] = ((unsigned)iy < (unsigned)IH && (unsigned)ix < (unsigned)IW) \
                        ? Xn[(ci * IH + iy) * IW + ix] : 0.f;                    \
            }                                                                    \
        }

    #define STASH2(bufv)                                                         \
        {   uint32_t h0,l0,h1,l1,h2,l2,h3,l3;                                    \
            split_tf32(wA[0],h0,l0); split_tf32(wA[1],h1,l1);                    \
            split_tf32(wA[2],h2,l2); split_tf32(wA[3],h3,l3);                    \
            Aph[bufv][2*ahh+0][acol] = make_uint2(h0, h2);                       \
            Aph[bufv][2*ahh+1][acol] = make_uint2(h1, h3);                       \
            Apl[bufv][2*ahh+0][acol] = make_uint2(l0, l2);                       \
            Apl[bufv][2*ahh+1][acol] = make_uint2(l1, l3);                       \
            split_tf32(vB[0],h0,l0); split_tf32(vB[1],h1,l1);                    \
            split_tf32(vB[2],h2,l2); split_tf32(vB[3],h3,l3);                    \
            Bph[bufv][2*bhh+0][bpv] = make_uint2(h0, h2);                        \
            Bph[bufv][2*bhh+1][bpv] = make_uint2(h1, h3);                        \
            Bpl[bufv][2*bhh+0][bpv] = make_uint2(l0, l2);                        \
            Bpl[bufv][2*bhh+1][bpv] = make_uint2(l1, l3);                        \
        }

    GATHER_CT(0)
    STASH2(0)
    __syncthreads();

    for (int tile = 0; tile < NT; tile++) {
        const int cur = tile & 1;
        const bool more = (tile + 1 < NT);
        if (more) GATHER_CT((tile + 1) << 3)

        uint32_t ah[2][4], al[2][4];
        #pragma unroll
        for (int mt = 0; mt < 2; mt++) {
            int ca = wm * 32 + mt * 16 + lr;
            uint2 u0 = Aph[cur][kq][ca];
            uint2 u1 = Aph[cur][kq][ca + 8];
            ah[mt][0] = u0.x; ah[mt][1] = u1.x; ah[mt][2] = u0.y; ah[mt][3] = u1.y;
            uint2 v0 = Apl[cur][kq][ca];
            uint2 v1 = Apl[cur][kq][ca + 8];
            al[mt][0] = v0.x; al[mt][1] = v1.x; al[mt][2] = v0.y; al[mt][3] = v1.y;
        }
        #pragma unroll
        for (int nt = 0; nt < 8; nt++) {
            int pa = wn * 64 + nt * 8 + lr;
            uint2 bh = Bph[cur][kq][pa];
            uint2 bl = Bpl[cur][kq][pa];
            #pragma unroll
            for (int mt = 0; mt < 2; mt++) {
                mma_tf32(acc[mt][nt], ah[mt], bh.x, bh.y);
                mma_tf32(acc[mt][nt], ah[mt], bl.x, bl.y);
                mma_tf32(acc[mt][nt], al[mt], bh.x, bh.y);
            }
        }
        if (more) STASH2(cur ^ 1)
        __syncthreads();
    }

    const size_t ostride = (size_t)OH * OW;
    #pragma unroll
    for (int nt = 0; nt < 8; nt++) {
        #pragma unroll
        for (int e = 0; e < 2; e++) {
            int pp = pix0 + wn * 64 + nt * 8 + (kq << 1) + e;
            int n2 = pp / yhw, r2 = pp - n2 * yhw;
            int y2 = r2 / IW, x2 = r2 - y2 * IW;
            int oy = (y2 << 1) + py, ox = (x2 << 1) + px;
            #pragma unroll
            for (int mt = 0; mt < 2; mt++) {
                int c0r = co0 + wm * 32 + mt * 16 + lr;
                size_t idx = (((size_t)n2 * CO + c0r) * OH + oy) * OW + ox;
                Y[idx] = acc[mt][nt][e];
                Y[idx + 8 * ostride] = acc[mt][nt][2 + e];
            }
        }
    }
    #undef GATHER_CT
    #undef STASH2
}

// ---------------- d_t2 weight repack: Wp[py*2+px][ci][co][tap] ----------------
__global__ void pack_wt2(const float* __restrict__ W, float* __restrict__ Wp)
{
    int i = blockIdx.x * blockDim.x + threadIdx.x;
    if (i >= 12288) return;
    int tap = i & 3;
    int r = i >> 2;
    int co = r % 3;
    int r2 = r / 3;
    int ci = r2 & 255;
    int pp = r2 >> 8;
    int py = pp >> 1, px = pp & 1;
    int ky = ((tap >> 1) == 0) ? (1 - py) : (3 - py);
    int kx = ((tap & 1) == 0) ? (1 - px) : (3 - px);
    Wp[i] = W[((size_t)ci * 3 + co) * 16 + ky * 4 + kx];
}

// ---------------- direct ConvTranspose CO=3, packed weights, zero-fill taps ---
// Bit-identical to round-9 convt_direct: same tap order (ky asc, kx asc), OOB
// taps contribute fmaf(0,w,acc)=acc exactly.
__global__ void __launch_bounds__(256) convt_direct2(
    const float* __restrict__ Wp, const float* __restrict__ X, float* __restrict__ Y,
    int CI, int IH, int IW, int OH, int OW)
{
    int ox = threadIdx.x, oy = blockIdx.x, n = blockIdx.z;
    int py = oy & 1, px = ox & 1;
    int iyA = (oy + py) >> 1, iyB = iyA - 1;
    int ixA = (ox + px) >> 1, ixB = ixA - 1;
    bool vyA = (unsigned)iyA < (unsigned)IH, vyB = (unsigned)iyB < (unsigned)IH;
    bool vxA = (unsigned)ixA < (unsigned)IW, vxB = (unsigned)ixB < (unsigned)IW;
    const float* Xn = X + (size_t)n * CI * IH * IW;
    const float4* wp = (const float4*)(Wp + (size_t)(py * 2 + px) * 256 * 12);

    float a0 = 0.f, a1 = 0.f, a2 = 0.f;
    for (int ci = 0; ci < CI; ci++) {
        const float* xc = Xn + (size_t)ci * IH * IW;
        float x00 = (vyA && vxA) ? xc[iyA * IW + ixA] : 0.f;
        float x01 = (vyA && vxB) ? xc[iyA * IW + ixB] : 0.f;
        float x10 = (vyB && vxA) ? xc[iyB * IW + ixA] : 0.f;
        float x11 = (vyB && vxB) ? xc[iyB * IW + ixB] : 0.f;
        float4 w0 = wp[ci * 3 + 0];
        float4 w1 = wp[ci * 3 + 1];
        float4 w2 = wp[ci * 3 + 2];
        a0 = fmaf(x00, w0.x, a0); a0 = fmaf(x01, w0.y, a0);
        a0 = fmaf(x10, w0.z, a0); a0 = fmaf(x11, w0.w, a0);
        a1 = fmaf(x00, w1.x, a1); a1 = fmaf(x01, w1.y, a1);
        a1 = fmaf(x10, w1.z, a1); a1 = fmaf(x11, w1.w, a1);
        a2 = fmaf(x00, w2.x, a2); a2 = fmaf(x01, w2.y, a2);
        a2 = fmaf(x10, w2.z, a2); a2 = fmaf(x11, w2.w, a2);
    }
    size_t ohw = (size_t)OH * OW;
    size_t base = (size_t)n * 3 * ohw + (size_t)oy * OW + ox;
    Y[base] = a0;
    Y[base + ohw] = a1;
    Y[base + 2 * ohw] = a2;
}

// ---------------- BatchNorm stats: fp32 Kahan (FROZEN) ----------------
__global__ void bn_stats(const float* __restrict__ x, const float* __restrict__ r,
                         float* __restrict__ mean, float* __restrict__ istd,
                         int C, int HW, int Bn)
{
    int c = blockIdx.x;
    float s = 0.f, cs = 0.f, ss = 0.f, css = 0.f;
    for (int n = 0; n < Bn; n++) {
        const float* p = x + (size_t)(n * C + c) * HW;
        const float* q = r ? r + (size_t)(n * C + c) * HW : (const float*)0;
        for (int i = threadIdx.x; i < HW; i += blockDim.x) {
            float v = p[i];
            if (q) v = __fadd_rn(v, q[i]);
            float y1 = __fsub_rn(v, cs);
            float t1 = __fadd_rn(s, y1);
            cs = __fsub_rn(__fsub_rn(t1, s), y1); s = t1;
            float w = __fmul_rn(v, v);
            float y2 = __fsub_rn(w, css);
            float t2 = __fadd_rn(ss, y2);
            css = __fsub_rn(__fsub_rn(t2, ss), y2); ss = t2;
        }
    }
    s = __fsub_rn(s, cs); ss = __fsub_rn(ss, css);
    __shared__ float shs[32], shss[32];
    int lane = threadIdx.x & 31, wid = threadIdx.x >> 5;
    #pragma unroll
    for (int o = 16; o > 0; o >>= 1) {
        s  += __shfl_down_sync(0xffffffffu, s,  o);
        ss += __shfl_down_sync(0xffffffffu, ss, o);
    }
    if (lane == 0) { shs[wid] = s; shss[wid] = ss; }
    __syncthreads();
    if (threadIdx.x == 0) {
        int nw = blockDim.x >> 5;
        float ts = 0.f, tss = 0.f;
        for (int i = 0; i < nw; i++) { ts += shs[i]; tss += shss[i]; }
        float inv = 1.f / ((float)Bn * (float)HW);
        float m = ts * inv;
        float var = fmaxf(tss * inv - m * m, 0.f);
        mean[c] = m;
        istd[c] = rsqrtf(var + EPSBN);
    }
}

__global__ void bn_apply4(const float4* __restrict__ x, const float4* __restrict__ r,
                          float4* __restrict__ y,
                          const float* __restrict__ g, const float* __restrict__ b,
                          const float* __restrict__ mean, const float* __restrict__ istd,
                          int C, int hwshift4, int total4, int mode)
{
    int stride = gridDim.x * blockDim.x;
    for (int i = blockIdx.x * blockDim.x + threadIdx.x; i < total4; i += stride) {
        int c = (i >> hwshift4) % C;
        float4 v = x[i];
        if (r) {
            float4 rv = r[i];
            v.x = __fadd_rn(v.x, rv.x); v.y = __fadd_rn(v.y, rv.y);
            v.z = __fadd_rn(v.z, rv.z); v.w = __fadd_rn(v.w, rv.w);
        }
        float gc = g[c], bc = b[c], mc = mean[c], ic = istd[c];
        v.x = __fadd_rn(__fmul_rn(__fmul_rn(gc, __fsub_rn(v.x, mc)), ic), bc);
        v.y = __fadd_rn(__fmul_rn(__fmul_rn(gc, __fsub_rn(v.y, mc)), ic), bc);
        v.z = __fadd_rn(__fmul_rn(__fmul_rn(gc, __fsub_rn(v.z, mc)), ic), bc);
        v.w = __fadd_rn(__fmul_rn(__fmul_rn(gc, __fsub_rn(v.w, mc)), ic), bc);
        if (mode == 1) {
            v.x = fmaxf(v.x, 0.f); v.y = fmaxf(v.y, 0.f);
            v.z = fmaxf(v.z, 0.f); v.w = fmaxf(v.w, 0.f);
        } else if (mode == 2) {
            v.x = tanhf(v.x); v.y = tanhf(v.y);
            v.z = tanhf(v.z); v.w = tanhf(v.w);
        }
        y[i] = v;
    }
}

// ---------------- VQ (FROZEN: bit-exact path validated in round 4) ----------
__global__ void transpose_cb(const float* __restrict__ cb, float* __restrict__ cbT)
{
    int i = blockIdx.x * blockDim.x + threadIdx.x;
    int j = i >> 8, k = i & 255;
    cbT[k * 512 + j] = cb[i];
}

__global__ void cnorm_k(const float* __restrict__ cb, float* __restrict__ cn)
{
    int j = blockIdx.x * blockDim.x + threadIdx.x;
    if (j < 512) {
        float s = 0.f;
        const float* p = cb + j * 256;
        for (int c = 0; c < 256; c++) s = __fadd_rn(s, __fmul_rn(p[c], p[c]));
        cn[j] = s;
    }
}

__global__ void fnorm_k(const float* __restrict__ ze, float* __restrict__ fn, int HW)
{
    int w = (blockIdx.x * blockDim.x + threadIdx.x) >> 5;
    int lane = threadIdx.x & 31;
    int n = w / HW, hw = w - n * HW;
    const float* base = ze + (size_t)n * 256 * HW + hw;
    float s = 0.f;
    for (int k = lane; k < 256; k += 32) {
        float v = base[(size_t)k * HW];
        s = __fadd_rn(s, __fmul_rn(v, v));
    }
    #pragma unroll
    for (int o = 16; o > 0; o >>= 1) s += __shfl_down_sync(0xffffffffu, s, o);
    if (lane == 0) fn[w] = s;
}

#define VQ_KC 16
__global__ void __launch_bounds__(512) vq_dist_argmin(
    const float* __restrict__ ze, const float* __restrict__ cbT,
    const float* __restrict__ cn, const float* __restrict__ fnorm,
    int* __restrict__ idx, int HW)
{
    __shared__ float fs[64 * 17];
    __shared__ __align__(16) float cbs[VQ_KC * 512];
    __shared__ float cns[512];
    __shared__ float rd[64 * 8];
    __shared__ int   rj[64 * 8];

    const int t = threadIdx.x, px = t & 63, jg = t >> 6;
    const int p = blockIdx.x * 64 + px;
    cns[t] = cn[t];

    float acc[64];
    #pragma unroll
    for (int j = 0; j < 64; j++) acc[j] = 0.f;

    for (int k0 = 0; k0 < 256; k0 += VQ_KC) {
        __syncthreads();
        for (int i = t; i < 64 * VQ_KC; i += 512) {
            int kk = i >> 6, pp = i & 63;
            int gp = blockIdx.x * 64 + pp;
            int gn = gp / HW, ghw = gp - gn * HW;
            fs[pp * 17 + kk] = ze[((size_t)gn * 256 + (k0 + kk)) * HW + ghw];
        }
        for (int i = t; i < VQ_KC * 512; i += 512)
            cbs[i] = cbT[(size_t)(k0 + (i >> 9)) * 512 + (i & 511)];
        __syncthreads();

        float fv[VQ_KC];
        #pragma unroll
        for (int kk = 0; kk < VQ_KC; kk++) fv[kk] = fs[px * 17 + kk];

        #pragma unroll
        for (int j4 = 0; j4 < 16; j4++) {
            float a0, a1, a2, a3;
            {
                float4 c = *(const float4*)&cbs[jg * 64 + j4 * 4];
                a0 = __fmul_rn(fv[0], c.x); a1 = __fmul_rn(fv[0], c.y);
                a2 = __fmul_rn(fv[0], c.z); a3 = __fmul_rn(fv[0], c.w);
                #pragma unroll
                for (int kk = 1; kk < 8; kk++) {
                    float4 d = *(const float4*)&cbs[kk * 512 + jg * 64 + j4 * 4];
                    a0 = fmaf(fv[kk], d.x, a0); a1 = fmaf(fv[kk], d.y, a1);
                    a2 = fmaf(fv[kk], d.z, a2); a3 = fmaf(fv[kk], d.w, a3);
                }
                acc[j4*4+0] = __fadd_rn(acc[j4*4+0], a0);
                acc[j4*4+1] = __fadd_rn(acc[j4*4+1], a1);
                acc[j4*4+2] = __fadd_rn(acc[j4*4+2], a2);
                acc[j4*4+3] = __fadd_rn(acc[j4*4+3], a3);
            }
            {
                float4 c = *(const float4*)&cbs[8 * 512 + jg * 64 + j4 * 4];
                a0 = __fmul_rn(fv[8], c.x); a1 = __fmul_rn(fv[8], c.y);
                a2 = __fmul_rn(fv[8], c.z); a3 = __fmul_rn(fv[8], c.w);
                #pragma unroll
                for (int kk = 9; kk < 16; kk++) {
                    float4 d = *(const float4*)&cbs[kk * 512 + jg * 64 + j4 * 4];
                    a0 = fmaf(fv[kk], d.x, a0); a1 = fmaf(fv[kk], d.y, a1);
                    a2 = fmaf(fv[kk], d.z, a2); a3 = fmaf(fv[kk], d.w, a3);
                }
                acc[j4*4+0] = __fadd_rn(acc[j4*4+0], a0);
                acc[j4*4+1] = __fadd_rn(acc[j4*4+1], a1);
                acc[j4*4+2] = __fadd_rn(acc[j4*4+2], a2);
                acc[j4*4+3] = __fadd_rn(acc[j4*4+3], a3);
            }
        }
    }

    float S = fnorm[p];
    float best = 3.4028235e38f;
    int bj = 0;
    #pragma unroll
    for (int j = 0; j < 64; j++) {
        float q = __fsub_rn(S, __fmul_rn(2.0f, acc[j]));
        float dj = __fadd_rn(q, cns[jg * 64 + j]);
        if (dj < best) { best = dj; bj = jg * 64 + j; }
    }
    rd[px * 8 + jg] = best;
    rj[px * 8 + jg] = bj;
    __syncthreads();
    if (t < 64) {
        float bb = rd[t * 8]; int jj = rj[t * 8];
        #pragma unroll
        for (int gsel = 1; gsel < 8; gsel++) {
            float d2 = rd[t * 8 + gsel];
            if (d2 < bb) { bb = d2; jj = rj[t * 8 + gsel]; }
        }
        idx[blockIdx.x * 64 + t] = jj;
    }
}

__global__ void vq_gather(const int* __restrict__ idx, const float* __restrict__ cb,
                          float* __restrict__ zq, int HW, int total)
{
    int stride = gridDim.x * blockDim.x;
    for (int i = blockIdx.x * blockDim.x + threadIdx.x; i < total; i += stride) {
        int hw = i % HW, nc = i / HW, c = nc & 255, n = nc >> 8;
        zq[i] = cb[idx[n * HW + hw] * 256 + c];
    }
}

// ---------------- pipeline ----------------
extern "C" void kernel_launch(void* const* d_in, const int* in_sizes, int n_in,
                              void* d_out, int out_size)
{
    const float* img  = (const float*)d_in[0];
    const float* e_w1 = (const float*)d_in[1];
    const float* e_g1 = (const float*)d_in[2];
    const float* e_b1 = (const float*)d_in[3];
    const float* e_w2 = (const float*)d_in[4];
    const float* e_g2 = (const float*)d_in[5];
    const float* e_b2 = (const float*)d_in[6];
    const float* e_w3 = (const float*)d_in[7];
    const float* e_g3 = (const float*)d_in[8];
    const float* e_b3 = (const float*)d_in[9];
    const float* e_w4 = (const float*)d_in[10];
    const float* e_g4 = (const float*)d_in[12];
    const float* e_b4 = (const float*)d_in[13];
    const float* e_g5 = (const float*)d_in[14];
    const float* e_b5 = (const float*)d_in[15];
    const float* cb   = (const float*)d_in[16];
    const float* dw1  = (const float*)d_in[17];
    const float* dg1  = (const float*)d_in[18];
    const float* db1  = (const float*)d_in[19];
    const float* dw2  = (const float*)d_in[20];
    const float* dg2  = (const float*)d_in[21];
    const float* db2  = (const float*)d_in[22];
    const float* dg3  = (const float*)d_in[23];
    const float* db3  = (const float*)d_in[24];
    const float* dt1  = (const float*)d_in[25];
    const float* dg4  = (const float*)d_in[26];
    const float* db4  = (const float*)d_in[27];
    const float* dt2  = (const float*)d_in[28];
    const float* dg5  = (const float*)d_in[30];
    const float* db5  = (const float*)d_in[31];
    float* out = (float*)d_out;

    float *buf128, *b64a, *b64b, *b64c, *mean, *istd, *cnorm, *fnorm, *cbT, *wp;
    int* idx;
    cudaGetSymbolAddress((void**)&buf128, g_buf128);
    cudaGetSymbolAddress((void**)&b64a,   g_b64a);
    cudaGetSymbolAddress((void**)&b64b,   g_b64b);
    cudaGetSymbolAddress((void**)&b64c,   g_b64c);
    cudaGetSymbolAddress((void**)&mean,   g_mean);
    cudaGetSymbolAddress((void**)&istd,   g_istd);
    cudaGetSymbolAddress((void**)&cnorm,  g_cnorm);
    cudaGetSymbolAddress((void**)&fnorm,  g_fnorm);
    cudaGetSymbolAddress((void**)&cbT,    g_cbT);
    cudaGetSymbolAddress((void**)&wp,     g_wp);
    cudaGetSymbolAddress((void**)&idx,    g_idx);

    const int T128 = 33554432, T64 = 8388608;
    const int Q128 = T128 / 4, Q64 = T64 / 4;
    #define F4(p) ((float4*)(p))
    #define CF4(p) ((const float4*)(p))

    // independent prep
    pack_wt2<<<48, 256>>>(dt2, wp);
    transpose_cb<<<512, 256>>>(cb, cbT);
    cnorm_k<<<2, 256>>>(cb, cnorm);

    // ---- encoder (fp32 SIMT, numerics FROZEN) ----
    conv_gemm_t<16,4,2,1><<<dim3(1024, 2), 256>>>(e_w1, img, buf128, 256, 3, 256, 256, 128, 128);
    bn_stats<<<256, 256>>>(buf128, (const float*)0, mean, istd, 256, 16384, 8);
    bn_apply4<<<8192, 256>>>(CF4(buf128), (const float4*)0, F4(buf128), e_g1, e_b1, mean, istd, 256, 12, Q128, 1);

    conv_gemm_t<16,4,2,1><<<dim3(256, 2), 256>>>(e_w2, buf128, b64a, 256, 256, 128, 128, 64, 64);
    bn_stats<<<256, 256>>>(b64a, (const float*)0, mean, istd, 256, 4096, 8);
    bn_apply4<<<4096, 256>>>(CF4(b64a), (const float4*)0, F4(b64a), e_g2, e_b2, mean, istd, 256, 10, Q64, 1);

    conv_gemm_t<9,3,1,1><<<dim3(256, 2), 256>>>(e_w3, b64a, b64b, 256, 256, 64, 64, 64, 64);
    bn_stats<<<256, 256>>>(b64b, (const float*)0, mean, istd, 256, 4096, 8);
    bn_apply4<<<4096, 256>>>(CF4(b64b), (const float4*)0, F4(b64b), e_g3, e_b3, mean, istd, 256, 10, Q64, 1);

    conv_gemm_t<1,1,1,0><<<dim3(256, 2), 256>>>(e_w4, b64b, b64c, 256, 256, 64, 64, 64, 64);
    bn_stats<<<256, 256>>>(b64c, (const float*)0, mean, istd, 256, 4096, 8);
    bn_apply4<<<4096, 256>>>(CF4(b64c), (const float4*)0, F4(b64c), e_g4, e_b4, mean, istd, 256, 10, Q64, 1);

    bn_stats<<<256, 256>>>(b64a, b64c, mean, istd, 256, 4096, 8);
    bn_apply4<<<4096, 256>>>(CF4(b64a), CF4(b64c), F4(b64b), e_g5, e_b5, mean, istd, 256, 10, Q64, 0);

    // ---- VQ (frozen) ----
    fnorm_k<<<4096, 256>>>(b64b, fnorm, 4096);
    vq_dist_argmin<<<512, 512>>>(b64b, cbT, cnorm, fnorm, idx, 4096);
    vq_gather<<<8192, 256>>>(idx, cb, b64c, 4096, T64);

    // ---- decoder (3-pass split-TF32 tensor cores, tolerance path) ----
    conv_mma_t<9,3,1><<<dim3(256, 2), 256>>>(dw1, b64c, b64a, 256, 256, 64, 64, 64, 64);
    bn_stats<<<256, 256>>>(b64a, (const float*)0, mean, istd, 256, 4096, 8);
    bn_apply4<<<4096, 256>>>(CF4(b64a), (const float4*)0, F4(b64a), dg1, db1, mean, istd, 256, 10, Q64, 1);

    conv_mma_t<1,1,0><<<dim3(256, 2), 256>>>(dw2, b64a, b64b, 256, 256, 64, 64, 64, 64);
    bn_stats<<<256, 256>>>(b64b, (const float*)0, mean, istd, 256, 4096, 8);
    bn_apply4<<<4096, 256>>>(CF4(b64b), (const float4*)0, F4(b64b), dg2, db2, mean, istd, 256, 10, Q64, 1);

    bn_stats<<<256, 256>>>(b64c, b64b, mean, istd, 256, 4096, 8);
    bn_apply4<<<4096, 256>>>(CF4(b64c), CF4(b64b), F4(b64a), dg3, db3, mean, istd, 256, 10, Q64, 1);

    convt_mma<<<dim3(256, 2, 4), 256>>>(dt1, b64a, buf128, 256, 256, 64, 64, 128, 128);
    bn_stats<<<256, 256>>>(buf128, (const float*)0, mean, istd, 256, 16384, 8);
    bn_apply4<<<8192, 256>>>(CF4(buf128), (const float4*)0, F4(buf128), dg4, db4, mean, istd, 256, 12, Q128, 1);

    convt_direct2<<<dim3(256, 1, 8), 256>>>(wp, buf128, out, 256, 128, 128, 256, 256);
    bn_stats<<<3, 256>>>(out, (const float*)0, mean, istd, 3, 65536, 8);
    bn_apply4<<<384, 256>>>(CF4(out), (const float4*)0, F4(out), dg5, db5, mean, istd, 3, 14, 393216, 2);
}

// round 14
// speedup vs baseline: 1.1467x; 1.0977x over previous
#include <cuda_runtime.h>
#include <math.h>
#include <stdint.h>

#define EPSBN 1e-5f

__device__ float g_buf128[33554432];
__device__ float g_b64a[8388608];
__device__ float g_b64b[8388608];
__device__ float g_b64c[8388608];
__device__ float g_mean[256];
__device__ float g_istd[256];
__device__ float g_cnorm[512];
__device__ float g_fnorm[32768];
__device__ float g_cbT[131072];
__device__ float g_wp[12288];
__device__ float2 g_part[2048];
__device__ int   g_idx[32768];

// ---------------- tf32 helpers (decoder tolerance path only) ----------------
__device__ __forceinline__ uint32_t f2tf32(float x) {
    uint32_t r;
    asm("cvt.rna.tf32.f32 %0, %1;" : "=r"(r) : "f"(x));
    return r;
}
__device__ __forceinline__ void split_tf32(float x, uint32_t& h, uint32_t& l) {
    h = f2tf32(x);
    l = f2tf32(x - __uint_as_float(h));
}
__device__ __forceinline__ void mma_tf32(float* c, const uint32_t* a, uint32_t b0, uint32_t b1) {
    asm volatile(
        "mma.sync.aligned.m16n8k8.row.col.f32.tf32.tf32.f32 "
        "{%0,%1,%2,%3}, {%4,%5,%6,%7}, {%8,%9}, {%0,%1,%2,%3};\n"
        : "+f"(c[0]), "+f"(c[1]), "+f"(c[2]), "+f"(c[3])
        : "r"(a[0]), "r"(a[1]), "r"(a[2]), "r"(a[3]), "r"(b0), "r"(b1));
}

// ---------------- ENCODER conv: 128x128x8 fp32 SIMT (numerics FROZEN) --------
// Arithmetic bit-identical to rounds 4-13 (folds every 64 k). ONLY the output
// stores are vectorized to float4 (same values, same addresses).
template<int KHW, int KW, int STRIDE, int PAD>
__global__ void __launch_bounds__(256, 2) conv_gemm_t(
    const float* __restrict__ W, const float* __restrict__ X, float* __restrict__ Y,
    int CO, int CI, int IH, int IW, int OH, int OW)
{
    const int Ktot = CI * KHW;
    __shared__ __align__(16) float As[8][128];
    __shared__ __align__(16) float Bs[8][128];
    const int t = threadIdx.x;
    const int pix0 = blockIdx.x * 128, co0 = blockIdx.y * 128;
    const int ohw = OH * OW;

    const int acol = t >> 1;
    const int akq  = (t & 1) << 2;
    const float* Wrow = W + (size_t)(co0 + acol) * Ktot + akq;

    const int bpv = t & 127;
    const int bkq = (t >> 7) << 2;
    const int pixb = pix0 + bpv;
    const int nb = pixb / ohw, remb = pixb - nb * ohw;
    const int oyb = remb / OW, oxb = remb - oyb * OW;
    const int iy0 = oyb * STRIDE - PAD, ix0 = oxb * STRIDE - PAD;
    const float* Xn = X + (size_t)nb * CI * IH * IW;

    const int tx = t & 15, ty = t >> 4;
    float acc[8][8] = {};
    float tot[8][8] = {};
    int nch = 0;

    for (int k0 = 0; k0 < Ktot; k0 += 8) {
        float4 wv = *(const float4*)(Wrow + k0);
        float bval[4];
        #pragma unroll
        for (int i = 0; i < 4; i++) {
            int k = k0 + bkq + i;
            int ci = k / KHW;
            int kr = k - ci * KHW;
            int ky = kr / KW;
            int kx = kr - ky * KW;
            int iy = iy0 + ky, ix = ix0 + kx;
            float v = 0.f;
            if ((unsigned)iy < (unsigned)IH && (unsigned)ix < (unsigned)IW)
                v = Xn[(ci * IH + iy) * IW + ix];
            bval[i] = v;
        }
        As[akq + 0][acol] = wv.x;
        As[akq + 1][acol] = wv.y;
        As[akq + 2][acol] = wv.z;
        As[akq + 3][acol] = wv.w;
        #pragma unroll
        for (int i = 0; i < 4; i++) Bs[bkq + i][bpv] = bval[i];
        __syncthreads();
        #pragma unroll
        for (int kk = 0; kk < 8; kk++) {
            float4 a0 = *(const float4*)&As[kk][ty << 2];
            float4 a1 = *(const float4*)&As[kk][64 + (ty << 2)];
            float4 b0 = *(const float4*)&Bs[kk][tx << 2];
            float4 b1 = *(const float4*)&Bs[kk][64 + (tx << 2)];
            float av[8] = {a0.x, a0.y, a0.z, a0.w, a1.x, a1.y, a1.z, a1.w};
            float bv[8] = {b0.x, b0.y, b0.z, b0.w, b1.x, b1.y, b1.z, b1.w};
            #pragma unroll
            for (int i = 0; i < 8; i++)
                #pragma unroll
                for (int j = 0; j < 8; j++)
                    acc[i][j] = fmaf(av[i], bv[j], acc[i][j]);
        }
        __syncthreads();
        if (++nch == 8) {
            nch = 0;
            #pragma unroll
            for (int i = 0; i < 8; i++)
                #pragma unroll
                for (int j = 0; j < 8; j++) {
                    tot[i][j] = __fadd_rn(tot[i][j], acc[i][j]);
                    acc[i][j] = 0.f;
                }
        }
    }
    #pragma unroll
    for (int i = 0; i < 8; i++)
        #pragma unroll
        for (int j = 0; j < 8; j++) tot[i][j] = __fadd_rn(tot[i][j], acc[i][j]);

    // vectorized epilogue: 4 consecutive pixels per float4 (same row, aligned)
    #pragma unroll
    for (int jq = 0; jq < 2; jq++) {
        int p0 = pix0 + (jq ? 64 : 0) + (tx << 2);
        int n2 = p0 / ohw, r2 = p0 - n2 * ohw;
        int oy2 = r2 / OW, ox2 = r2 - oy2 * OW;
        size_t base = (size_t)n2 * CO * ohw + (size_t)oy2 * OW + ox2;
        #pragma unroll
        for (int i = 0; i < 8; i++) {
            int co = co0 + ((i < 4) ? (ty << 2) + i : 64 + (ty << 2) + (i - 4));
            float4 v = make_float4(tot[i][jq * 4 + 0], tot[i][jq * 4 + 1],
                                   tot[i][jq * 4 + 2], tot[i][jq * 4 + 3]);
            *(float4*)&Y[base + (size_t)co * ohw] = v;
        }
    }
}

// ---------------- DECODER conv: 128x128x8 3xTF32 MMA, db + uint2-paired smem --
template<int KHW, int KW, int PAD>
__global__ void __launch_bounds__(256, 2) conv_mma_t(
    const float* __restrict__ W, const float* __restrict__ X, float* __restrict__ Y,
    int CO, int CI, int IH, int IW, int OH, int OW)
{
    const int Ktot = CI * KHW;
    const int NT = Ktot >> 3;
    __shared__ uint2 Aph[2][4][140], Apl[2][4][140], Bph[2][4][140], Bpl[2][4][140];
    const int t = threadIdx.x;
    const int pix0 = blockIdx.x * 128, co0 = blockIdx.y * 128;
    const int ohw = OH * OW;

    const int acol = t >> 1, ahh = t & 1;
    const float* Wrow = W + (size_t)(co0 + acol) * Ktot;

    const int bpv = t & 127, bhh = t >> 7;
    const int pixb = pix0 + bpv;
    const int nb = pixb / ohw, remb = pixb - nb * ohw;
    const int oyb = remb / OW, oxb = remb - oyb * OW;
    const int iy0 = oyb - PAD, ix0 = oxb - PAD;
    const float* Xn = X + (size_t)nb * CI * IH * IW;

    const int warp = t >> 5, lane = t & 31;
    const int wm = warp >> 1, wn = warp & 1;
    const int kq = lane & 3, lr = lane >> 2;

    float acc[2][8][4];
    #pragma unroll
    for (int a = 0; a < 2; a++)
        #pragma unroll
        for (int b = 0; b < 8; b++)
            #pragma unroll
            for (int c = 0; c < 4; c++) acc[a][b][c] = 0.f;

    float wA[4], vB[4];

    #define GATHER_CONV(k0v)                                                     \
        {   float2 w01 = *(const float2*)(Wrow + (k0v) + 2 * ahh);               \
            float2 w45 = *(const float2*)(Wrow + (k0v) + 2 * ahh + 4);           \
            wA[0] = w01.x; wA[1] = w01.y; wA[2] = w45.x; wA[3] = w45.y;          \
            _Pragma("unroll")                                                    \
            for (int i = 0; i < 4; i++) {                                        \
                int klocal = 2 * bhh + (i & 1) + ((i >> 1) << 2);                \
                int k = (k0v) + klocal;                                          \
                int ci = k / KHW;                                                \
                int kr = k - ci * KHW;                                           \
                int ky = kr / KW;                                                \
                int kx = kr - ky * KW;                                           \
                int iy = iy0 + ky, ix = ix0 + kx;                                \
                float v = 0.f;                                                   \
                if ((unsigned)iy < (unsigned)IH && (unsigned)ix < (unsigned)IW)  \
                    v = Xn[(ci * IH + iy) * IW + ix];                            \
                vB[i] = v;                                                       \
            }                                                                    \
        }

    #define STASH(bufv)                                                          \
        {   uint32_t h0,l0,h1,l1,h2,l2,h3,l3;                                    \
            split_tf32(wA[0],h0,l0); split_tf32(wA[1],h1,l1);                    \
            split_tf32(wA[2],h2,l2); split_tf32(wA[3],h3,l3);                    \
            Aph[bufv][2*ahh+0][acol] = make_uint2(h0, h2);                       \
            Aph[bufv][2*ahh+1][acol] = make_uint2(h1, h3);                       \
            Apl[bufv][2*ahh+0][acol] = make_uint2(l0, l2);                       \
            Apl[bufv][2*ahh+1][acol] = make_uint2(l1, l3);                       \
            split_tf32(vB[0],h0,l0); split_tf32(vB[1],h1,l1);                    \
            split_tf32(vB[2],h2,l2); split_tf32(vB[3],h3,l3);                    \
            Bph[bufv][2*bhh+0][bpv] = make_uint2(h0, h2);                        \
            Bph[bufv][2*bhh+1][bpv] = make_uint2(h1, h3);                        \
            Bpl[bufv][2*bhh+0][bpv] = make_uint2(l0, l2);                        \
            Bpl[bufv][2*bhh+1][bpv] = make_uint2(l1, l3);                        \
        }

    GATHER_CONV(0)
    STASH(0)
    __syncthreads();

    for (int tile = 0; tile < NT; tile++) {
        const int cur = tile & 1;
        const bool more = (tile + 1 < NT);
        if (more) GATHER_CONV((tile + 1) << 3)

        uint32_t ah[2][4], al[2][4];
        #pragma unroll
        for (int mt = 0; mt < 2; mt++) {
            int ca = wm * 32 + mt * 16 + lr;
            uint2 u0 = Aph[cur][kq][ca];
            uint2 u1 = Aph[cur][kq][ca + 8];
            ah[mt][0] = u0.x; ah[mt][1] = u1.x; ah[mt][2] = u0.y; ah[mt][3] = u1.y;
            uint2 v0 = Apl[cur][kq][ca];
            uint2 v1 = Apl[cur][kq][ca + 8];
            al[mt][0] = v0.x; al[mt][1] = v1.x; al[mt][2] = v0.y; al[mt][3] = v1.y;
        }
        #pragma unroll
        for (int nt = 0; nt < 8; nt++) {
            int pa = wn * 64 + nt * 8 + lr;
            uint2 bh = Bph[cur][kq][pa];
            uint2 bl = Bpl[cur][kq][pa];
            #pragma unroll
            for (int mt = 0; mt < 2; mt++) {
                mma_tf32(acc[mt][nt], ah[mt], bh.x, bh.y);
                mma_tf32(acc[mt][nt], ah[mt], bl.x, bl.y);
                mma_tf32(acc[mt][nt], al[mt], bh.x, bh.y);
            }
        }
        if (more) STASH(cur ^ 1)
        __syncthreads();
    }

    #pragma unroll
    for (int nt = 0; nt < 8; nt++) {
        int p = pix0 + wn * 64 + nt * 8 + (kq << 1);
        int n2 = p / ohw, r2 = p - n2 * ohw;
        int oy2 = r2 / OW, ox2 = r2 - oy2 * OW;
        size_t rowbase = (size_t)n2 * CO * ohw + (size_t)oy2 * OW + ox2;
        #pragma unroll
        for (int mt = 0; mt < 2; mt++) {
            int c0r = co0 + wm * 32 + mt * 16 + lr;
            float2 v0 = make_float2(acc[mt][nt][0], acc[mt][nt][1]);
            float2 v1 = make_float2(acc[mt][nt][2], acc[mt][nt][3]);
            *(float2*)&Y[rowbase + (size_t)c0r * ohw] = v0;
            *(float2*)&Y[rowbase + (size_t)(c0r + 8) * ohw] = v1;
        }
    }
    #undef GATHER_CONV
    #undef STASH
}

// ---------------- DECODER convT(k=4,s=2,p=1): parity-split 3xTF32 MMA, db -----
__global__ void __launch_bounds__(256, 2) convt_mma(
    const float* __restrict__ W, const float* __restrict__ X, float* __restrict__ Y,
    int CO, int CI, int IH, int IW, int OH, int OW)
{
    const int py = (blockIdx.z >> 1) & 1, px = blockIdx.z & 1;
    const int ky0 = 1 - py, ky1 = 3 - py, dy0 = py, dy1 = py - 1;
    const int kx0 = 1 - px, kx1 = 3 - px, dx0 = px, dx1 = px - 1;
    const int Ktot = CI * 4;
    const int NT = Ktot >> 3;
    __shared__ uint2 Aph[2][4][140], Apl[2][4][140], Bph[2][4][140], Bpl[2][4][140];
    const int t = threadIdx.x;
    const int pix0 = blockIdx.x * 128, co0 = blockIdx.y * 128;
    const int yhw = IH * IW;

    const int acol = t >> 1, ahh = t & 1;
    const int bpv = t & 127, bhh = t >> 7;
    const int pixb = pix0 + bpv;
    const int nb = pixb / yhw, remb = pixb - nb * yhw;
    const int yb = remb / IW, xb = remb - yb * IW;
    const float* Xn = X + (size_t)nb * CI * yhw;

    const int warp = t >> 5, lane = t & 31;
    const int wm = warp >> 1, wn = warp & 1;
    const int kq = lane & 3, lr = lane >> 2;

    float acc[2][8][4];
    #pragma unroll
    for (int a = 0; a < 2; a++)
        #pragma unroll
        for (int b = 0; b < 8; b++)
            #pragma unroll
            for (int c = 0; c < 4; c++) acc[a][b][c] = 0.f;

    float wA[4], vB[4];

    #define GATHER_CT(k0v)                                                       \
        {   _Pragma("unroll")                                                    \
            for (int i = 0; i < 4; i++) {                                        \
                int klocal = 2 * ahh + (i & 1) + ((i >> 1) << 2);                \
                int k = (k0v) + klocal;                                          \
                int ci = k >> 2, tt = k & 3;                                     \
                int ky = (tt & 2) ? ky1 : ky0;                                   \
                int kx = (tt & 1) ? kx1 : kx0;                                   \
                wA[i] = W[(((size_t)ci * CO + co0 + acol) << 4) + (ky << 2) + kx]; \
            }                                                                    \
            _Pragma("unroll")                                                    \
            for (int i = 0; i < 4; i++) {                                        \
                int klocal = 2 * bhh + (i & 1) + ((i >> 1) << 2);                \
                int k = (k0v) + klocal;                                          \
                int ci = k >> 2, tt = k & 3;                                     \
                int iy = yb + ((tt & 2) ? dy1 : dy0);                            \
                int ix = xb + ((tt & 1) ? dx1 : dx0);                            \
                vB[i] = ((unsigned)iy < (unsigned)IH && (unsigned)ix < (unsigned)IW) \
                        ? Xn[(ci * IH + iy) * IW + ix] : 0.f;                    \
            }                                                                    \
        }

    #define STASH2(bufv)                                                         \
        {   uint32_t h0,l0,h1,l1,h2,l2,h3,l3;                                    \
            split_tf32(wA[0],h0,l0); split_tf32(wA[1],h1,l1);                    \
            split_tf32(wA[2],h2,l2); split_tf32(wA[3],h3,l3);                    \
            Aph[bufv][2*ahh+0][acol] = make_uint2(h0, h2);                       \
            Aph[bufv][2*ahh+1][acol] = make_uint2(h1, h3);                       \
            Apl[bufv][2*ahh+0][acol] = make_uint2(l0, l2);                       \
            Apl[bufv][2*ahh+1][acol] = make_uint2(l1, l3);                       \
            split_tf32(vB[0],h0,l0); split_tf32(vB[1],h1,l1);                    \
            split_tf32(vB[2],h2,l2); split_tf32(vB[3],h3,l3);                    \
            Bph[bufv][2*bhh+0][bpv] = make_uint2(h0, h2);                        \
            Bph[bufv][2*bhh+1][bpv] = make_uint2(h1, h3);                        \
            Bpl[bufv][2*bhh+0][bpv] = make_uint2(l0, l2);                        \
            Bpl[bufv][2*bhh+1][bpv] = make_uint2(l1, l3);                        \
        }

    GATHER_CT(0)
    STASH2(0)
    __syncthreads();

    for (int tile = 0; tile < NT; tile++) {
        const int cur = tile & 1;
        const bool more = (tile + 1 < NT);
        if (more) GATHER_CT((tile + 1) << 3)

        uint32_t ah[2][4], al[2][4];
        #pragma unroll
        for (int mt = 0; mt < 2; mt++) {
            int ca = wm * 32 + mt * 16 + lr;
            uint2 u0 = Aph[cur][kq][ca];
            uint2 u1 = Aph[cur][kq][ca + 8];
            ah[mt][0] = u0.x; ah[mt][1] = u1.x; ah[mt][2] = u0.y; ah[mt][3] = u1.y;
            uint2 v0 = Apl[cur][kq][ca];
            uint2 v1 = Apl[cur][kq][ca + 8];
            al[mt][0] = v0.x; al[mt][1] = v1.x; al[mt][2] = v0.y; al[mt][3] = v1.y;
        }
        #pragma unroll
        for (int nt = 0; nt < 8; nt++) {
            int pa = wn * 64 + nt * 8 + lr;
            uint2 bh = Bph[cur][kq][pa];
            uint2 bl = Bpl[cur][kq][pa];
            #pragma unroll
            for (int mt = 0; mt < 2; mt++) {
                mma_tf32(acc[mt][nt], ah[mt], bh.x, bh.y);
                mma_tf32(acc[mt][nt], ah[mt], bl.x, bl.y);
                mma_tf32(acc[mt][nt], al[mt], bh.x, bh.y);
            }
        }
        if (more) STASH2(cur ^ 1)
        __syncthreads();
    }

    const size_t ostride = (size_t)OH * OW;
    #pragma unroll
    for (int nt = 0; nt < 8; nt++) {
        #pragma unroll
        for (int e = 0; e < 2; e++) {
            int pp = pix0 + wn * 64 + nt * 8 + (kq << 1) + e;
            int n2 = pp / yhw, r2 = pp - n2 * yhw;
            int y2 = r2 / IW, x2 = r2 - y2 * IW;
            int oy = (y2 << 1) + py, ox = (x2 << 1) + px;
            #pragma unroll
            for (int mt = 0; mt < 2; mt++) {
                int c0r = co0 + wm * 32 + mt * 16 + lr;
                size_t idx = (((size_t)n2 * CO + c0r) * OH + oy) * OW + ox;
                Y[idx] = acc[mt][nt][e];
                Y[idx + 8 * ostride] = acc[mt][nt][2 + e];
            }
        }
    }
    #undef GATHER_CT
    #undef STASH2
}

// ---------------- d_t2 weight repack + packed direct convT ----------------
__global__ void pack_wt2(const float* __restrict__ W, float* __restrict__ Wp)
{
    int i = blockIdx.x * blockDim.x + threadIdx.x;
    if (i >= 12288) return;
    int tap = i & 3;
    int r = i >> 2;
    int co = r % 3;
    int r2 = r / 3;
    int ci = r2 & 255;
    int pp = r2 >> 8;
    int py = pp >> 1, px = pp & 1;
    int ky = ((tap >> 1) == 0) ? (1 - py) : (3 - py);
    int kx = ((tap & 1) == 0) ? (1 - px) : (3 - px);
    Wp[i] = W[((size_t)ci * 3 + co) * 16 + ky * 4 + kx];
}

__global__ void __launch_bounds__(256) convt_direct2(
    const float* __restrict__ Wp, const float* __restrict__ X, float* __restrict__ Y,
    int CI, int IH, int IW, int OH, int OW)
{
    int ox = threadIdx.x, oy = blockIdx.x, n = blockIdx.z;
    int py = oy & 1, px = ox & 1;
    int iyA = (oy + py) >> 1, iyB = iyA - 1;
    int ixA = (ox + px) >> 1, ixB = ixA - 1;
    bool vyA = (unsigned)iyA < (unsigned)IH, vyB = (unsigned)iyB < (unsigned)IH;
    bool vxA = (unsigned)ixA < (unsigned)IW, vxB = (unsigned)ixB < (unsigned)IW;
    const float* Xn = X + (size_t)n * CI * IH * IW;
    const float4* wp = (const float4*)(Wp + (size_t)(py * 2 + px) * 256 * 12);

    float a0 = 0.f, a1 = 0.f, a2 = 0.f;
    for (int ci = 0; ci < CI; ci++) {
        const float* xc = Xn + (size_t)ci * IH * IW;
        float x00 = (vyA && vxA) ? xc[iyA * IW + ixA] : 0.f;
        float x01 = (vyA && vxB) ? xc[iyA * IW + ixB] : 0.f;
        float x10 = (vyB && vxA) ? xc[iyB * IW + ixA] : 0.f;
        float x11 = (vyB && vxB) ? xc[iyB * IW + ixB] : 0.f;
        float4 w0 = wp[ci * 3 + 0];
        float4 w1 = wp[ci * 3 + 1];
        float4 w2 = wp[ci * 3 + 2];
        a0 = fmaf(x00, w0.x, a0); a0 = fmaf(x01, w0.y, a0);
        a0 = fmaf(x10, w0.z, a0); a0 = fmaf(x11, w0.w, a0);
        a1 = fmaf(x00, w1.x, a1); a1 = fmaf(x01, w1.y, a1);
        a1 = fmaf(x10, w1.z, a1); a1 = fmaf(x11, w1.w, a1);
        a2 = fmaf(x00, w2.x, a2); a2 = fmaf(x01, w2.y, a2);
        a2 = fmaf(x10, w2.z, a2); a2 = fmaf(x11, w2.w, a2);
    }
    size_t ohw = (size_t)OH * OW;
    size_t base = (size_t)n * 3 * ohw + (size_t)oy * OW + ox;
    Y[base] = a0;
    Y[base + ohw] = a1;
    Y[base + 2 * ohw] = a2;
}

// ---------------- BatchNorm stats: single-phase fp32 Kahan (ENCODER, FROZEN) --
__global__ void bn_stats(const float* __restrict__ x, const float* __restrict__ r,
                         float* __restrict__ mean, float* __restrict__ istd,
                         int C, int HW, int Bn)
{
    int c = blockIdx.x;
    float s = 0.f, cs = 0.f, ss = 0.f, css = 0.f;
    for (int n = 0; n < Bn; n++) {
        const float* p = x + (size_t)(n * C + c) * HW;
        const float* q = r ? r + (size_t)(n * C + c) * HW : (const float*)0;
        for (int i = threadIdx.x; i < HW; i += blockDim.x) {
            float v = p[i];
            if (q) v = __fadd_rn(v, q[i]);
            float y1 = __fsub_rn(v, cs);
            float t1 = __fadd_rn(s, y1);
            cs = __fsub_rn(__fsub_rn(t1, s), y1); s = t1;
            float w = __fmul_rn(v, v);
            float y2 = __fsub_rn(w, css);
            float t2 = __fadd_rn(ss, y2);
            css = __fsub_rn(__fsub_rn(t2, ss), y2); ss = t2;
        }
    }
    s = __fsub_rn(s, cs); ss = __fsub_rn(ss, css);
    __shared__ float shs[32], shss[32];
    int lane = threadIdx.x & 31, wid = threadIdx.x >> 5;
    #pragma unroll
    for (int o = 16; o > 0; o >>= 1) {
        s  += __shfl_down_sync(0xffffffffu, s,  o);
        ss += __shfl_down_sync(0xffffffffu, ss, o);
    }
    if (lane == 0) { shs[wid] = s; shss[wid] = ss; }
    __syncthreads();
    if (threadIdx.x == 0) {
        int nw = blockDim.x >> 5;
        float ts = 0.f, tss = 0.f;
        for (int i = 0; i < nw; i++) { ts += shs[i]; tss += shss[i]; }
        float inv = 1.f / ((float)Bn * (float)HW);
        float m = ts * inv;
        float var = fmaxf(tss * inv - m * m, 0.f);
        mean[c] = m;
        istd[c] = rsqrtf(var + EPSBN);
    }
}

// ---------------- Two-phase parallel stats (DECODER tolerance path) ----------
// Deterministic: fixed slice partition + fixed ascending-slice combine.
#define NSL 8
__global__ void bn_stats_part(const float* __restrict__ x, const float* __restrict__ r,
                              float2* __restrict__ part, int C, int HW, int Bn)
{
    int c = blockIdx.x, sl = blockIdx.y;
    int chunk = HW / NSL;
    int i0 = sl * chunk;
    float s = 0.f, ss = 0.f;
    for (int n = 0; n < Bn; n++) {
        const float* p = x + (size_t)(n * C + c) * HW;
        const float* q = r ? r + (size_t)(n * C + c) * HW : (const float*)0;
        for (int i = i0 + threadIdx.x; i < i0 + chunk; i += blockDim.x) {
            float v = p[i];
            if (q) v += q[i];
            s += v; ss += v * v;
        }
    }
    __shared__ float shs[32], shss[32];
    int lane = threadIdx.x & 31, wid = threadIdx.x >> 5;
    #pragma unroll
    for (int o = 16; o > 0; o >>= 1) {
        s  += __shfl_down_sync(0xffffffffu, s,  o);
        ss += __shfl_down_sync(0xffffffffu, ss, o);
    }
    if (lane == 0) { shs[wid] = s; shss[wid] = ss; }
    __syncthreads();
    if (threadIdx.x == 0) {
        int nw = blockDim.x >> 5;
        float ts = 0.f, tss = 0.f;
        for (int i = 0; i < nw; i++) { ts += shs[i]; tss += shss[i]; }
        part[c * NSL + sl] = make_float2(ts, tss);
    }
}

__global__ void bn_stats_comb(const float2* __restrict__ part,
                              float* __restrict__ mean, float* __restrict__ istd,
                              int C, float inv)
{
    int c = blockIdx.x * blockDim.x + threadIdx.x;
    if (c >= C) return;
    float ts = 0.f, tss = 0.f;
    for (int sl = 0; sl < NSL; sl++) {
        float2 v = part[c * NSL + sl];
        ts += v.x; tss += v.y;
    }
    float m = ts * inv;
    float var = fmaxf(tss * inv - m * m, 0.f);
    mean[c] = m;
    istd[c] = rsqrtf(var + EPSBN);
}

__global__ void bn_apply4(const float4* __restrict__ x, const float4* __restrict__ r,
                          float4* __restrict__ y,
                          const float* __restrict__ g, const float* __restrict__ b,
                          const float* __restrict__ mean, const float* __restrict__ istd,
                          int C, int hwshift4, int total4, int mode)
{
    int stride = gridDim.x * blockDim.x;
    for (int i = blockIdx.x * blockDim.x + threadIdx.x; i < total4; i += stride) {
        int c = (i >> hwshift4) % C;
        float4 v = x[i];
        if (r) {
            float4 rv = r[i];
            v.x = __fadd_rn(v.x, rv.x); v.y = __fadd_rn(v.y, rv.y);
            v.z = __fadd_rn(v.z, rv.z); v.w = __fadd_rn(v.w, rv.w);
        }
        float gc = g[c], bc = b[c], mc = mean[c], ic = istd[c];
        v.x = __fadd_rn(__fmul_rn(__fmul_rn(gc, __fsub_rn(v.x, mc)), ic), bc);
        v.y = __fadd_rn(__fmul_rn(__fmul_rn(gc, __fsub_rn(v.y, mc)), ic), bc);
        v.z = __fadd_rn(__fmul_rn(__fmul_rn(gc, __fsub_rn(v.z, mc)), ic), bc);
        v.w = __fadd_rn(__fmul_rn(__fmul_rn(gc, __fsub_rn(v.w, mc)), ic), bc);
        if (mode == 1) {
            v.x = fmaxf(v.x, 0.f); v.y = fmaxf(v.y, 0.f);
            v.z = fmaxf(v.z, 0.f); v.w = fmaxf(v.w, 0.f);
        } else if (mode == 2) {
            v.x = tanhf(v.x); v.y = tanhf(v.y);
            v.z = tanhf(v.z); v.w = tanhf(v.w);
        }
        y[i] = v;
    }
}

// ---------------- VQ (FROZEN: bit-exact path validated in round 4) ----------
__global__ void transpose_cb(const float* __restrict__ cb, float* __restrict__ cbT)
{
    int i = blockIdx.x * blockDim.x + threadIdx.x;
    int j = i >> 8, k = i & 255;
    cbT[k * 512 + j] = cb[i];
}

__global__ void cnorm_k(const float* __restrict__ cb, float* __restrict__ cn)
{
    int j = blockIdx.x * blockDim.x + threadIdx.x;
    if (j < 512) {
        float s = 0.f;
        const float* p = cb + j * 256;
        for (int c = 0; c < 256; c++) s = __fadd_rn(s, __fmul_rn(p[c], p[c]));
        cn[j] = s;
    }
}

__global__ void fnorm_k(const float* __restrict__ ze, float* __restrict__ fn, int HW)
{
    int w = (blockIdx.x * blockDim.x + threadIdx.x) >> 5;
    int lane = threadIdx.x & 31;
    int n = w / HW, hw = w - n * HW;
    const float* base = ze + (size_t)n * 256 * HW + hw;
    float s = 0.f;
    for (int k = lane; k < 256; k += 32) {
        float v = base[(size_t)k * HW];
        s = __fadd_rn(s, __fmul_rn(v, v));
    }
    #pragma unroll
    for (int o = 16; o > 0; o >>= 1) s += __shfl_down_sync(0xffffffffu, s, o);
    if (lane == 0) fn[w] = s;
}

#define VQ_KC 16
__global__ void __launch_bounds__(512) vq_dist_argmin(
    const float* __restrict__ ze, const float* __restrict__ cbT,
    const float* __restrict__ cn, const float* __restrict__ fnorm,
    int* __restrict__ idx, int HW)
{
    __shared__ float fs[64 * 17];
    __shared__ __align__(16) float cbs[VQ_KC * 512];
    __shared__ float cns[512];
    __shared__ float rd[64 * 8];
    __shared__ int   rj[64 * 8];

    const int t = threadIdx.x, px = t & 63, jg = t >> 6;
    const int p = blockIdx.x * 64 + px;
    cns[t] = cn[t];

    float acc[64];
    #pragma unroll
    for (int j = 0; j < 64; j++) acc[j] = 0.f;

    for (int k0 = 0; k0 < 256; k0 += VQ_KC) {
        __syncthreads();
        for (int i = t; i < 64 * VQ_KC; i += 512) {
            int kk = i >> 6, pp = i & 63;
            int gp = blockIdx.x * 64 + pp;
            int gn = gp / HW, ghw = gp - gn * HW;
            fs[pp * 17 + kk] = ze[((size_t)gn * 256 + (k0 + kk)) * HW + ghw];
        }
        for (int i = t; i < VQ_KC * 512; i += 512)
            cbs[i] = cbT[(size_t)(k0 + (i >> 9)) * 512 + (i & 511)];
        __syncthreads();

        float fv[VQ_KC];
        #pragma unroll
        for (int kk = 0; kk < VQ_KC; kk++) fv[kk] = fs[px * 17 + kk];

        #pragma unroll
        for (int j4 = 0; j4 < 16; j4++) {
            float a0, a1, a2, a3;
            {
                float4 c = *(const float4*)&cbs[jg * 64 + j4 * 4];
                a0 = __fmul_rn(fv[0], c.x); a1 = __fmul_rn(fv[0], c.y);
                a2 = __fmul_rn(fv[0], c.z); a3 = __fmul_rn(fv[0], c.w);
                #pragma unroll
                for (int kk = 1; kk < 8; kk++) {
                    float4 d = *(const float4*)&cbs[kk * 512 + jg * 64 + j4 * 4];
                    a0 = fmaf(fv[kk], d.x, a0); a1 = fmaf(fv[kk], d.y, a1);
                    a2 = fmaf(fv[kk], d.z, a2); a3 = fmaf(fv[kk], d.w, a3);
                }
                acc[j4*4+0] = __fadd_rn(acc[j4*4+0], a0);
                acc[j4*4+1] = __fadd_rn(acc[j4*4+1], a1);
                acc[j4*4+2] = __fadd_rn(acc[j4*4+2], a2);
                acc[j4*4+3] = __fadd_rn(acc[j4*4+3], a3);
            }
            {
                float4 c = *(const float4*)&cbs[8 * 512 + jg * 64 + j4 * 4];
                a0 = __fmul_rn(fv[8], c.x); a1 = __fmul_rn(fv[8], c.y);
                a2 = __fmul_rn(fv[8], c.z); a3 = __fmul_rn(fv[8], c.w);
                #pragma unroll
                for (int kk = 9; kk < 16; kk++) {
                    float4 d = *(const float4*)&cbs[kk * 512 + jg * 64 + j4 * 4];
                    a0 = fmaf(fv[kk], d.x, a0); a1 = fmaf(fv[kk], d.y, a1);
                    a2 = fmaf(fv[kk], d.z, a2); a3 = fmaf(fv[kk], d.w, a3);
                }
                acc[j4*4+0] = __fadd_rn(acc[j4*4+0], a0);
                acc[j4*4+1] = __fadd_rn(acc[j4*4+1], a1);
                acc[j4*4+2] = __fadd_rn(acc[j4*4+2], a2);
                acc[j4*4+3] = __fadd_rn(acc[j4*4+3], a3);
            }
        }
    }

    float S = fnorm[p];
    float best = 3.4028235e38f;
    int bj = 0;
    #pragma unroll
    for (int j = 0; j < 64; j++) {
        float q = __fsub_rn(S, __fmul_rn(2.0f, acc[j]));
        float dj = __fadd_rn(q, cns[jg * 64 + j]);
        if (dj < best) { best = dj; bj = jg * 64 + j; }
    }
    rd[px * 8 + jg] = best;
    rj[px * 8 + jg] = bj;
    __syncthreads();
    if (t < 64) {
        float bb = rd[t * 8]; int jj = rj[t * 8];
        #pragma unroll
        for (int gsel = 1; gsel < 8; gsel++) {
            float d2 = rd[t * 8 + gsel];
            if (d2 < bb) { bb = d2; jj = rj[t * 8 + gsel]; }
        }
        idx[blockIdx.x * 64 + t] = jj;
    }
}

__global__ void vq_gather4(const int* __restrict__ idx, const float* __restrict__ cb,
                           float4* __restrict__ zq, int total4)
{
    int stride = gridDim.x * blockDim.x;
    for (int i = blockIdx.x * blockDim.x + threadIdx.x; i < total4; i += stride) {
        int hw4 = i & 1023;            // HW/4 = 1024
        int nc = i >> 10;
        int c = nc & 255, n = nc >> 8;
        const int* ip = idx + n * 4096 + (hw4 << 2);
        zq[i] = make_float4(cb[ip[0] * 256 + c], cb[ip[1] * 256 + c],
                            cb[ip[2] * 256 + c], cb[ip[3] * 256 + c]);
    }
}

// ---------------- pipeline ----------------
extern "C" void kernel_launch(void* const* d_in, const int* in_sizes, int n_in,
                              void* d_out, int out_size)
{
    const float* img  = (const float*)d_in[0];
    const float* e_w1 = (const float*)d_in[1];
    const float* e_g1 = (const float*)d_in[2];
    const float* e_b1 = (const float*)d_in[3];
    const float* e_w2 = (const float*)d_in[4];
    const float* e_g2 = (const float*)d_in[5];
    const float* e_b2 = (const float*)d_in[6];
    const float* e_w3 = (const float*)d_in[7];
    const float* e_g3 = (const float*)d_in[8];
    const float* e_b3 = (const float*)d_in[9];
    const float* e_w4 = (const float*)d_in[10];
    const float* e_g4 = (const float*)d_in[12];
    const float* e_b4 = (const float*)d_in[13];
    const float* e_g5 = (const float*)d_in[14];
    const float* e_b5 = (const float*)d_in[15];
    const float* cb   = (const float*)d_in[16];
    const float* dw1  = (const float*)d_in[17];
    const float* dg1  = (const float*)d_in[18];
    const float* db1  = (const float*)d_in[19];
    const float* dw2  = (const float*)d_in[20];
    const float* dg2  = (const float*)d_in[21];
    const float* db2  = (const float*)d_in[22];
    const float* dg3  = (const float*)d_in[23];
    const float* db3  = (const float*)d_in[24];
    const float* dt1  = (const float*)d_in[25];
    const float* dg4  = (const float*)d_in[26];
    const float* db4  = (const float*)d_in[27];
    const float* dt2  = (const float*)d_in[28];
    const float* dg5  = (const float*)d_in[30];
    const float* db5  = (const float*)d_in[31];
    float* out = (float*)d_out;

    float *buf128, *b64a, *b64b, *b64c, *mean, *istd, *cnorm, *fnorm, *cbT, *wp;
    float2* part;
    int* idx;
    cudaGetSymbolAddress((void**)&buf128, g_buf128);
    cudaGetSymbolAddress((void**)&b64a,   g_b64a);
    cudaGetSymbolAddress((void**)&b64b,   g_b64b);
    cudaGetSymbolAddress((void**)&b64c,   g_b64c);
    cudaGetSymbolAddress((void**)&mean,   g_mean);
    cudaGetSymbolAddress((void**)&istd,   g_istd);
    cudaGetSymbolAddress((void**)&cnorm,  g_cnorm);
    cudaGetSymbolAddress((void**)&fnorm,  g_fnorm);
    cudaGetSymbolAddress((void**)&cbT,    g_cbT);
    cudaGetSymbolAddress((void**)&wp,     g_wp);
    cudaGetSymbolAddress((void**)&part,   g_part);
    cudaGetSymbolAddress((void**)&idx,    g_idx);

    const int T128 = 33554432, T64 = 8388608;
    const int Q128 = T128 / 4, Q64 = T64 / 4;
    const float INV128 = 1.f / (8.f * 16384.f);
    const float INV64  = 1.f / (8.f * 4096.f);
    const float INVOUT = 1.f / (8.f * 65536.f);
    #define F4(p) ((float4*)(p))
    #define CF4(p) ((const float4*)(p))

    // independent prep
    pack_wt2<<<48, 256>>>(dt2, wp);
    transpose_cb<<<512, 256>>>(cb, cbT);
    cnorm_k<<<2, 256>>>(cb, cnorm);

    // ---- encoder (fp32 SIMT, numerics FROZEN; stores vectorized only) ----
    conv_gemm_t<16,4,2,1><<<dim3(1024, 2), 256>>>(e_w1, img, buf128, 256, 3, 256, 256, 128, 128);
    bn_stats<<<256, 256>>>(buf128, (const float*)0, mean, istd, 256, 16384, 8);
    bn_apply4<<<8192, 256>>>(CF4(buf128), (const float4*)0, F4(buf128), e_g1, e_b1, mean, istd, 256, 12, Q128, 1);

    conv_gemm_t<16,4,2,1><<<dim3(256, 2), 256>>>(e_w2, buf128, b64a, 256, 256, 128, 128, 64, 64);
    bn_stats<<<256, 256>>>(b64a, (const float*)0, mean, istd, 256, 4096, 8);
    bn_apply4<<<4096, 256>>>(CF4(b64a), (const float4*)0, F4(b64a), e_g2, e_b2, mean, istd, 256, 10, Q64, 1);

    conv_gemm_t<9,3,1,1><<<dim3(256, 2), 256>>>(e_w3, b64a, b64b, 256, 256, 64, 64, 64, 64);
    bn_stats<<<256, 256>>>(b64b, (const float*)0, mean, istd, 256, 4096, 8);
    bn_apply4<<<4096, 256>>>(CF4(b64b), (const float4*)0, F4(b64b), e_g3, e_b3, mean, istd, 256, 10, Q64, 1);

    conv_gemm_t<1,1,1,0><<<dim3(256, 2), 256>>>(e_w4, b64b, b64c, 256, 256, 64, 64, 64, 64);
    bn_stats<<<256, 256>>>(b64c, (const float*)0, mean, istd, 256, 4096, 8);
    bn_apply4<<<4096, 256>>>(CF4(b64c), (const float4*)0, F4(b64c), e_g4, e_b4, mean, istd, 256, 10, Q64, 1);

    bn_stats<<<256, 256>>>(b64a, b64c, mean, istd, 256, 4096, 8);
    bn_apply4<<<4096, 256>>>(CF4(b64a), CF4(b64c), F4(b64b), e_g5, e_b5, mean, istd, 256, 10, Q64, 0);

    // ---- VQ (frozen) ----
    fnorm_k<<<4096, 256>>>(b64b, fnorm, 4096);
    vq_dist_argmin<<<512, 512>>>(b64b, cbT, cnorm, fnorm, idx, 4096);
    vq_gather4<<<2048, 256>>>(idx, cb, F4(b64c), Q64);

    // ---- decoder (3-pass split-TF32 tensor cores + parallel stats) ----
    conv_mma_t<9,3,1><<<dim3(256, 2), 256>>>(dw1, b64c, b64a, 256, 256, 64, 64, 64, 64);
    bn_stats_part<<<dim3(256, NSL), 256>>>(b64a, (const float*)0, part, 256, 4096, 8);
    bn_stats_comb<<<1, 256>>>(part, mean, istd, 256, INV64);
    bn_apply4<<<4096, 256>>>(CF4(b64a), (const float4*)0, F4(b64a), dg1, db1, mean, istd, 256, 10, Q64, 1);

    conv_mma_t<1,1,0><<<dim3(256, 2), 256>>>(dw2, b64a, b64b, 256, 256, 64, 64, 64, 64);
    bn_stats_part<<<dim3(256, NSL), 256>>>(b64b, (const float*)0, part, 256, 4096, 8);
    bn_stats_comb<<<1, 256>>>(part, mean, istd, 256, INV64);
    bn_apply4<<<4096, 256>>>(CF4(b64b), (const float4*)0, F4(b64b), dg2, db2, mean, istd, 256, 10, Q64, 1);

    bn_stats_part<<<dim3(256, NSL), 256>>>(b64c, b64b, part, 256, 4096, 8);
    bn_stats_comb<<<1, 256>>>(part, mean, istd, 256, INV64);
    bn_apply4<<<4096, 256>>>(CF4(b64c), CF4(b64b), F4(b64a), dg3, db3, mean, istd, 256, 10, Q64, 1);

    convt_mma<<<dim3(256, 2, 4), 256>>>(dt1, b64a, buf128, 256, 256, 64, 64, 128, 128);
    bn_stats_part<<<dim3(256, NSL), 256>>>(buf128, (const float*)0, part, 256, 16384, 8);
    bn_stats_comb<<<1, 256>>>(part, mean, istd, 256, INV128);
    bn_apply4<<<8192, 256>>>(CF4(buf128), (const float4*)0, F4(buf128), dg4, db4, mean, istd, 256, 12, Q128, 1);

    convt_direct2<<<dim3(256, 1, 8), 256>>>(wp, buf128, out, 256, 128, 128, 256, 256);
    bn_stats_part<<<dim3(3, NSL), 256>>>(out, (const float*)0, part, 3, 65536, 8);
    bn_stats_comb<<<1, 32>>>(part, mean, istd, 3, INVOUT);
    bn_apply4<<<384, 256>>>(CF4(out), (const float4*)0, F4(out), dg5, db5, mean, istd, 3, 14, 393216, 2);
}

// round 15
// speedup vs baseline: 1.1864x; 1.0347x over previous
#include <cuda_runtime.h>
#include <math.h>
#include <stdint.h>

#define EPSBN 1e-5f
#define NSL 8

__device__ float g_buf128[33554432];
__device__ float g_b64a[8388608];
__device__ float g_b64b[8388608];
__device__ float g_b64c[8388608];
__device__ float g_mean[256];
__device__ float g_istd[256];
__device__ float g_cnorm[512];
__device__ float g_fnorm[32768];
__device__ float g_cbT[131072];
__device__ float g_wp[12288];
__device__ float2 g_part[2048];
__device__ int   g_idx[32768];

// ---------------- tf32 helpers (decoder tolerance path only) ----------------
__device__ __forceinline__ uint32_t f2tf32(float x) {
    uint32_t r;
    asm("cvt.rna.tf32.f32 %0, %1;" : "=r"(r) : "f"(x));
    return r;
}
__device__ __forceinline__ void split_tf32(float x, uint32_t& h, uint32_t& l) {
    h = f2tf32(x);
    l = f2tf32(x - __uint_as_float(h));
}
__device__ __forceinline__ void mma_tf32(float* c, const uint32_t* a, uint32_t b0, uint32_t b1) {
    asm volatile(
        "mma.sync.aligned.m16n8k8.row.col.f32.tf32.tf32.f32 "
        "{%0,%1,%2,%3}, {%4,%5,%6,%7}, {%8,%9}, {%0,%1,%2,%3};\n"
        : "+f"(c[0]), "+f"(c[1]), "+f"(c[2]), "+f"(c[3])
        : "r"(a[0]), "r"(a[1]), "r"(a[2]), "r"(a[3]), "r"(b0), "r"(b1));
}

// ---------------- ENCODER conv: 128x128x8 fp32 SIMT (FMA chain FROZEN) -------
// Arithmetic bit-identical to rounds 4-14 (folds every 64 k); float4 stores.
template<int KHW, int KW, int STRIDE, int PAD>
__global__ void __launch_bounds__(256, 2) conv_gemm_t(
    const float* __restrict__ W, const float* __restrict__ X, float* __restrict__ Y,
    int CO, int CI, int IH, int IW, int OH, int OW)
{
    const int Ktot = CI * KHW;
    __shared__ __align__(16) float As[8][128];
    __shared__ __align__(16) float Bs[8][128];
    const int t = threadIdx.x;
    const int pix0 = blockIdx.x * 128, co0 = blockIdx.y * 128;
    const int ohw = OH * OW;

    const int acol = t >> 1;
    const int akq  = (t & 1) << 2;
    const float* Wrow = W + (size_t)(co0 + acol) * Ktot + akq;

    const int bpv = t & 127;
    const int bkq = (t >> 7) << 2;
    const int pixb = pix0 + bpv;
    const int nb = pixb / ohw, remb = pixb - nb * ohw;
    const int oyb = remb / OW, oxb = remb - oyb * OW;
    const int iy0 = oyb * STRIDE - PAD, ix0 = oxb * STRIDE - PAD;
    const float* Xn = X + (size_t)nb * CI * IH * IW;

    const int tx = t & 15, ty = t >> 4;
    float acc[8][8] = {};
    float tot[8][8] = {};
    int nch = 0;

    for (int k0 = 0; k0 < Ktot; k0 += 8) {
        float4 wv = *(const float4*)(Wrow + k0);
        float bval[4];
        #pragma unroll
        for (int i = 0; i < 4; i++) {
            int k = k0 + bkq + i;
            int ci = k / KHW;
            int kr = k - ci * KHW;
            int ky = kr / KW;
            int kx = kr - ky * KW;
            int iy = iy0 + ky, ix = ix0 + kx;
            float v = 0.f;
            if ((unsigned)iy < (unsigned)IH && (unsigned)ix < (unsigned)IW)
                v = Xn[(ci * IH + iy) * IW + ix];
            bval[i] = v;
        }
        As[akq + 0][acol] = wv.x;
        As[akq + 1][acol] = wv.y;
        As[akq + 2][acol] = wv.z;
        As[akq + 3][acol] = wv.w;
        #pragma unroll
        for (int i = 0; i < 4; i++) Bs[bkq + i][bpv] = bval[i];
        __syncthreads();
        #pragma unroll
        for (int kk = 0; kk < 8; kk++) {
            float4 a0 = *(const float4*)&As[kk][ty << 2];
            float4 a1 = *(const float4*)&As[kk][64 + (ty << 2)];
            float4 b0 = *(const float4*)&Bs[kk][tx << 2];
            float4 b1 = *(const float4*)&Bs[kk][64 + (tx << 2)];
            float av[8] = {a0.x, a0.y, a0.z, a0.w, a1.x, a1.y, a1.z, a1.w};
            float bv[8] = {b0.x, b0.y, b0.z, b0.w, b1.x, b1.y, b1.z, b1.w};
            #pragma unroll
            for (int i = 0; i < 8; i++)
                #pragma unroll
                for (int j = 0; j < 8; j++)
                    acc[i][j] = fmaf(av[i], bv[j], acc[i][j]);
        }
        __syncthreads();
        if (++nch == 8) {
            nch = 0;
            #pragma unroll
            for (int i = 0; i < 8; i++)
                #pragma unroll
                for (int j = 0; j < 8; j++) {
                    tot[i][j] = __fadd_rn(tot[i][j], acc[i][j]);
                    acc[i][j] = 0.f;
                }
        }
    }
    #pragma unroll
    for (int i = 0; i < 8; i++)
        #pragma unroll
        for (int j = 0; j < 8; j++) tot[i][j] = __fadd_rn(tot[i][j], acc[i][j]);

    #pragma unroll
    for (int jq = 0; jq < 2; jq++) {
        int p0 = pix0 + (jq ? 64 : 0) + (tx << 2);
        int n2 = p0 / ohw, r2 = p0 - n2 * ohw;
        int oy2 = r2 / OW, ox2 = r2 - oy2 * OW;
        size_t base = (size_t)n2 * CO * ohw + (size_t)oy2 * OW + ox2;
        #pragma unroll
        for (int i = 0; i < 8; i++) {
            int co = co0 + ((i < 4) ? (ty << 2) + i : 64 + (ty << 2) + (i - 4));
            float4 v = make_float4(tot[i][jq * 4 + 0], tot[i][jq * 4 + 1],
                                   tot[i][jq * 4 + 2], tot[i][jq * 4 + 3]);
            *(float4*)&Y[base + (size_t)co * ohw] = v;
        }
    }
}

// ---------------- DECODER conv: 128x128x8 3xTF32 MMA, db + uint2-paired smem --
template<int KHW, int KW, int PAD>
__global__ void __launch_bounds__(256, 2) conv_mma_t(
    const float* __restrict__ W, const float* __restrict__ X, float* __restrict__ Y,
    int CO, int CI, int IH, int IW, int OH, int OW)
{
    const int Ktot = CI * KHW;
    const int NT = Ktot >> 3;
    __shared__ uint2 Aph[2][4][140], Apl[2][4][140], Bph[2][4][140], Bpl[2][4][140];
    const int t = threadIdx.x;
    const int pix0 = blockIdx.x * 128, co0 = blockIdx.y * 128;
    const int ohw = OH * OW;

    const int acol = t >> 1, ahh = t & 1;
    const float* Wrow = W + (size_t)(co0 + acol) * Ktot;

    const int bpv = t & 127, bhh = t >> 7;
    const int pixb = pix0 + bpv;
    const int nb = pixb / ohw, remb = pixb - nb * ohw;
    const int oyb = remb / OW, oxb = remb - oyb * OW;
    const int iy0 = oyb - PAD, ix0 = oxb - PAD;
    const float* Xn = X + (size_t)nb * CI * IH * IW;

    const int warp = t >> 5, lane = t & 31;
    const int wm = warp >> 1, wn = warp & 1;
    const int kq = lane & 3, lr = lane >> 2;

    float acc[2][8][4];
    #pragma unroll
    for (int a = 0; a < 2; a++)
        #pragma unroll
        for (int b = 0; b < 8; b++)
            #pragma unroll
            for (int c = 0; c < 4; c++) acc[a][b][c] = 0.f;

    float wA[4], vB[4];

    #define GATHER_CONV(k0v)                                                     \
        {   float2 w01 = *(const float2*)(Wrow + (k0v) + 2 * ahh);               \
            float2 w45 = *(const float2*)(Wrow + (k0v) + 2 * ahh + 4);           \
            wA[0] = w01.x; wA[1] = w01.y; wA[2] = w45.x; wA[3] = w45.y;          \
            _Pragma("unroll")                                                    \
            for (int i = 0; i < 4; i++) {                                        \
                int klocal = 2 * bhh + (i & 1) + ((i >> 1) << 2);                \
                int k = (k0v) + klocal;                                          \
                int ci = k / KHW;                                                \
                int kr = k - ci * KHW;                                           \
                int ky = kr / KW;                                                \
                int kx = kr - ky * KW;                                           \
                int iy = iy0 + ky, ix = ix0 + kx;                                \
                float v = 0.f;                                                   \
                if ((unsigned)iy < (unsigned)IH && (unsigned)ix < (unsigned)IW)  \
                    v = Xn[(ci * IH + iy) * IW + ix];                            \
                vB[i] = v;                                                       \
            }                                                                    \
        }

    #define STASH(bufv)                                                          \
        {   uint32_t h0,l0,h1,l1,h2,l2,h3,l3;                                    \
            split_tf32(wA[0],h0,l0); split_tf32(wA[1],h1,l1);                    \
            split_tf32(wA[2],h2,l2); split_tf32(wA[3],h3,l3);                    \
            Aph[bufv][2*ahh+0][acol] = make_uint2(h0, h2);                       \
            Aph[bufv][2*ahh+1][acol] = make_uint2(h1, h3);                       \
            Apl[bufv][2*ahh+0][acol] = make_uint2(l0, l2);                       \
            Apl[bufv][2*ahh+1][acol] = make_uint2(l1, l3);                       \
            split_tf32(vB[0],h0,l0); split_tf32(vB[1],h1,l1);                    \
            split_tf32(vB[2],h2,l2); split_tf32(vB[3],h3,l3);                    \
            Bph[bufv][2*bhh+0][bpv] = make_uint2(h0, h2);                        \
            Bph[bufv][2*bhh+1][bpv] = make_uint2(h1, h3);                        \
            Bpl[bufv][2*bhh+0][bpv] = make_uint2(l0, l2);                        \
            Bpl[bufv][2*bhh+1][bpv] = make_uint2(l1, l3);                        \
        }

    GATHER_CONV(0)
    STASH(0)
    __syncthreads();

    for (int tile = 0; tile < NT; tile++) {
        const int cur = tile & 1;
        const bool more = (tile + 1 < NT);
        if (more) GATHER_CONV((tile + 1) << 3)

        uint32_t ah[2][4], al[2][4];
        #pragma unroll
        for (int mt = 0; mt < 2; mt++) {
            int ca = wm * 32 + mt * 16 + lr;
            uint2 u0 = Aph[cur][kq][ca];
            uint2 u1 = Aph[cur][kq][ca + 8];
            ah[mt][0] = u0.x; ah[mt][1] = u1.x; ah[mt][2] = u0.y; ah[mt][3] = u1.y;
            uint2 v0 = Apl[cur][kq][ca];
            uint2 v1 = Apl[cur][kq][ca + 8];
            al[mt][0] = v0.x; al[mt][1] = v1.x; al[mt][2] = v0.y; al[mt][3] = v1.y;
        }
        #pragma unroll
        for (int nt = 0; nt < 8; nt++) {
            int pa = wn * 64 + nt * 8 + lr;
            uint2 bh = Bph[cur][kq][pa];
            uint2 bl = Bpl[cur][kq][pa];
            #pragma unroll
            for (int mt = 0; mt < 2; mt++) {
                mma_tf32(acc[mt][nt], ah[mt], bh.x, bh.y);
                mma_tf32(acc[mt][nt], ah[mt], bl.x, bl.y);
                mma_tf32(acc[mt][nt], al[mt], bh.x, bh.y);
            }
        }
        if (more) STASH(cur ^ 1)
        __syncthreads();
    }

    #pragma unroll
    for (int nt = 0; nt < 8; nt++) {
        int p = pix0 + wn * 64 + nt * 8 + (kq << 1);
        int n2 = p / ohw, r2 = p - n2 * ohw;
        int oy2 = r2 / OW, ox2 = r2 - oy2 * OW;
        size_t rowbase = (size_t)n2 * CO * ohw + (size_t)oy2 * OW + ox2;
        #pragma unroll
        for (int mt = 0; mt < 2; mt++) {
            int c0r = co0 + wm * 32 + mt * 16 + lr;
            float2 v0 = make_float2(acc[mt][nt][0], acc[mt][nt][1]);
            float2 v1 = make_float2(acc[mt][nt][2], acc[mt][nt][3]);
            *(float2*)&Y[rowbase + (size_t)c0r * ohw] = v0;
            *(float2*)&Y[rowbase + (size_t)(c0r + 8) * ohw] = v1;
        }
    }
    #undef GATHER_CONV
    #undef STASH
}

// ---------------- DECODER convT(k=4,s=2,p=1): parity-split 3xTF32 MMA, db -----
__global__ void __launch_bounds__(256, 2) convt_mma(
    const float* __restrict__ W, const float* __restrict__ X, float* __restrict__ Y,
    int CO, int CI, int IH, int IW, int OH, int OW)
{
    const int py = (blockIdx.z >> 1) & 1, px = blockIdx.z & 1;
    const int ky0 = 1 - py, ky1 = 3 - py, dy0 = py, dy1 = py - 1;
    const int kx0 = 1 - px, kx1 = 3 - px, dx0 = px, dx1 = px - 1;
    const int Ktot = CI * 4;
    const int NT = Ktot >> 3;
    __shared__ uint2 Aph[2][4][140], Apl[2][4][140], Bph[2][4][140], Bpl[2][4][140];
    const int t = threadIdx.x;
    const int pix0 = blockIdx.x * 128, co0 = blockIdx.y * 128;
    const int yhw = IH * IW;

    const int acol = t >> 1, ahh = t & 1;
    const int bpv = t & 127, bhh = t >> 7;
    const int pixb = pix0 + bpv;
    const int nb = pixb / yhw, remb = pixb - nb * yhw;
    const int yb = remb / IW, xb = remb - yb * IW;
    const float* Xn = X + (size_t)nb * CI * yhw;

    const int warp = t >> 5, lane = t & 31;
    const int wm = warp >> 1, wn = warp & 1;
    const int kq = lane & 3, lr = lane >> 2;

    float acc[2][8][4];
    #pragma unroll
    for (int a = 0; a < 2; a++)
        #pragma unroll
        for (int b = 0; b < 8; b++)
            #pragma unroll
            for (int c = 0; c < 4; c++) acc[a][b][c] = 0.f;

    float wA[4], vB[4];

    #define GATHER_CT(k0v)                                                       \
        {   _Pragma("unroll")                                                    \
            for (int i = 0; i < 4; i++) {                                        \
                int klocal = 2 * ahh + (i & 1) + ((i >> 1) << 2);                \
                int k = (k0v) + klocal;                                          \
                int ci = k >> 2, tt = k & 3;                                     \
                int ky = (tt & 2) ? ky1 : ky0;                                   \
                int kx = (tt & 1) ? kx1 : kx0;                                   \
                wA[i] = W[(((size_t)ci * CO + co0 + acol) << 4) + (ky << 2) + kx]; \
            }                                                                    \
            _Pragma("unroll")                                                    \
            for (int i = 0; i < 4; i++) {                                        \
                int klocal = 2 * bhh + (i & 1) + ((i >> 1) << 2);                \
                int k = (k0v) + klocal;                                          \
                int ci = k >> 2, tt = k & 3;                                     \
                int iy = yb + ((tt & 2) ? dy1 : dy0);                            \
                int ix = xb + ((tt & 1) ? dx1 : dx0);                            \
                vB[i] = ((unsigned)iy < (unsigned)IH && (unsigned)ix < (unsigned)IW) \
                        ? Xn[(ci * IH + iy) * IW + ix] : 0.f;                    \
            }                                                                    \
        }

    #define STASH2(bufv)                                                         \
        {   uint32_t h0,l0,h1,l1,h2,l2,h3,l3;                                    \
            split_tf32(wA[0],h0,l0); split_tf32(wA[1],h1,l1);                    \
            split_tf32(wA[2],h2,l2); split_tf32(wA[3],h3,l3);                    \
            Aph[bufv][2*ahh+0][acol] = make_uint2(h0, h2);                       \
            Aph[bufv][2*ahh+1][acol] = make_uint2(h1, h3);                       \
            Apl[bufv][2*ahh+0][acol] = make_uint2(l0, l2);                       \
            Apl[bufv][2*ahh+1][acol] = make_uint2(l1, l3);                       \
            split_tf32(vB[0],h0,l0); split_tf32(vB[1],h1,l1);                    \
            split_tf32(vB[2],h2,l2); split_tf32(vB[3],h3,l3);                    \
            Bph[bufv][2*bhh+0][bpv] = make_uint2(h0, h2);                        \
            Bph[bufv][2*bhh+1][bpv] = make_uint2(h1, h3);                        \
            Bpl[bufv][2*bhh+0][bpv] = make_uint2(l0, l2);                        \
            Bpl[bufv][2*bhh+1][bpv] = make_uint2(l1, l3);                        \
        }

    GATHER_CT(0)
    STASH2(0)
    __syncthreads();

    for (int tile = 0; tile < NT; tile++) {
        const int cur = tile & 1;
        const bool more = (tile + 1 < NT);
        if (more) GATHER_CT((tile + 1) << 3)

        uint32_t ah[2][4], al[2][4];
        #pragma unroll
        for (int mt = 0; mt < 2; mt++) {
            int ca = wm * 32 + mt * 16 + lr;
            uint2 u0 = Aph[cur][kq][ca];
            uint2 u1 = Aph[cur][kq][ca + 8];
            ah[mt][0] = u0.x; ah[mt][1] = u1.x; ah[mt][2] = u0.y; ah[mt][3] = u1.y;
            uint2 v0 = Apl[cur][kq][ca];
            uint2 v1 = Apl[cur][kq][ca + 8];
            al[mt][0] = v0.x; al[mt][1] = v1.x; al[mt][2] = v0.y; al[mt][3] = v1.y;
        }
        #pragma unroll
        for (int nt = 0; nt < 8; nt++) {
            int pa = wn * 64 + nt * 8 + lr;
            uint2 bh = Bph[cur][kq][pa];
            uint2 bl = Bpl[cur][kq][pa];
            #pragma unroll
            for (int mt = 0; mt < 2; mt++) {
                mma_tf32(acc[mt][nt], ah[mt], bh.x, bh.y);
                mma_tf32(acc[mt][nt], ah[mt], bl.x, bl.y);
                mma_tf32(acc[mt][nt], al[mt], bh.x, bh.y);
            }
        }
        if (more) STASH2(cur ^ 1)
        __syncthreads();
    }

    const size_t ostride = (size_t)OH * OW;
    #pragma unroll
    for (int nt = 0; nt < 8; nt++) {
        #pragma unroll
        for (int e = 0; e < 2; e++) {
            int pp = pix0 + wn * 64 + nt * 8 + (kq << 1) + e;
            int n2 = pp / yhw, r2 = pp - n2 * yhw;
            int y2 = r2 / IW, x2 = r2 - y2 * IW;
            int oy = (y2 << 1) + py, ox = (x2 << 1) + px;
            #pragma unroll
            for (int mt = 0; mt < 2; mt++) {
                int c0r = co0 + wm * 32 + mt * 16 + lr;
                size_t idx = (((size_t)n2 * CO + c0r) * OH + oy) * OW + ox;
                Y[idx] = acc[mt][nt][e];
                Y[idx + 8 * ostride] = acc[mt][nt][2 + e];
            }
        }
    }
    #undef GATHER_CT
    #undef STASH2
}

// ---------------- d_t2 weight repack + packed direct convT ----------------
__global__ void pack_wt2(const float* __restrict__ W, float* __restrict__ Wp)
{
    int i = blockIdx.x * blockDim.x + threadIdx.x;
    if (i >= 12288) return;
    int tap = i & 3;
    int r = i >> 2;
    int co = r % 3;
    int r2 = r / 3;
    int ci = r2 & 255;
    int pp = r2 >> 8;
    int py = pp >> 1, px = pp & 1;
    int ky = ((tap >> 1) == 0) ? (1 - py) : (3 - py);
    int kx = ((tap & 1) == 0) ? (1 - px) : (3 - px);
    Wp[i] = W[((size_t)ci * 3 + co) * 16 + ky * 4 + kx];
}

__global__ void __launch_bounds__(256) convt_direct2(
    const float* __restrict__ Wp, const float* __restrict__ X, float* __restrict__ Y,
    int CI, int IH, int IW, int OH, int OW)
{
    int ox = threadIdx.x, oy = blockIdx.x, n = blockIdx.z;
    int py = oy & 1, px = ox & 1;
    int iyA = (oy + py) >> 1, iyB = iyA - 1;
    int ixA = (ox + px) >> 1, ixB = ixA - 1;
    bool vyA = (unsigned)iyA < (unsigned)IH, vyB = (unsigned)iyB < (unsigned)IH;
    bool vxA = (unsigned)ixA < (unsigned)IW, vxB = (unsigned)ixB < (unsigned)IW;
    const float* Xn = X + (size_t)n * CI * IH * IW;
    const float4* wp = (const float4*)(Wp + (size_t)(py * 2 + px) * 256 * 12);

    float a0 = 0.f, a1 = 0.f, a2 = 0.f;
    for (int ci = 0; ci < CI; ci++) {
        const float* xc = Xn + (size_t)ci * IH * IW;
        float x00 = (vyA && vxA) ? xc[iyA * IW + ixA] : 0.f;
        float x01 = (vyA && vxB) ? xc[iyA * IW + ixB] : 0.f;
        float x10 = (vyB && vxA) ? xc[iyB * IW + ixA] : 0.f;
        float x11 = (vyB && vxB) ? xc[iyB * IW + ixB] : 0.f;
        float4 w0 = wp[ci * 3 + 0];
        float4 w1 = wp[ci * 3 + 1];
        float4 w2 = wp[ci * 3 + 2];
        a0 = fmaf(x00, w0.x, a0); a0 = fmaf(x01, w0.y, a0);
        a0 = fmaf(x10, w0.z, a0); a0 = fmaf(x11, w0.w, a0);
        a1 = fmaf(x00, w1.x, a1); a1 = fmaf(x01, w1.y, a1);
        a1 = fmaf(x10, w1.z, a1); a1 = fmaf(x11, w1.w, a1);
        a2 = fmaf(x00, w2.x, a2); a2 = fmaf(x01, w2.y, a2);
        a2 = fmaf(x10, w2.z, a2); a2 = fmaf(x11, w2.w, a2);
    }
    size_t ohw = (size_t)OH * OW;
    size_t base = (size_t)n * 3 * ohw + (size_t)oy * OW + ox;
    Y[base] = a0;
    Y[base + ohw] = a1;
    Y[base + 2 * ohw] = a2;
}

// ---------------- Two-phase parallel BN stats (ALL BNs) ----------------------
// Kahan within fixed slices + deterministic ascending-slice combine.
// Perturbs mean/istd by ~ulp of O(1) values: 10-1000x below the conv-order
// noise already tolerated between this kernel and the reference (zero flips
// across rounds 4-14) -> VQ-safe by dominance.
__global__ void bn_stats_part(const float* __restrict__ x, const float* __restrict__ r,
                              float2* __restrict__ part, int C, int HW, int Bn)
{
    int c = blockIdx.x, sl = blockIdx.y;
    int chunk = HW / NSL;
    int i0 = sl * chunk;
    float s = 0.f, cs = 0.f, ss = 0.f, css = 0.f;
    for (int n = 0; n < Bn; n++) {
        const float* p = x + (size_t)(n * C + c) * HW;
        const float* q = r ? r + (size_t)(n * C + c) * HW : (const float*)0;
        for (int i = i0 + threadIdx.x; i < i0 + chunk; i += blockDim.x) {
            float v = p[i];
            if (q) v = __fadd_rn(v, q[i]);
            float y1 = __fsub_rn(v, cs);
            float t1 = __fadd_rn(s, y1);
            cs = __fsub_rn(__fsub_rn(t1, s), y1); s = t1;
            float w = __fmul_rn(v, v);
            float y2 = __fsub_rn(w, css);
            float t2 = __fadd_rn(ss, y2);
            css = __fsub_rn(__fsub_rn(t2, ss), y2); ss = t2;
        }
    }
    s = __fsub_rn(s, cs); ss = __fsub_rn(ss, css);
    __shared__ float shs[32], shss[32];
    int lane = threadIdx.x & 31, wid = threadIdx.x >> 5;
    #pragma unroll
    for (int o = 16; o > 0; o >>= 1) {
        s  += __shfl_down_sync(0xffffffffu, s,  o);
        ss += __shfl_down_sync(0xffffffffu, ss, o);
    }
    if (lane == 0) { shs[wid] = s; shss[wid] = ss; }
    __syncthreads();
    if (threadIdx.x == 0) {
        int nw = blockDim.x >> 5;
        float ts = 0.f, tss = 0.f;
        for (int i = 0; i < nw; i++) { ts += shs[i]; tss += shss[i]; }
        part[c * NSL + sl] = make_float2(ts, tss);
    }
}

__global__ void bn_stats_comb(const float2* __restrict__ part,
                              float* __restrict__ mean, float* __restrict__ istd,
                              int C, float inv)
{
    int c = blockIdx.x * blockDim.x + threadIdx.x;
    if (c >= C) return;
    float ts = 0.f, tss = 0.f;
    for (int sl = 0; sl < NSL; sl++) {
        float2 v = part[c * NSL + sl];
        ts += v.x; tss += v.y;
    }
    float m = ts * inv;
    float var = fmaxf(tss * inv - m * m, 0.f);
    mean[c] = m;
    istd[c] = rsqrtf(var + EPSBN);
}

__global__ void bn_apply4(const float4* __restrict__ x, const float4* __restrict__ r,
                          float4* __restrict__ y,
                          const float* __restrict__ g, const float* __restrict__ b,
                          const float* __restrict__ mean, const float* __restrict__ istd,
                          int C, int hwshift4, int total4, int mode)
{
    int stride = gridDim.x * blockDim.x;
    for (int i = blockIdx.x * blockDim.x + threadIdx.x; i < total4; i += stride) {
        int c = (i >> hwshift4) % C;
        float4 v = x[i];
        if (r) {
            float4 rv = r[i];
            v.x = __fadd_rn(v.x, rv.x); v.y = __fadd_rn(v.y, rv.y);
            v.z = __fadd_rn(v.z, rv.z); v.w = __fadd_rn(v.w, rv.w);
        }
        float gc = g[c], bc = b[c], mc = mean[c], ic = istd[c];
        v.x = __fadd_rn(__fmul_rn(__fmul_rn(gc, __fsub_rn(v.x, mc)), ic), bc);
        v.y = __fadd_rn(__fmul_rn(__fmul_rn(gc, __fsub_rn(v.y, mc)), ic), bc);
        v.z = __fadd_rn(__fmul_rn(__fmul_rn(gc, __fsub_rn(v.z, mc)), ic), bc);
        v.w = __fadd_rn(__fmul_rn(__fmul_rn(gc, __fsub_rn(v.w, mc)), ic), bc);
        if (mode == 1) {
            v.x = fmaxf(v.x, 0.f); v.y = fmaxf(v.y, 0.f);
            v.z = fmaxf(v.z, 0.f); v.w = fmaxf(v.w, 0.f);
        } else if (mode == 2) {
            v.x = tanhf(v.x); v.y = tanhf(v.y);
            v.z = tanhf(v.z); v.w = tanhf(v.w);
        }
        y[i] = v;
    }
}

// ---------------- VQ (FROZEN: bit-exact path validated in round 4) ----------
__global__ void transpose_cb(const float* __restrict__ cb, float* __restrict__ cbT)
{
    int i = blockIdx.x * blockDim.x + threadIdx.x;
    int j = i >> 8, k = i & 255;
    cbT[k * 512 + j] = cb[i];
}

__global__ void cnorm_k(const float* __restrict__ cb, float* __restrict__ cn)
{
    int j = blockIdx.x * blockDim.x + threadIdx.x;
    if (j < 512) {
        float s = 0.f;
        const float* p = cb + j * 256;
        for (int c = 0; c < 256; c++) s = __fadd_rn(s, __fmul_rn(p[c], p[c]));
        cn[j] = s;
    }
}

__global__ void fnorm_k(const float* __restrict__ ze, float* __restrict__ fn, int HW)
{
    int w = (blockIdx.x * blockDim.x + threadIdx.x) >> 5;
    int lane = threadIdx.x & 31;
    int n = w / HW, hw = w - n * HW;
    const float* base = ze + (size_t)n * 256 * HW + hw;
    float s = 0.f;
    for (int k = lane; k < 256; k += 32) {
        float v = base[(size_t)k * HW];
        s = __fadd_rn(s, __fmul_rn(v, v));
    }
    #pragma unroll
    for (int o = 16; o > 0; o >>= 1) s += __shfl_down_sync(0xffffffffu, s, o);
    if (lane == 0) fn[w] = s;
}

#define VQ_KC 16
__global__ void __launch_bounds__(512) vq_dist_argmin(
    const float* __restrict__ ze, const float* __restrict__ cbT,
    const float* __restrict__ cn, const float* __restrict__ fnorm,
    int* __restrict__ idx, int HW)
{
    __shared__ float fs[64 * 17];
    __shared__ __align__(16) float cbs[VQ_KC * 512];
    __shared__ float cns[512];
    __shared__ float rd[64 * 8];
    __shared__ int   rj[64 * 8];

    const int t = threadIdx.x, px = t & 63, jg = t >> 6;
    const int p = blockIdx.x * 64 + px;
    cns[t] = cn[t];

    float acc[64];
    #pragma unroll
    for (int j = 0; j < 64; j++) acc[j] = 0.f;

    for (int k0 = 0; k0 < 256; k0 += VQ_KC) {
        __syncthreads();
        for (int i = t; i < 64 * VQ_KC; i += 512) {
            int kk = i >> 6, pp = i & 63;
            int gp = blockIdx.x * 64 + pp;
            int gn = gp / HW, ghw = gp - gn * HW;
            fs[pp * 17 + kk] = ze[((size_t)gn * 256 + (k0 + kk)) * HW + ghw];
        }
        for (int i = t; i < VQ_KC * 512; i += 512)
            cbs[i] = cbT[(size_t)(k0 + (i >> 9)) * 512 + (i & 511)];
        __syncthreads();

        float fv[VQ_KC];
        #pragma unroll
        for (int kk = 0; kk < VQ_KC; kk++) fv[kk] = fs[px * 17 + kk];

        #pragma unroll
        for (int j4 = 0; j4 < 16; j4++) {
            float a0, a1, a2, a3;
            {
                float4 c = *(const float4*)&cbs[jg * 64 + j4 * 4];
                a0 = __fmul_rn(fv[0], c.x); a1 = __fmul_rn(fv[0], c.y);
                a2 = __fmul_rn(fv[0], c.z); a3 = __fmul_rn(fv[0], c.w);
                #pragma unroll
                for (int kk = 1; kk < 8; kk++) {
                    float4 d = *(const float4*)&cbs[kk * 512 + jg * 64 + j4 * 4];
                    a0 = fmaf(fv[kk], d.x, a0); a1 = fmaf(fv[kk], d.y, a1);
                    a2 = fmaf(fv[kk], d.z, a2); a3 = fmaf(fv[kk], d.w, a3);
                }
                acc[j4*4+0] = __fadd_rn(acc[j4*4+0], a0);
                acc[j4*4+1] = __fadd_rn(acc[j4*4+1], a1);
                acc[j4*4+2] = __fadd_rn(acc[j4*4+2], a2);
                acc[j4*4+3] = __fadd_rn(acc[j4*4+3], a3);
            }
            {
                float4 c = *(const float4*)&cbs[8 * 512 + jg * 64 + j4 * 4];
                a0 = __fmul_rn(fv[8], c.x); a1 = __fmul_rn(fv[8], c.y);
                a2 = __fmul_rn(fv[8], c.z); a3 = __fmul_rn(fv[8], c.w);
                #pragma unroll
                for (int kk = 9; kk < 16; kk++) {
                    float4 d = *(const float4*)&cbs[kk * 512 + jg * 64 + j4 * 4];
                    a0 = fmaf(fv[kk], d.x, a0); a1 = fmaf(fv[kk], d.y, a1);
                    a2 = fmaf(fv[kk], d.z, a2); a3 = fmaf(fv[kk], d.w, a3);
                }
                acc[j4*4+0] = __fadd_rn(acc[j4*4+0], a0);
                acc[j4*4+1] = __fadd_rn(acc[j4*4+1], a1);
                acc[j4*4+2] = __fadd_rn(acc[j4*4+2], a2);
                acc[j4*4+3] = __fadd_rn(acc[j4*4+3], a3);
            }
        }
    }

    float S = fnorm[p];
    float best = 3.4028235e38f;
    int bj = 0;
    #pragma unroll
    for (int j = 0; j < 64; j++) {
        float q = __fsub_rn(S, __fmul_rn(2.0f, acc[j]));
        float dj = __fadd_rn(q, cns[jg * 64 + j]);
        if (dj < best) { best = dj; bj = jg * 64 + j; }
    }
    rd[px * 8 + jg] = best;
    rj[px * 8 + jg] = bj;
    __syncthreads();
    if (t < 64) {
        float bb = rd[t * 8]; int jj = rj[t * 8];
        #pragma unroll
        for (int gsel = 1; gsel < 8; gsel++) {
            float d2 = rd[t * 8 + gsel];
            if (d2 < bb) { bb = d2; jj = rj[t * 8 + gsel]; }
        }
        idx[blockIdx.x * 64 + t] = jj;
    }
}

__global__ void vq_gather4(const int* __restrict__ idx, const float* __restrict__ cb,
                           float4* __restrict__ zq, int total4)
{
    int stride = gridDim.x * blockDim.x;
    for (int i = blockIdx.x * blockDim.x + threadIdx.x; i < total4; i += stride) {
        int hw4 = i & 1023;
        int nc = i >> 10;
        int c = nc & 255, n = nc >> 8;
        const int* ip = idx + n * 4096 + (hw4 << 2);
        zq[i] = make_float4(cb[ip[0] * 256 + c], cb[ip[1] * 256 + c],
                            cb[ip[2] * 256 + c], cb[ip[3] * 256 + c]);
    }
}

// ---------------- pipeline ----------------
extern "C" void kernel_launch(void* const* d_in, const int* in_sizes, int n_in,
                              void* d_out, int out_size)
{
    const float* img  = (const float*)d_in[0];
    const float* e_w1 = (const float*)d_in[1];
    const float* e_g1 = (const float*)d_in[2];
    const float* e_b1 = (const float*)d_in[3];
    const float* e_w2 = (const float*)d_in[4];
    const float* e_g2 = (const float*)d_in[5];
    const float* e_b2 = (const float*)d_in[6];
    const float* e_w3 = (const float*)d_in[7];
    const float* e_g3 = (const float*)d_in[8];
    const float* e_b3 = (const float*)d_in[9];
    const float* e_w4 = (const float*)d_in[10];
    const float* e_g4 = (const float*)d_in[12];
    const float* e_b4 = (const float*)d_in[13];
    const float* e_g5 = (const float*)d_in[14];
    const float* e_b5 = (const float*)d_in[15];
    const float* cb   = (const float*)d_in[16];
    const float* dw1  = (const float*)d_in[17];
    const float* dg1  = (const float*)d_in[18];
    const float* db1  = (const float*)d_in[19];
    const float* dw2  = (const float*)d_in[20];
    const float* dg2  = (const float*)d_in[21];
    const float* db2  = (const float*)d_in[22];
    const float* dg3  = (const float*)d_in[23];
    const float* db3  = (const float*)d_in[24];
    const float* dt1  = (const float*)d_in[25];
    const float* dg4  = (const float*)d_in[26];
    const float* db4  = (const float*)d_in[27];
    const float* dt2  = (const float*)d_in[28];
    const float* dg5  = (const float*)d_in[30];
    const float* db5  = (const float*)d_in[31];
    float* out = (float*)d_out;

    float *buf128, *b64a, *b64b, *b64c, *mean, *istd, *cnorm, *fnorm, *cbT, *wp;
    float2* part;
    int* idx;
    cudaGetSymbolAddress((void**)&buf128, g_buf128);
    cudaGetSymbolAddress((void**)&b64a,   g_b64a);
    cudaGetSymbolAddress((void**)&b64b,   g_b64b);
    cudaGetSymbolAddress((void**)&b64c,   g_b64c);
    cudaGetSymbolAddress((void**)&mean,   g_mean);
    cudaGetSymbolAddress((void**)&istd,   g_istd);
    cudaGetSymbolAddress((void**)&cnorm,  g_cnorm);
    cudaGetSymbolAddress((void**)&fnorm,  g_fnorm);
    cudaGetSymbolAddress((void**)&cbT,    g_cbT);
    cudaGetSymbolAddress((void**)&wp,     g_wp);
    cudaGetSymbolAddress((void**)&part,   g_part);
    cudaGetSymbolAddress((void**)&idx,    g_idx);

    const int T128 = 33554432, T64 = 8388608;
    const int Q128 = T128 / 4, Q64 = T64 / 4;
    const float INV128 = 1.f / (8.f * 16384.f);
    const float INV64  = 1.f / (8.f * 4096.f);
    const float INVOUT = 1.f / (8.f * 65536.f);
    #define F4(p) ((float4*)(p))
    #define CF4(p) ((const float4*)(p))
    #define BN_STATS(buf, res, HW, INV, Cc)                                     \
        bn_stats_part<<<dim3(Cc, NSL), 256>>>(buf, res, part, Cc, HW, 8);       \
        bn_stats_comb<<<1, (Cc) >= 256 ? 256 : 32>>>(part, mean, istd, Cc, INV);

    // independent prep
    pack_wt2<<<48, 256>>>(dt2, wp);
    transpose_cb<<<512, 256>>>(cb, cbT);
    cnorm_k<<<2, 256>>>(cb, cnorm);

    // ---- encoder (conv FMA chains FROZEN; stats two-phase per dominance) ----
    conv_gemm_t<16,4,2,1><<<dim3(1024, 2), 256>>>(e_w1, img, buf128, 256, 3, 256, 256, 128, 128);
    BN_STATS(buf128, (const float*)0, 16384, INV128, 256)
    bn_apply4<<<8192, 256>>>(CF4(buf128), (const float4*)0, F4(buf128), e_g1, e_b1, mean, istd, 256, 12, Q128, 1);

    conv_gemm_t<16,4,2,1><<<dim3(256, 2), 256>>>(e_w2, buf128, b64a, 256, 256, 128, 128, 64, 64);
    BN_STATS(b64a, (const float*)0, 4096, INV64, 256)
    bn_apply4<<<4096, 256>>>(CF4(b64a), (const float4*)0, F4(b64a), e_g2, e_b2, mean, istd, 256, 10, Q64, 1);

    conv_gemm_t<9,3,1,1><<<dim3(256, 2), 256>>>(e_w3, b64a, b64b, 256, 256, 64, 64, 64, 64);
    BN_STATS(b64b, (const float*)0, 4096, INV64, 256)
    bn_apply4<<<4096, 256>>>(CF4(b64b), (const float4*)0, F4(b64b), e_g3, e_b3, mean, istd, 256, 10, Q64, 1);

    conv_gemm_t<1,1,1,0><<<dim3(256, 2), 256>>>(e_w4, b64b, b64c, 256, 256, 64, 64, 64, 64);
    BN_STATS(b64c, (const float*)0, 4096, INV64, 256)
    bn_apply4<<<4096, 256>>>(CF4(b64c), (const float4*)0, F4(b64c), e_g4, e_b4, mean, istd, 256, 10, Q64, 1);

    BN_STATS(b64a, b64c, 4096, INV64, 256)
    bn_apply4<<<4096, 256>>>(CF4(b64a), CF4(b64c), F4(b64b), e_g5, e_b5, mean, istd, 256, 10, Q64, 0);

    // ---- VQ (frozen) ----
    fnorm_k<<<4096, 256>>>(b64b, fnorm, 4096);
    vq_dist_argmin<<<512, 512>>>(b64b, cbT, cnorm, fnorm, idx, 4096);
    vq_gather4<<<2048, 256>>>(idx, cb, F4(b64c), Q64);

    // ---- decoder (3-pass split-TF32 tensor cores, tolerance path) ----
    conv_mma_t<9,3,1><<<dim3(256, 2), 256>>>(dw1, b64c, b64a, 256, 256, 64, 64, 64, 64);
    BN_STATS(b64a, (const float*)0, 4096, INV64, 256)
    bn_apply4<<<4096, 256>>>(CF4(b64a), (const float4*)0, F4(b64a), dg1, db1, mean, istd, 256, 10, Q64, 1);

    conv_mma_t<1,1,0><<<dim3(256, 2), 256>>>(dw2, b64a, b64b, 256, 256, 64, 64, 64, 64);
    BN_STATS(b64b, (const float*)0, 4096, INV64, 256)
    bn_apply4<<<4096, 256>>>(CF4(b64b), (const float4*)0, F4(b64b), dg2, db2, mean, istd, 256, 10, Q64, 1);

    BN_STATS(b64c, b64b, 4096, INV64, 256)
    bn_apply4<<<4096, 256>>>(CF4(b64c), CF4(b64b), F4(b64a), dg3, db3, mean, istd, 256, 10, Q64, 1);

    convt_mma<<<dim3(256, 2, 4), 256>>>(dt1, b64a, buf128, 256, 256, 64, 64, 128, 128);
    BN_STATS(buf128, (const float*)0, 16384, INV128, 256)
    bn_apply4<<<8192, 256>>>(CF4(buf128), (const float4*)0, F4(buf128), dg4, db4, mean, istd, 256, 12, Q128, 1);

    convt_direct2<<<dim3(256, 1, 8), 256>>>(wp, buf128, out, 256, 128, 128, 256, 256);
    BN_STATS(out, (const float*)0, 65536, INVOUT, 3)
    bn_apply4<<<384, 256>>>(CF4(out), (const float4*)0, F4(out), dg5, db5, mean, istd, 3, 14, 393216, 2);
}

// round 16
// speedup vs baseline: 1.2136x; 1.0229x over previous
#include <cuda_runtime.h>
#include <math.h>
#include <stdint.h>

#define EPSBN 1e-5f
#define NSL 8

__device__ float g_buf128[33554432];
__device__ float g_b64a[8388608];
__device__ float g_b64b[8388608];
__device__ float g_b64c[8388608];
__device__ float g_mean[256];
__device__ float g_istd[256];
__device__ float g_cnorm[512];
__device__ float g_fnorm[32768];
__device__ float g_cbT[131072];
__device__ float g_wp[12288];
__device__ float2 g_part[2048];
__device__ int   g_idx[32768];

// ---------------- tf32 helpers (decoder tolerance path only) ----------------
__device__ __forceinline__ uint32_t f2tf32(float x) {
    uint32_t r;
    asm("cvt.rna.tf32.f32 %0, %1;" : "=r"(r) : "f"(x));
    return r;
}
__device__ __forceinline__ void split_tf32(float x, uint32_t& h, uint32_t& l) {
    h = f2tf32(x);
    l = f2tf32(x - __uint_as_float(h));
}
__device__ __forceinline__ void mma_tf32(float* c, const uint32_t* a, uint32_t b0, uint32_t b1) {
    asm volatile(
        "mma.sync.aligned.m16n8k8.row.col.f32.tf32.tf32.f32 "
        "{%0,%1,%2,%3}, {%4,%5,%6,%7}, {%8,%9}, {%0,%1,%2,%3};\n"
        : "+f"(c[0]), "+f"(c[1]), "+f"(c[2]), "+f"(c[3])
        : "r"(a[0]), "r"(a[1]), "r"(a[2]), "r"(a[3]), "r"(b0), "r"(b1));
}

// ------ ENCODER conv: 128co x 64pix x 8k, double-buffered, 3 CTAs/SM --------
// NUMERICS FROZEN: per-(co,pixel) ascending-k FMA chain with acc->tot folds
// every 64 k — bit-identical to rounds 4-15 (this tile/db structure was proven
// bit-equivalent in rounds 5/6: identical rel_err). Only the schedule differs:
// templated gather math, register-prefetch db, one sync/tile, occupancy 3.
template<int KHW, int KW, int STRIDE, int PAD>
__global__ void __launch_bounds__(256, 3) conv_gemm_db2(
    const float* __restrict__ W, const float* __restrict__ X, float* __restrict__ Y,
    int CO, int CI, int IH, int IW, int OH, int OW)
{
    const int Ktot = CI * KHW;
    const int NT = Ktot >> 3;
    __shared__ __align__(16) float As[2][8][128];
    __shared__ __align__(16) float Bs[2][8][64];
    const int t = threadIdx.x;
    const int pix0 = blockIdx.x * 64, co0 = blockIdx.y * 128;
    const int ohw = OH * OW;

    const int acol = t >> 1;
    const int akq  = (t & 1) << 2;
    const float* Wrow = W + (size_t)(co0 + acol) * Ktot + akq;

    const int bpv = t & 63;
    const int bkq = (t >> 6) << 1;
    const int pixb = pix0 + bpv;
    const int nb = pixb / ohw, remb = pixb - nb * ohw;
    const int oyb = remb / OW, oxb = remb - oyb * OW;
    const int iy0 = oyb * STRIDE - PAD, ix0 = oxb * STRIDE - PAD;
    const float* Xn = X + (size_t)nb * CI * IH * IW;

    const int tx = t & 15, ty = t >> 4;

    #define GATHER2(k0v, r0, r1)                                                 \
        {   int k = (k0v) + bkq;                                                 \
            int ci = k / KHW;                                                    \
            int kr = k - ci * KHW;                                               \
            int ky = kr / KW;                                                    \
            int kx = kr - ky * KW;                                               \
            int iy = iy0 + ky, ix = ix0 + kx;                                    \
            r0 = ((unsigned)iy < (unsigned)IH && (unsigned)ix < (unsigned)IW)    \
                 ? Xn[(ci * IH + iy) * IW + ix] : 0.f;                           \
            k = (k0v) + bkq + 1;                                                 \
            ci = k / KHW; kr = k - ci * KHW; ky = kr / KW; kx = kr - ky * KW;    \
            iy = iy0 + ky; ix = ix0 + kx;                                        \
            r1 = ((unsigned)iy < (unsigned)IH && (unsigned)ix < (unsigned)IW)    \
                 ? Xn[(ci * IH + iy) * IW + ix] : 0.f;                           \
        }

    // prefetch tile 0
    float4 wv = *(const float4*)(Wrow);
    float bb0, bb1;
    GATHER2(0, bb0, bb1)
    As[0][akq + 0][acol] = wv.x;
    As[0][akq + 1][acol] = wv.y;
    As[0][akq + 2][acol] = wv.z;
    As[0][akq + 3][acol] = wv.w;
    Bs[0][bkq + 0][bpv] = bb0;
    Bs[0][bkq + 1][bpv] = bb1;
    __syncthreads();

    float acc[8][4] = {};
    float tot[8][4] = {};
    int nch = 0;

    for (int tile = 0; tile < NT; tile++) {
        const int cur = tile & 1;
        const bool more = (tile + 1 < NT);
        float4 wn;
        float nb0 = 0.f, nb1 = 0.f;
        if (more) {
            int k0 = (tile + 1) << 3;
            wn = *(const float4*)(Wrow + k0);
            GATHER2(k0, nb0, nb1)
        }
        #pragma unroll
        for (int kk = 0; kk < 8; kk++) {
            float4 a0 = *(const float4*)&As[cur][kk][ty << 2];
            float4 a1 = *(const float4*)&As[cur][kk][64 + (ty << 2)];
            float4 b0 = *(const float4*)&Bs[cur][kk][tx << 2];
            float av[8] = {a0.x, a0.y, a0.z, a0.w, a1.x, a1.y, a1.z, a1.w};
            float bv[4] = {b0.x, b0.y, b0.z, b0.w};
            #pragma unroll
            for (int i = 0; i < 8; i++)
                #pragma unroll
                for (int j = 0; j < 4; j++)
                    acc[i][j] = fmaf(av[i], bv[j], acc[i][j]);
        }
        if (more) {
            const int nxt = cur ^ 1;
            As[nxt][akq + 0][acol] = wn.x;
            As[nxt][akq + 1][acol] = wn.y;
            As[nxt][akq + 2][acol] = wn.z;
            As[nxt][akq + 3][acol] = wn.w;
            Bs[nxt][bkq + 0][bpv] = nb0;
            Bs[nxt][bkq + 1][bpv] = nb1;
        }
        __syncthreads();
        if (++nch == 8) {            // fold every 64 k (bit-matches rounds 4-15)
            nch = 0;
            #pragma unroll
            for (int i = 0; i < 8; i++)
                #pragma unroll
                for (int j = 0; j < 4; j++) {
                    tot[i][j] = __fadd_rn(tot[i][j], acc[i][j]);
                    acc[i][j] = 0.f;
                }
        }
    }
    #pragma unroll
    for (int i = 0; i < 8; i++)
        #pragma unroll
        for (int j = 0; j < 4; j++) tot[i][j] = __fadd_rn(tot[i][j], acc[i][j]);

    // float4 epilogue: 4 consecutive pixels per store
    {
        int p0 = pix0 + (tx << 2);
        int n2 = p0 / ohw, r2 = p0 - n2 * ohw;
        int oy2 = r2 / OW, ox2 = r2 - oy2 * OW;
        size_t base = (size_t)n2 * CO * ohw + (size_t)oy2 * OW + ox2;
        #pragma unroll
        for (int i = 0; i < 8; i++) {
            int co = co0 + ((i < 4) ? (ty << 2) + i : 64 + (ty << 2) + (i - 4));
            float4 v = make_float4(tot[i][0], tot[i][1], tot[i][2], tot[i][3]);
            *(float4*)&Y[base + (size_t)co * ohw] = v;
        }
    }
    #undef GATHER2
}

// ---------------- DECODER conv: 128x128x8 3xTF32 MMA, db + uint2-paired smem --
template<int KHW, int KW, int PAD>
__global__ void __launch_bounds__(256, 2) conv_mma_t(
    const float* __restrict__ W, const float* __restrict__ X, float* __restrict__ Y,
    int CO, int CI, int IH, int IW, int OH, int OW)
{
    const int Ktot = CI * KHW;
    const int NT = Ktot >> 3;
    __shared__ uint2 Aph[2][4][140], Apl[2][4][140], Bph[2][4][140], Bpl[2][4][140];
    const int t = threadIdx.x;
    const int pix0 = blockIdx.x * 128, co0 = blockIdx.y * 128;
    const int ohw = OH * OW;

    const int acol = t >> 1, ahh = t & 1;
    const float* Wrow = W + (size_t)(co0 + acol) * Ktot;

    const int bpv = t & 127, bhh = t >> 7;
    const int pixb = pix0 + bpv;
    const int nb = pixb / ohw, remb = pixb - nb * ohw;
    const int oyb = remb / OW, oxb = remb - oyb * OW;
    const int iy0 = oyb - PAD, ix0 = oxb - PAD;
    const float* Xn = X + (size_t)nb * CI * IH * IW;

    const int warp = t >> 5, lane = t & 31;
    const int wm = warp >> 1, wn = warp & 1;
    const int kq = lane & 3, lr = lane >> 2;

    float acc[2][8][4];
    #pragma unroll
    for (int a = 0; a < 2; a++)
        #pragma unroll
        for (int b = 0; b < 8; b++)
            #pragma unroll
            for (int c = 0; c < 4; c++) acc[a][b][c] = 0.f;

    float wA[4], vB[4];

    #define GATHER_CONV(k0v)                                                     \
        {   float2 w01 = *(const float2*)(Wrow + (k0v) + 2 * ahh);               \
            float2 w45 = *(const float2*)(Wrow + (k0v) + 2 * ahh + 4);           \
            wA[0] = w01.x; wA[1] = w01.y; wA[2] = w45.x; wA[3] = w45.y;          \
            _Pragma("unroll")                                                    \
            for (int i = 0; i < 4; i++) {                                        \
                int klocal = 2 * bhh + (i & 1) + ((i >> 1) << 2);                \
                int k = (k0v) + klocal;                                          \
                int ci = k / KHW;                                                \
                int kr = k - ci * KHW;                                           \
                int ky = kr / KW;                                                \
                int kx = kr - ky * KW;                                           \
                int iy = iy0 + ky, ix = ix0 + kx;                                \
                float v = 0.f;                                                   \
                if ((unsigned)iy < (unsigned)IH && (unsigned)ix < (unsigned)IW)  \
                    v = Xn[(ci * IH + iy) * IW + ix];                            \
                vB[i] = v;                                                       \
            }                                                                    \
        }

    #define STASH(bufv)                                                          \
        {   uint32_t h0,l0,h1,l1,h2,l2,h3,l3;                                    \
            split_tf32(wA[0],h0,l0); split_tf32(wA[1],h1,l1);                    \
            split_tf32(wA[2],h2,l2); split_tf32(wA[3],h3,l3);                    \
            Aph[bufv][2*ahh+0][acol] = make_uint2(h0, h2);                       \
            Aph[bufv][2*ahh+1][acol] = make_uint2(h1, h3);                       \
            Apl[bufv][2*ahh+0][acol] = make_uint2(l0, l2);                       \
            Apl[bufv][2*ahh+1][acol] = make_uint2(l1, l3);                       \
            split_tf32(vB[0],h0,l0); split_tf32(vB[1],h1,l1);                    \
            split_tf32(vB[2],h2,l2); split_tf32(vB[3],h3,l3);                    \
            Bph[bufv][2*bhh+0][bpv] = make_uint2(h0, h2);                        \
            Bph[bufv][2*bhh+1][bpv] = make_uint2(h1, h3);                        \
            Bpl[bufv][2*bhh+0][bpv] = make_uint2(l0, l2);                        \
            Bpl[bufv][2*bhh+1][bpv] = make_uint2(l1, l3);                        \
        }

    GATHER_CONV(0)
    STASH(0)
    __syncthreads();

    for (int tile = 0; tile < NT; tile++) {
        const int cur = tile & 1;
        const bool more = (tile + 1 < NT);
        if (more) GATHER_CONV((tile + 1) << 3)

        uint32_t ah[2][4], al[2][4];
        #pragma unroll
        for (int mt = 0; mt < 2; mt++) {
            int ca = wm * 32 + mt * 16 + lr;
            uint2 u0 = Aph[cur][kq][ca];
            uint2 u1 = Aph[cur][kq][ca + 8];
            ah[mt][0] = u0.x; ah[mt][1] = u1.x; ah[mt][2] = u0.y; ah[mt][3] = u1.y;
            uint2 v0 = Apl[cur][kq][ca];
            uint2 v1 = Apl[cur][kq][ca + 8];
            al[mt][0] = v0.x; al[mt][1] = v1.x; al[mt][2] = v0.y; al[mt][3] = v1.y;
        }
        #pragma unroll
        for (int nt = 0; nt < 8; nt++) {
            int pa = wn * 64 + nt * 8 + lr;
            uint2 bh = Bph[cur][kq][pa];
            uint2 bl = Bpl[cur][kq][pa];
            #pragma unroll
            for (int mt = 0; mt < 2; mt++) {
                mma_tf32(acc[mt][nt], ah[mt], bh.x, bh.y);
                mma_tf32(acc[mt][nt], ah[mt], bl.x, bl.y);
                mma_tf32(acc[mt][nt], al[mt], bh.x, bh.y);
            }
        }
        if (more) STASH(cur ^ 1)
        __syncthreads();
    }

    #pragma unroll
    for (int nt = 0; nt < 8; nt++) {
        int p = pix0 + wn * 64 + nt * 8 + (kq << 1);
        int n2 = p / ohw, r2 = p - n2 * ohw;
        int oy2 = r2 / OW, ox2 = r2 - oy2 * OW;
        size_t rowbase = (size_t)n2 * CO * ohw + (size_t)oy2 * OW + ox2;
        #pragma unroll
        for (int mt = 0; mt < 2; mt++) {
            int c0r = co0 + wm * 32 + mt * 16 + lr;
            float2 v0 = make_float2(acc[mt][nt][0], acc[mt][nt][1]);
            float2 v1 = make_float2(acc[mt][nt][2], acc[mt][nt][3]);
            *(float2*)&Y[rowbase + (size_t)c0r * ohw] = v0;
            *(float2*)&Y[rowbase + (size_t)(c0r + 8) * ohw] = v1;
        }
    }
    #undef GATHER_CONV
    #undef STASH
}

// ---------------- DECODER convT(k=4,s=2,p=1): parity-split 3xTF32 MMA, db -----
__global__ void __launch_bounds__(256, 2) convt_mma(
    const float* __restrict__ W, const float* __restrict__ X, float* __restrict__ Y,
    int CO, int CI, int IH, int IW, int OH, int OW)
{
    const int py = (blockIdx.z >> 1) & 1, px = blockIdx.z & 1;
    const int ky0 = 1 - py, ky1 = 3 - py, dy0 = py, dy1 = py - 1;
    const int kx0 = 1 - px, kx1 = 3 - px, dx0 = px, dx1 = px - 1;
    const int Ktot = CI * 4;
    const int NT = Ktot >> 3;
    __shared__ uint2 Aph[2][4][140], Apl[2][4][140], Bph[2][4][140], Bpl[2][4][140];
    const int t = threadIdx.x;
    const int pix0 = blockIdx.x * 128, co0 = blockIdx.y * 128;
    const int yhw = IH * IW;

    const int acol = t >> 1, ahh = t & 1;
    const int bpv = t & 127, bhh = t >> 7;
    const int pixb = pix0 + bpv;
    const int nb = pixb / yhw, remb = pixb - nb * yhw;
    const int yb = remb / IW, xb = remb - yb * IW;
    const float* Xn = X + (size_t)nb * CI * yhw;

    const int warp = t >> 5, lane = t & 31;
    const int wm = warp >> 1, wn = warp & 1;
    const int kq = lane & 3, lr = lane >> 2;

    float acc[2][8][4];
    #pragma unroll
    for (int a = 0; a < 2; a++)
        #pragma unroll
        for (int b = 0; b < 8; b++)
            #pragma unroll
            for (int c = 0; c < 4; c++) acc[a][b][c] = 0.f;

    float wA[4], vB[4];

    #define GATHER_CT(k0v)                                                       \
        {   _Pragma("unroll")                                                    \
            for (int i = 0; i < 4; i++) {                                        \
                int klocal = 2 * ahh + (i & 1) + ((i >> 1) << 2);                \
                int k = (k0v) + klocal;                                          \
                int ci = k >> 2, tt = k & 3;                                     \
                int ky = (tt & 2) ? ky1 : ky0;                                   \
                int kx = (tt & 1) ? kx1 : kx0;                                   \
                wA[i] = W[(((size_t)ci * CO + co0 + acol) << 4) + (ky << 2) + kx]; \
            }                                                                    \
            _Pragma("unroll")                                                    \
            for (int i = 0; i < 4; i++) {                                        \
                int klocal = 2 * bhh + (i & 1) + ((i >> 1) << 2);                \
                int k = (k0v) + klocal;                                          \
                int ci = k >> 2, tt = k & 3;                                     \
                int iy = yb + ((tt & 2) ? dy1 : dy0);                            \
                int ix = xb + ((tt & 1) ? dx1 : dx0);                            \
                vB[i] = ((unsigned)iy < (unsigned)IH && (unsigned)ix < (unsigned)IW) \
                        ? Xn[(ci * IH + iy) * IW + ix] : 0.f;                    \
            }                                                                    \
        }

    #define STASH2(bufv)                                                         \
        {   uint32_t h0,l0,h1,l1,h2,l2,h3,l3;                                    \
            split_tf32(wA[0],h0,l0); split_tf32(wA[1],h1,l1);                    \
            split_tf32(wA[2],h2,l2); split_tf32(wA[3],h3,l3);                    \
            Aph[bufv][2*ahh+0][acol] = make_uint2(h0, h2);                       \
            Aph[bufv][2*ahh+1][acol] = make_uint2(h1, h3);                       \
            Apl[bufv][2*ahh+0][acol] = make_uint2(l0, l2);                       \
            Apl[bufv][2*ahh+1][acol] = make_uint2(l1, l3);                       \
            split_tf32(vB[0],h0,l0); split_tf32(vB[1],h1,l1);                    \
            split_tf32(vB[2],h2,l2); split_tf32(vB[3],h3,l3);                    \
            Bph[bufv][2*bhh+0][bpv] = make_uint2(h0, h2);                        \
            Bph[bufv][2*bhh+1][bpv] = make_uint2(h1, h3);                        \
            Bpl[bufv][2*bhh+0][bpv] = make_uint2(l0, l2);                        \
            Bpl[bufv][2*bhh+1][bpv] = make_uint2(l1, l3);                        \
        }

    GATHER_CT(0)
    STASH2(0)
    __syncthreads();

    for (int tile = 0; tile < NT; tile++) {
        const int cur = tile & 1;
        const bool more = (tile + 1 < NT);
        if (more) GATHER_CT((tile + 1) << 3)

        uint32_t ah[2][4], al[2][4];
        #pragma unroll
        for (int mt = 0; mt < 2; mt++) {
            int ca = wm * 32 + mt * 16 + lr;
            uint2 u0 = Aph[cur][kq][ca];
            uint2 u1 = Aph[cur][kq][ca + 8];
            ah[mt][0] = u0.x; ah[mt][1] = u1.x; ah[mt][2] = u0.y; ah[mt][3] = u1.y;
            uint2 v0 = Apl[cur][kq][ca];
            uint2 v1 = Apl[cur][kq][ca + 8];
            al[mt][0] = v0.x; al[mt][1] = v1.x; al[mt][2] = v0.y; al[mt][3] = v1.y;
        }
        #pragma unroll
        for (int nt = 0; nt < 8; nt++) {
            int pa = wn * 64 + nt * 8 + lr;
            uint2 bh = Bph[cur][kq][pa];
            uint2 bl = Bpl[cur][kq][pa];
            #pragma unroll
            for (int mt = 0; mt < 2; mt++) {
                mma_tf32(acc[mt][nt], ah[mt], bh.x, bh.y);
                mma_tf32(acc[mt][nt], ah[mt], bl.x, bl.y);
                mma_tf32(acc[mt][nt], al[mt], bh.x, bh.y);
            }
        }
        if (more) STASH2(cur ^ 1)
        __syncthreads();
    }

    const size_t ostride = (size_t)OH * OW;
    #pragma unroll
    for (int nt = 0; nt < 8; nt++) {
        #pragma unroll
        for (int e = 0; e < 2; e++) {
            int pp = pix0 + wn * 64 + nt * 8 + (kq << 1) + e;
            int n2 = pp / yhw, r2 = pp - n2 * yhw;
            int y2 = r2 / IW, x2 = r2 - y2 * IW;
            int oy = (y2 << 1) + py, ox = (x2 << 1) + px;
            #pragma unroll
            for (int mt = 0; mt < 2; mt++) {
                int c0r = co0 + wm * 32 + mt * 16 + lr;
                size_t idx = (((size_t)n2 * CO + c0r) * OH + oy) * OW + ox;
                Y[idx] = acc[mt][nt][e];
                Y[idx + 8 * ostride] = acc[mt][nt][2 + e];
            }
        }
    }
    #undef GATHER_CT
    #undef STASH2
}

// ---------------- d_t2 weight repack + packed direct convT ----------------
__global__ void pack_wt2(const float* __restrict__ W, float* __restrict__ Wp)
{
    int i = blockIdx.x * blockDim.x + threadIdx.x;
    if (i >= 12288) return;
    int tap = i & 3;
    int r = i >> 2;
    int co = r % 3;
    int r2 = r / 3;
    int ci = r2 & 255;
    int pp = r2 >> 8;
    int py = pp >> 1, px = pp & 1;
    int ky = ((tap >> 1) == 0) ? (1 - py) : (3 - py);
    int kx = ((tap & 1) == 0) ? (1 - px) : (3 - px);
    Wp[i] = W[((size_t)ci * 3 + co) * 16 + ky * 4 + kx];
}

__global__ void __launch_bounds__(256) convt_direct2(
    const float* __restrict__ Wp, const float* __restrict__ X, float* __restrict__ Y,
    int CI, int IH, int IW, int OH, int OW)
{
    int ox = threadIdx.x, oy = blockIdx.x, n = blockIdx.z;
    int py = oy & 1, px = ox & 1;
    int iyA = (oy + py) >> 1, iyB = iyA - 1;
    int ixA = (ox + px) >> 1, ixB = ixA - 1;
    bool vyA = (unsigned)iyA < (unsigned)IH, vyB = (unsigned)iyB < (unsigned)IH;
    bool vxA = (unsigned)ixA < (unsigned)IW, vxB = (unsigned)ixB < (unsigned)IW;
    const float* Xn = X + (size_t)n * CI * IH * IW;
    const float4* wp = (const float4*)(Wp + (size_t)(py * 2 + px) * 256 * 12);

    float a0 = 0.f, a1 = 0.f, a2 = 0.f;
    for (int ci = 0; ci < CI; ci++) {
        const float* xc = Xn + (size_t)ci * IH * IW;
        float x00 = (vyA && vxA) ? xc[iyA * IW + ixA] : 0.f;
        float x01 = (vyA && vxB) ? xc[iyA * IW + ixB] : 0.f;
        float x10 = (vyB && vxA) ? xc[iyB * IW + ixA] : 0.f;
        float x11 = (vyB && vxB) ? xc[iyB * IW + ixB] : 0.f;
        float4 w0 = wp[ci * 3 + 0];
        float4 w1 = wp[ci * 3 + 1];
        float4 w2 = wp[ci * 3 + 2];
        a0 = fmaf(x00, w0.x, a0); a0 = fmaf(x01, w0.y, a0);
        a0 = fmaf(x10, w0.z, a0); a0 = fmaf(x11, w0.w, a0);
        a1 = fmaf(x00, w1.x, a1); a1 = fmaf(x01, w1.y, a1);
        a1 = fmaf(x10, w1.z, a1); a1 = fmaf(x11, w1.w, a1);
        a2 = fmaf(x00, w2.x, a2); a2 = fmaf(x01, w2.y, a2);
        a2 = fmaf(x10, w2.z, a2); a2 = fmaf(x11, w2.w, a2);
    }
    size_t ohw = (size_t)OH * OW;
    size_t base = (size_t)n * 3 * ohw + (size_t)oy * OW + ox;
    Y[base] = a0;
    Y[base + ohw] = a1;
    Y[base + 2 * ohw] = a2;
}

// ---------------- Two-phase parallel BN stats (ALL BNs) ----------------------
__global__ void bn_stats_part(const float* __restrict__ x, const float* __restrict__ r,
                              float2* __restrict__ part, int C, int HW, int Bn)
{
    int c = blockIdx.x, sl = blockIdx.y;
    int chunk = HW / NSL;
    int i0 = sl * chunk;
    float s = 0.f, cs = 0.f, ss = 0.f, css = 0.f;
    for (int n = 0; n < Bn; n++) {
        const float* p = x + (size_t)(n * C + c) * HW;
        const float* q = r ? r + (size_t)(n * C + c) * HW : (const float*)0;
        for (int i = i0 + threadIdx.x; i < i0 + chunk; i += blockDim.x) {
            float v = p[i];
            if (q) v = __fadd_rn(v, q[i]);
            float y1 = __fsub_rn(v, cs);
            float t1 = __fadd_rn(s, y1);
            cs = __fsub_rn(__fsub_rn(t1, s), y1); s = t1;
            float w = __fmul_rn(v, v);
            float y2 = __fsub_rn(w, css);
            float t2 = __fadd_rn(ss, y2);
            css = __fsub_rn(__fsub_rn(t2, ss), y2); ss = t2;
        }
    }
    s = __fsub_rn(s, cs); ss = __fsub_rn(ss, css);
    __shared__ float shs[32], shss[32];
    int lane = threadIdx.x & 31, wid = threadIdx.x >> 5;
    #pragma unroll
    for (int o = 16; o > 0; o >>= 1) {
        s  += __shfl_down_sync(0xffffffffu, s,  o);
        ss += __shfl_down_sync(0xffffffffu, ss, o);
    }
    if (lane == 0) { shs[wid] = s; shss[wid] = ss; }
    __syncthreads();
    if (threadIdx.x == 0) {
        int nw = blockDim.x >> 5;
        float ts = 0.f, tss = 0.f;
        for (int i = 0; i < nw; i++) { ts += shs[i]; tss += shss[i]; }
        part[c * NSL + sl] = make_float2(ts, tss);
    }
}

__global__ void bn_stats_comb(const float2* __restrict__ part,
                              float* __restrict__ mean, float* __restrict__ istd,
                              int C, float inv)
{
    int c = blockIdx.x * blockDim.x + threadIdx.x;
    if (c >= C) return;
    float ts = 0.f, tss = 0.f;
    for (int sl = 0; sl < NSL; sl++) {
        float2 v = part[c * NSL + sl];
        ts += v.x; tss += v.y;
    }
    float m = ts * inv;
    float var = fmaxf(tss * inv - m * m, 0.f);
    mean[c] = m;
    istd[c] = rsqrtf(var + EPSBN);
}

__global__ void bn_apply4(const float4* __restrict__ x, const float4* __restrict__ r,
                          float4* __restrict__ y,
                          const float* __restrict__ g, const float* __restrict__ b,
                          const float* __restrict__ mean, const float* __restrict__ istd,
                          int C, int hwshift4, int total4, int mode)
{
    int stride = gridDim.x * blockDim.x;
    for (int i = blockIdx.x * blockDim.x + threadIdx.x; i < total4; i += stride) {
        int c = (i >> hwshift4) % C;
        float4 v = x[i];
        if (r) {
            float4 rv = r[i];
            v.x = __fadd_rn(v.x, rv.x); v.y = __fadd_rn(v.y, rv.y);
            v.z = __fadd_rn(v.z, rv.z); v.w = __fadd_rn(v.w, rv.w);
        }
        float gc = g[c], bc = b[c], mc = mean[c], ic = istd[c];
        v.x = __fadd_rn(__fmul_rn(__fmul_rn(gc, __fsub_rn(v.x, mc)), ic), bc);
        v.y = __fadd_rn(__fmul_rn(__fmul_rn(gc, __fsub_rn(v.y, mc)), ic), bc);
        v.z = __fadd_rn(__fmul_rn(__fmul_rn(gc, __fsub_rn(v.z, mc)), ic), bc);
        v.w = __fadd_rn(__fmul_rn(__fmul_rn(gc, __fsub_rn(v.w, mc)), ic), bc);
        if (mode == 1) {
            v.x = fmaxf(v.x, 0.f); v.y = fmaxf(v.y, 0.f);
            v.z = fmaxf(v.z, 0.f); v.w = fmaxf(v.w, 0.f);
        } else if (mode == 2) {
            v.x = tanhf(v.x); v.y = tanhf(v.y);
            v.z = tanhf(v.z); v.w = tanhf(v.w);
        }
        y[i] = v;
    }
}

// ---------------- VQ (FROZEN: bit-exact path validated in round 4) ----------
__global__ void transpose_cb(const float* __restrict__ cb, float* __restrict__ cbT)
{
    int i = blockIdx.x * blockDim.x + threadIdx.x;
    int j = i >> 8, k = i & 255;
    cbT[k * 512 + j] = cb[i];
}

__global__ void cnorm_k(const float* __restrict__ cb, float* __restrict__ cn)
{
    int j = blockIdx.x * blockDim.x + threadIdx.x;
    if (j < 512) {
        float s = 0.f;
        const float* p = cb + j * 256;
        for (int c = 0; c < 256; c++) s = __fadd_rn(s, __fmul_rn(p[c], p[c]));
        cn[j] = s;
    }
}

__global__ void fnorm_k(const float* __restrict__ ze, float* __restrict__ fn, int HW)
{
    int w = (blockIdx.x * blockDim.x + threadIdx.x) >> 5;
    int lane = threadIdx.x & 31;
    int n = w / HW, hw = w - n * HW;
    const float* base = ze + (size_t)n * 256 * HW + hw;
    float s = 0.f;
    for (int k = lane; k < 256; k += 32) {
        float v = base[(size_t)k * HW];
        s = __fadd_rn(s, __fmul_rn(v, v));
    }
    #pragma unroll
    for (int o = 16; o > 0; o >>= 1) s += __shfl_down_sync(0xffffffffu, s, o);
    if (lane == 0) fn[w] = s;
}

#define VQ_KC 16
__global__ void __launch_bounds__(512) vq_dist_argmin(
    const float* __restrict__ ze, const float* __restrict__ cbT,
    const float* __restrict__ cn, const float* __restrict__ fnorm,
    int* __restrict__ idx, int HW)
{
    __shared__ float fs[64 * 17];
    __shared__ __align__(16) float cbs[VQ_KC * 512];
    __shared__ float cns[512];
    __shared__ float rd[64 * 8];
    __shared__ int   rj[64 * 8];

    const int t = threadIdx.x, px = t & 63, jg = t >> 6;
    const int p = blockIdx.x * 64 + px;
    cns[t] = cn[t];

    float acc[64];
    #pragma unroll
    for (int j = 0; j < 64; j++) acc[j] = 0.f;

    for (int k0 = 0; k0 < 256; k0 += VQ_KC) {
        __syncthreads();
        for (int i = t; i < 64 * VQ_KC; i += 512) {
            int kk = i >> 6, pp = i & 63;
            int gp = blockIdx.x * 64 + pp;
            int gn = gp / HW, ghw = gp - gn * HW;
            fs[pp * 17 + kk] = ze[((size_t)gn * 256 + (k0 + kk)) * HW + ghw];
        }
        for (int i = t; i < VQ_KC * 512; i += 512)
            cbs[i] = cbT[(size_t)(k0 + (i >> 9)) * 512 + (i & 511)];
        __syncthreads();

        float fv[VQ_KC];
        #pragma unroll
        for (int kk = 0; kk < VQ_KC; kk++) fv[kk] = fs[px * 17 + kk];

        #pragma unroll
        for (int j4 = 0; j4 < 16; j4++) {
            float a0, a1, a2, a3;
            {
                float4 c = *(const float4*)&cbs[jg * 64 + j4 * 4];
                a0 = __fmul_rn(fv[0], c.x); a1 = __fmul_rn(fv[0], c.y);
                a2 = __fmul_rn(fv[0], c.z); a3 = __fmul_rn(fv[0], c.w);
                #pragma unroll
                for (int kk = 1; kk < 8; kk++) {
                    float4 d = *(const float4*)&cbs[kk * 512 + jg * 64 + j4 * 4];
                    a0 = fmaf(fv[kk], d.x, a0); a1 = fmaf(fv[kk], d.y, a1);
                    a2 = fmaf(fv[kk], d.z, a2); a3 = fmaf(fv[kk], d.w, a3);
                }
                acc[j4*4+0] = __fadd_rn(acc[j4*4+0], a0);
                acc[j4*4+1] = __fadd_rn(acc[j4*4+1], a1);
                acc[j4*4+2] = __fadd_rn(acc[j4*4+2], a2);
                acc[j4*4+3] = __fadd_rn(acc[j4*4+3], a3);
            }
            {
                float4 c = *(const float4*)&cbs[8 * 512 + jg * 64 + j4 * 4];
                a0 = __fmul_rn(fv[8], c.x); a1 = __fmul_rn(fv[8], c.y);
                a2 = __fmul_rn(fv[8], c.z); a3 = __fmul_rn(fv[8], c.w);
                #pragma unroll
                for (int kk = 9; kk < 16; kk++) {
                    float4 d = *(const float4*)&cbs[kk * 512 + jg * 64 + j4 * 4];
                    a0 = fmaf(fv[kk], d.x, a0); a1 = fmaf(fv[kk], d.y, a1);
                    a2 = fmaf(fv[kk], d.z, a2); a3 = fmaf(fv[kk], d.w, a3);
                }
                acc[j4*4+0] = __fadd_rn(acc[j4*4+0], a0);
                acc[j4*4+1] = __fadd_rn(acc[j4*4+1], a1);
                acc[j4*4+2] = __fadd_rn(acc[j4*4+2], a2);
                acc[j4*4+3] = __fadd_rn(acc[j4*4+3], a3);
            }
        }
    }

    float S = fnorm[p];
    float best = 3.4028235e38f;
    int bj = 0;
    #pragma unroll
    for (int j = 0; j < 64; j++) {
        float q = __fsub_rn(S, __fmul_rn(2.0f, acc[j]));
        float dj = __fadd_rn(q, cns[jg * 64 + j]);
        if (dj < best) { best = dj; bj = jg * 64 + j; }
    }
    rd[px * 8 + jg] = best;
    rj[px * 8 + jg] = bj;
    __syncthreads();
    if (t < 64) {
        float bb = rd[t * 8]; int jj = rj[t * 8];
        #pragma unroll
        for (int gsel = 1; gsel < 8; gsel++) {
            float d2 = rd[t * 8 + gsel];
            if (d2 < bb) { bb = d2; jj = rj[t * 8 + gsel]; }
        }
        idx[blockIdx.x * 64 + t] = jj;
    }
}

__global__ void vq_gather4(const int* __restrict__ idx, const float* __restrict__ cb,
                           float4* __restrict__ zq, int total4)
{
    int stride = gridDim.x * blockDim.x;
    for (int i = blockIdx.x * blockDim.x + threadIdx.x; i < total4; i += stride) {
        int hw4 = i & 1023;
        int nc = i >> 10;
        int c = nc & 255, n = nc >> 8;
        const int* ip = idx + n * 4096 + (hw4 << 2);
        zq[i] = make_float4(cb[ip[0] * 256 + c], cb[ip[1] * 256 + c],
                            cb[ip[2] * 256 + c], cb[ip[3] * 256 + c]);
    }
}

// ---------------- pipeline ----------------
extern "C" void kernel_launch(void* const* d_in, const int* in_sizes, int n_in,
                              void* d_out, int out_size)
{
    const float* img  = (const float*)d_in[0];
    const float* e_w1 = (const float*)d_in[1];
    const float* e_g1 = (const float*)d_in[2];
    const float* e_b1 = (const float*)d_in[3];
    const float* e_w2 = (const float*)d_in[4];
    const float* e_g2 = (const float*)d_in[5];
    const float* e_b2 = (const float*)d_in[6];
    const float* e_w3 = (const float*)d_in[7];
    const float* e_g3 = (const float*)d_in[8];
    const float* e_b3 = (const float*)d_in[9];
    const float* e_w4 = (const float*)d_in[10];
    const float* e_g4 = (const float*)d_in[12];
    const float* e_b4 = (const float*)d_in[13];
    const float* e_g5 = (const float*)d_in[14];
    const float* e_b5 = (const float*)d_in[15];
    const float* cb   = (const float*)d_in[16];
    const float* dw1  = (const float*)d_in[17];
    const float* dg1  = (const float*)d_in[18];
    const float* db1  = (const float*)d_in[19];
    const float* dw2  = (const float*)d_in[20];
    const float* dg2  = (const float*)d_in[21];
    const float* db2  = (const float*)d_in[22];
    const float* dg3  = (const float*)d_in[23];
    const float* db3  = (const float*)d_in[24];
    const float* dt1  = (const float*)d_in[25];
    const float* dg4  = (const float*)d_in[26];
    const float* db4  = (const float*)d_in[27];
    const float* dt2  = (const float*)d_in[28];
    const float* dg5  = (const float*)d_in[30];
    const float* db5  = (const float*)d_in[31];
    float* out = (float*)d_out;

    float *buf128, *b64a, *b64b, *b64c, *mean, *istd, *cnorm, *fnorm, *cbT, *wp;
    float2* part;
    int* idx;
    cudaGetSymbolAddress((void**)&buf128, g_buf128);
    cudaGetSymbolAddress((void**)&b64a,   g_b64a);
    cudaGetSymbolAddress((void**)&b64b,   g_b64b);
    cudaGetSymbolAddress((void**)&b64c,   g_b64c);
    cudaGetSymbolAddress((void**)&mean,   g_mean);
    cudaGetSymbolAddress((void**)&istd,   g_istd);
    cudaGetSymbolAddress((void**)&cnorm,  g_cnorm);
    cudaGetSymbolAddress((void**)&fnorm,  g_fnorm);
    cudaGetSymbolAddress((void**)&cbT,    g_cbT);
    cudaGetSymbolAddress((void**)&wp,     g_wp);
    cudaGetSymbolAddress((void**)&part,   g_part);
    cudaGetSymbolAddress((void**)&idx,    g_idx);

    const int T128 = 33554432, T64 = 8388608;
    const int Q128 = T128 / 4, Q64 = T64 / 4;
    const float INV128 = 1.f / (8.f * 16384.f);
    const float INV64  = 1.f / (8.f * 4096.f);
    const float INVOUT = 1.f / (8.f * 65536.f);
    #define F4(p) ((float4*)(p))
    #define CF4(p) ((const float4*)(p))
    #define BN_STATS(buf, res, HW, INV, Cc)                                     \
        bn_stats_part<<<dim3(Cc, NSL), 256>>>(buf, res, part, Cc, HW, 8);       \
        bn_stats_comb<<<1, (Cc) >= 256 ? 256 : 32>>>(part, mean, istd, Cc, INV);

    // independent prep
    pack_wt2<<<48, 256>>>(dt2, wp);
    transpose_cb<<<512, 256>>>(cb, cbT);
    cnorm_k<<<2, 256>>>(cb, cnorm);

    // ---- encoder (fp32 SIMT 128x64 db, FMA chain FROZEN) ----
    conv_gemm_db2<16,4,2,1><<<dim3(2048, 2), 256>>>(e_w1, img, buf128, 256, 3, 256, 256, 128, 128);
    BN_STATS(buf128, (const float*)0, 16384, INV128, 256)
    bn_apply4<<<8192, 256>>>(CF4(buf128), (const float4*)0, F4(buf128), e_g1, e_b1, mean, istd, 256, 12, Q128, 1);

    conv_gemm_db2<16,4,2,1><<<dim3(512, 2), 256>>>(e_w2, buf128, b64a, 256, 256, 128, 128, 64, 64);
    BN_STATS(b64a, (const float*)0, 4096, INV64, 256)
    bn_apply4<<<4096, 256>>>(CF4(b64a), (const float4*)0, F4(b64a), e_g2, e_b2, mean, istd, 256, 10, Q64, 1);

    conv_gemm_db2<9,3,1,1><<<dim3(512, 2), 256>>>(e_w3, b64a, b64b, 256, 256, 64, 64, 64, 64);
    BN_STATS(b64b, (const float*)0, 4096, INV64, 256)
    bn_apply4<<<4096, 256>>>(CF4(b64b), (const float4*)0, F4(b64b), e_g3, e_b3, mean, istd, 256, 10, Q64, 1);

    conv_gemm_db2<1,1,1,0><<<dim3(512, 2), 256>>>(e_w4, b64b, b64c, 256, 256, 64, 64, 64, 64);
    BN_STATS(b64c, (const float*)0, 4096, INV64, 256)
    bn_apply4<<<4096, 256>>>(CF4(b64c), (const float4*)0, F4(b64c), e_g4, e_b4, mean, istd, 256, 10, Q64, 1);

    BN_STATS(b64a, b64c, 4096, INV64, 256)
    bn_apply4<<<4096, 256>>>(CF4(b64a), CF4(b64c), F4(b64b), e_g5, e_b5, mean, istd, 256, 10, Q64, 0);

    // ---- VQ (frozen) ----
    fnorm_k<<<4096, 256>>>(b64b, fnorm, 4096);
    vq_dist_argmin<<<512, 512>>>(b64b, cbT, cnorm, fnorm, idx, 4096);
    vq_gather4<<<2048, 256>>>(idx, cb, F4(b64c), Q64);

    // ---- decoder (3-pass split-TF32 tensor cores, tolerance path) ----
    conv_mma_t<9,3,1><<<dim3(256, 2), 256>>>(dw1, b64c, b64a, 256, 256, 64, 64, 64, 64);
    BN_STATS(b64a, (const float*)0, 4096, INV64, 256)
    bn_apply4<<<4096, 256>>>(CF4(b64a), (const float4*)0, F4(b64a), dg1, db1, mean, istd, 256, 10, Q64, 1);

    conv_mma_t<1,1,0><<<dim3(256, 2), 256>>>(dw2, b64a, b64b, 256, 256, 64, 64, 64, 64);
    BN_STATS(b64b, (const float*)0, 4096, INV64, 256)
    bn_apply4<<<4096, 256>>>(CF4(b64b), (const float4*)0, F4(b64b), dg2, db2, mean, istd, 256, 10, Q64, 1);

    BN_STATS(b64c, b64b, 4096, INV64, 256)
    bn_apply4<<<4096, 256>>>(CF4(b64c), CF4(b64b), F4(b64a), dg3, db3, mean, istd, 256, 10, Q64, 1);

    convt_mma<<<dim3(256, 2, 4), 256>>>(dt1, b64a, buf128, 256, 256, 64, 64, 128, 128);
    BN_STATS(buf128, (const float*)0, 16384, INV128, 256)
    bn_apply4<<<8192, 256>>>(CF4(buf128), (const float4*)0, F4(buf128), dg4, db4, mean, istd, 256, 12, Q128, 1);

    convt_direct2<<<dim3(256, 1, 8), 256>>>(wp, buf128, out, 256, 128, 128, 256, 256);
    BN_STATS(out, (const float*)0, 65536, INVOUT, 3)
    bn_apply4<<<384, 256>>>(CF4(out), (const float4*)0, F4(out), dg5, db5, mean, istd, 3, 14, 393216, 2);
}